// round 4
// baseline (speedup 1.0000x reference)
#include <cuda_runtime.h>
#include <math.h>

#define BATCH 4
#define NPTS 4096
#define NPTS2 4096
#define CINC 128
#define DIMC 64
#define KNNC 20
#define UPF 2
#define HPOSC 64
#define HATTC 256
#define EPSV 1e-5f
#define PPB 2          // points per block in attn kernels

// ---------------- scratch (static device memory; no allocations) ----------------
__device__ float g_qt[BATCH * NPTS * DIMC];     // (b, n, o) point-major
__device__ float g_kt[BATCH * NPTS2 * DIMC];
__device__ float g_vt[BATCH * NPTS2 * DIMC];
__device__ int   g_idx[BATCH * NPTS * KNNC];
__device__ float g_aw1t[DIMC * HATTC];          // aw1 transposed: [o][c]
__device__ float g_pw2t[HPOSC * DIMC];          // pw2 transposed: [h][o]
__device__ float g_wqt[CINC * DIMC];            // wq transposed: [c][o]
__device__ float g_wkt[CINC * DIMC];
__device__ float g_wvt[CINC * DIMC];
__device__ float g_a[(size_t)BATCH * NPTS * HATTC * KNNC];   // relu'd attn hidden
__device__ float g_vg[(size_t)BATCH * NPTS * DIMC * KNNC];   // v gathered + pe

// ---------------- packed f32x2 helpers ----------------
__device__ __forceinline__ unsigned long long ffma2(
    unsigned long long a, unsigned long long b, unsigned long long c) {
    unsigned long long d;
    asm("fma.rn.f32x2 %0, %1, %2, %3;" : "=l"(d) : "l"(a), "l"(b), "l"(c));
    return d;
}
__device__ __forceinline__ unsigned long long pack2(float lo, float hi) {
    unsigned long long d;
    asm("mov.b64 %0, {%1, %2};" : "=l"(d) : "f"(lo), "f"(hi));
    return d;
}
__device__ __forceinline__ void unpack2(unsigned long long v, float& lo, float& hi) {
    asm("mov.b64 {%0, %1}, %2;" : "=f"(lo), "=f"(hi) : "l"(v));
}

// ================= prep: transpose small weights =================
__global__ __launch_bounds__(256) void prep_kernel(
    const float* __restrict__ aw1, const float* __restrict__ pw2,
    const float* __restrict__ wq, const float* __restrict__ wk,
    const float* __restrict__ wv)
{
    int i = blockIdx.x * 256 + threadIdx.x;
    if (i < HATTC * DIMC) {            // aw1[c][o] -> g_aw1t[o][c]
        int c = i >> 6, o = i & 63;
        g_aw1t[o * HATTC + c] = aw1[i];
    }
    if (i < DIMC * HPOSC) {            // pw2[o][h] -> g_pw2t[h][o]
        int o = i >> 6, h = i & 63;
        g_pw2t[h * DIMC + o] = pw2[i];
    }
    if (i < DIMC * CINC) {             // w[o][c] -> g_wt[c][o]
        int o = i >> 7, c = i & 127;
        g_wqt[c * DIMC + o] = wq[i];
        g_wkt[c * DIMC + o] = wk[i];
        g_wvt[c * DIMC + o] = wv[i];
    }
}

// ================= QKV projection kernel =================
// grid (N/128, B), block 256. 128 points per block; thread = (o, point-quarter).
__global__ __launch_bounds__(256) void qkv_kernel(
    const float* __restrict__ query, const float* __restrict__ key_feat,
    const float* __restrict__ bq, const float* __restrict__ bk,
    const float* __restrict__ bv)
{
    int b = blockIdx.y;
    int n0 = blockIdx.x * 128;
    int tid = threadIdx.x;
    __shared__ __align__(16) float tile[CINC * 128];   // 64 KB

    int o = tid & 63;
    int jb = tid >> 6;                 // 0..3 -> points jb*32 .. jb*32+31

    // ---- q from query ----
    for (int i = tid; i < CINC * 128; i += 256) {
        int c = i >> 7, j = i & 127;
        tile[i] = query[(b * CINC + c) * NPTS + n0 + j];
    }
    __syncthreads();
    {
        unsigned long long acc[16];
#pragma unroll
        for (int m = 0; m < 16; m++) acc[m] = 0ULL;
#pragma unroll 4
        for (int c = 0; c < CINC; c++) {
            float w = g_wqt[c * DIMC + o];
            unsigned long long wp = pack2(w, w);
            const ulonglong2* tp = reinterpret_cast<const ulonglong2*>(tile + c * 128 + jb * 32);
#pragma unroll
            for (int jj = 0; jj < 8; jj++) {
                ulonglong2 t = tp[jj];
                acc[2 * jj]     = ffma2(wp, t.x, acc[2 * jj]);
                acc[2 * jj + 1] = ffma2(wp, t.y, acc[2 * jj + 1]);
            }
        }
        float bias = bq[o];
#pragma unroll
        for (int m = 0; m < 16; m++) {
            float lo, hi;
            unpack2(acc[m], lo, hi);
            int j = jb * 32 + 2 * m;
            g_qt[(b * NPTS + n0 + j) * DIMC + o]     = lo + bias;
            g_qt[(b * NPTS + n0 + j + 1) * DIMC + o] = hi + bias;
        }
    }
    __syncthreads();

    // ---- k, v from key_feat (two passes to cap registers) ----
    for (int i = tid; i < CINC * 128; i += 256) {
        int c = i >> 7, j = i & 127;
        tile[i] = key_feat[(b * CINC + c) * NPTS2 + n0 + j];
    }
    __syncthreads();
#pragma unroll
    for (int which = 0; which < 2; which++) {
        const float* wt = which ? g_wvt : g_wkt;
        float* gout = which ? g_vt : g_kt;
        float bias = which ? bv[o] : bk[o];
        unsigned long long acc[16];
#pragma unroll
        for (int m = 0; m < 16; m++) acc[m] = 0ULL;
#pragma unroll 4
        for (int c = 0; c < CINC; c++) {
            float w = wt[c * DIMC + o];
            unsigned long long wp = pack2(w, w);
            const ulonglong2* tp = reinterpret_cast<const ulonglong2*>(tile + c * 128 + jb * 32);
#pragma unroll
            for (int jj = 0; jj < 8; jj++) {
                ulonglong2 t = tp[jj];
                acc[2 * jj]     = ffma2(wp, t.x, acc[2 * jj]);
                acc[2 * jj + 1] = ffma2(wp, t.y, acc[2 * jj + 1]);
            }
        }
#pragma unroll
        for (int m = 0; m < 16; m++) {
            float lo, hi;
            unpack2(acc[m], lo, hi);
            int j = jb * 32 + 2 * m;
            gout[(b * NPTS2 + n0 + j) * DIMC + o]     = lo + bias;
            gout[(b * NPTS2 + n0 + j + 1) * DIMC + o] = hi + bias;
        }
    }
}

// ================= KNN kernel =================
// grid (N/256, B), block 512. Two threads per query, each scans half the support set.
__global__ __launch_bounds__(512) void knn_kernel(
    const float* __restrict__ pos1, const float* __restrict__ pos2)
{
    int b = blockIdx.y;
    int tid = threadIdx.x;
    int q = tid & 255;
    int half = tid >> 8;
    int n = blockIdx.x * 256 + q;

    __shared__ float sx[4096], sy[4096], sz[4096], sq2[4096];  // 64 KB
    __shared__ float smd[512][KNNC];                           // 40 KB
    __shared__ int   smi[512][KNNC];

    for (int i = tid; i < 4096; i += 512) {
        float x = pos2[(b * 3 + 0) * NPTS2 + i];
        float y = pos2[(b * 3 + 1) * NPTS2 + i];
        float z = pos2[(b * 3 + 2) * NPTS2 + i];
        sx[i] = x; sy[i] = y; sz[i] = z;
        sq2[i] = x * x + y * y + z * z;
    }

    float qx = pos1[(b * 3 + 0) * NPTS + n];
    float qy = pos1[(b * 3 + 1) * NPTS + n];
    float qz = pos1[(b * 3 + 2) * NPTS + n];
    float n1 = qx * qx + qy * qy + qz * qz;

    float bd[KNNC];
    int bi[KNNC];
#pragma unroll
    for (int j = 0; j < KNNC; j++) { bd[j] = 3.4e38f; bi[j] = 0; }

    __syncthreads();
    int base = half * 2048;
#pragma unroll 4
    for (int m = 0; m < 2048; m++) {
        int mm = base + m;
        float dot = fmaf(qx, sx[mm], fmaf(qy, sy[mm], qz * sz[mm]));
        float d = n1 + sq2[mm] - 2.f * dot;
        if (d < bd[KNNC - 1]) {
            float cd = d; int ci = mm;
#pragma unroll
            for (int j = 0; j < KNNC; j++) {
                if (cd < bd[j]) {
                    float td = bd[j]; bd[j] = cd; cd = td;
                    int ti = bi[j]; bi[j] = ci; ci = ti;
                }
            }
        }
    }
    // both halves dump their sorted lists to smem
#pragma unroll
    for (int j = 0; j < KNNC; j++) { smd[tid][j] = bd[j]; smi[tid][j] = bi[j]; }
    __syncthreads();

    if (!half) {
        // merge lists for query q: list A (chunk0, lower indices) wins ties
        const float* A = smd[q];  const int* Ai = smi[q];
        const float* Bm = smd[256 + q]; const int* Bi = smi[256 + q];
        int ia = 0, ib = 0;
#pragma unroll
        for (int t = 0; t < KNNC; t++) {
            float da = A[ia], db = Bm[ib];
            if (da <= db) { g_idx[(b * NPTS + n) * KNNC + t] = Ai[ia]; ia++; }
            else          { g_idx[(b * NPTS + n) * KNNC + t] = Bi[ib]; ib++; }
        }
    }
}

// ================= attn kernel A: gather + pos-mlp + attn-mlp layer 1 =================
// grid (N/PPB, B), block 256. Writes g_a (relu'd hidden) and g_vg.
__global__ __launch_bounds__(256) void attn_a_kernel(
    const float* __restrict__ pos1, const float* __restrict__ pos2,
    const float* __restrict__ pw1, const float* __restrict__ pb1,
    const float* __restrict__ pg,  const float* __restrict__ pbt,
    const float* __restrict__ pm,  const float* __restrict__ pv,
    const float* __restrict__ pb2,
    const float* __restrict__ ab1,
    const float* __restrict__ ag,  const float* __restrict__ abt2,
    const float* __restrict__ am,  const float* __restrict__ av)
{
    int b = blockIdx.y;
    int n0 = blockIdx.x * PPB;
    int tid = threadIdx.x;

    __shared__ __align__(16) float s_h[PPB * DIMC * KNNC];    // 10 KB
    __shared__ __align__(16) float s_vg[PPB * DIMC * KNNC];   // 10 KB
    __shared__ __align__(16) float s_a[PPB * HATTC * KNNC];   // 40 KB
    __shared__ __align__(16) float s_pe1[HPOSC * 24];         // 6 KB (per-point, reused)
    __shared__ float s_q[PPB * DIMC];
    __shared__ float s_prel[PPB * 3 * KNNC];
    __shared__ int   s_idx[PPB * KNNC];

    // ---- Phase 0: load idx, q, pos_rel, gathers ----
    if (tid < PPB * KNNC) {
        int p = tid / KNNC, k = tid - p * KNNC;
        s_idx[tid] = g_idx[(b * NPTS + n0 + p) * KNNC + k];
    }
    if (tid < PPB * DIMC) {
        int p = tid >> 6, o = tid & 63;
        s_q[tid] = g_qt[(b * NPTS + n0 + p) * DIMC + o];
    }
    __syncthreads();

    if (tid < PPB * 3 * KNNC) {
        int p = tid / (3 * KNNC), rem = tid - p * 3 * KNNC;
        int c = rem / KNNC, k = rem - c * KNNC;
        s_prel[tid] = pos1[(b * 3 + c) * NPTS + n0 + p]
                    - pos2[(b * 3 + c) * NPTS2 + s_idx[p * KNNC + k]];
    }
#pragma unroll
    for (int p = 0; p < PPB; p++) {
        for (int e = tid; e < DIMC * KNNC; e += 256) {
            int k = e >> 6, o = e & 63;
            int m = s_idx[p * KNNC + k];
            s_h[p * DIMC * KNNC + o * KNNC + k]  = s_q[p * DIMC + o] - g_kt[(b * NPTS2 + m) * DIMC + o];
            s_vg[p * DIMC * KNNC + o * KNNC + k] = g_vt[(b * NPTS2 + m) * DIMC + o];
        }
    }
    __syncthreads();

    // ---- Phase 1 + 1b per point (s_pe1 reused) ----
#pragma unroll
    for (int p = 0; p < PPB; p++) {
        for (int e = tid; e < HPOSC * 24; e += 256) {
            int h = e / 24, k = e - h * 24;
            float val = 0.f;
            if (k < KNNC) {
                const float* pr = s_prel + p * 3 * KNNC;
                float acc = fmaf(pw1[h * 3 + 0], pr[k],
                            fmaf(pw1[h * 3 + 1], pr[KNNC + k],
                                 pw1[h * 3 + 2] * pr[2 * KNNC + k])) + pb1[h];
                float inv = pg[h] * rsqrtf(pv[h] + EPSV);
                acc = fmaf(acc, inv, pbt[h] - pm[h] * inv);
                val = fmaxf(acc, 0.f);
            }
            s_pe1[e] = val;
        }
        __syncthreads();
        {
            int op = tid & 31, kg = tid >> 5;   // 32 o-pairs x 8 groups of 3 k
            int o0 = op * 2, k0 = kg * 3;
            unsigned long long acc[3] = {0ULL, 0ULL, 0ULL};
#pragma unroll 4
            for (int h = 0; h < HPOSC; h++) {
                unsigned long long w2 =
                    *reinterpret_cast<const unsigned long long*>(g_pw2t + h * DIMC + o0);
                const float* br = s_pe1 + h * 24 + k0;
                acc[0] = ffma2(w2, pack2(br[0], br[0]), acc[0]);
                acc[1] = ffma2(w2, pack2(br[1], br[1]), acc[1]);
                acc[2] = ffma2(w2, pack2(br[2], br[2]), acc[2]);
            }
            float b0 = pb2[o0], b1 = pb2[o0 + 1];
            float* hb = s_h + p * DIMC * KNNC;
            float* vb = s_vg + p * DIMC * KNNC;
#pragma unroll
            for (int j = 0; j < 3; j++) {
                int k = k0 + j;
                if (k < KNNC) {
                    float lo, hi;
                    unpack2(acc[j], lo, hi);
                    float v0 = lo + b0, v1 = hi + b1;
                    hb[o0 * KNNC + k] += v0;
                    vb[o0 * KNNC + k] += v0;
                    hb[(o0 + 1) * KNNC + k] += v1;
                    vb[(o0 + 1) * KNNC + k] += v1;
                }
            }
        }
        __syncthreads();
    }

    // ---- Phase 2: a = relu(bn(aw1 @ h)); thread=(p, c0), two channel passes ----
    {
        int p2 = tid >> 7, c0 = tid & 127;
        const float* hb = s_h + p2 * DIMC * KNNC;
#pragma unroll
        for (int pass = 0; pass < 2; pass++) {
            int c = c0 + pass * 128;
            unsigned long long acc[10];
#pragma unroll
            for (int j = 0; j < 10; j++) acc[j] = 0ULL;
#pragma unroll 4
            for (int o = 0; o < DIMC; o++) {
                float w = g_aw1t[o * HATTC + c];
                unsigned long long wp = pack2(w, w);
                const ulonglong2* hr = reinterpret_cast<const ulonglong2*>(hb + o * KNNC);
#pragma unroll
                for (int j = 0; j < 5; j++) {
                    ulonglong2 hv = hr[j];
                    acc[2 * j]     = ffma2(wp, hv.x, acc[2 * j]);
                    acc[2 * j + 1] = ffma2(wp, hv.y, acc[2 * j + 1]);
                }
            }
            float inv = ag[c] * rsqrtf(av[c] + EPSV);
            float bias = fmaf(ab1[c], inv, abt2[c]) - am[c] * inv;
            unsigned long long* row =
                reinterpret_cast<unsigned long long*>(s_a + p2 * HATTC * KNNC + c * KNNC);
#pragma unroll
            for (int j = 0; j < 10; j++) {
                float lo, hi;
                unpack2(acc[j], lo, hi);
                lo = fmaxf(fmaf(lo, inv, bias), 0.f);
                hi = fmaxf(fmaf(hi, inv, bias), 0.f);
                row[j] = pack2(lo, hi);
            }
        }
    }
    __syncthreads();

    // ---- write out a and vg (coalesced float4) ----
    {
        const float4* src = reinterpret_cast<const float4*>(s_a);
        float4* dst = reinterpret_cast<float4*>(g_a + ((size_t)(b * NPTS) + n0) * HATTC * KNNC);
        for (int e = tid; e < PPB * HATTC * KNNC / 4; e += 256) dst[e] = src[e];
        const float4* srcv = reinterpret_cast<const float4*>(s_vg);
        float4* dstv = reinterpret_cast<float4*>(g_vg + ((size_t)(b * NPTS) + n0) * DIMC * KNNC);
        for (int e = tid; e < PPB * DIMC * KNNC / 4; e += 256) dstv[e] = srcv[e];
    }
}

// ================= attn kernel B: attn weights + softmax + aggregate + output =================
// grid (N/PPB, B), block 256. thread = (row 0..127, p).
__global__ __launch_bounds__(256) void attn_b_kernel(
    const float* __restrict__ awt, const float* __restrict__ abt,
    const float* __restrict__ we,  const float* __restrict__ be,
    const float* __restrict__ query,
    float* __restrict__ out)
{
    int b = blockIdx.y;
    int n0 = blockIdx.x * PPB;
    int tid = threadIdx.x;

    __shared__ __align__(16) float s_a[PPB * HATTC * KNNC];   // 40 KB
    __shared__ __align__(16) float s_vg[PPB * DIMC * KNNC];   // 10 KB
    __shared__ float s_agg[PPB * DIMC * UPF];

    // ---- load a and vg ----
    {
        const float4* src = reinterpret_cast<const float4*>(g_a + ((size_t)(b * NPTS) + n0) * HATTC * KNNC);
        float4* dst = reinterpret_cast<float4*>(s_a);
        for (int e = tid; e < PPB * HATTC * KNNC / 4; e += 256) dst[e] = src[e];
        const float4* srcv = reinterpret_cast<const float4*>(g_vg + ((size_t)(b * NPTS) + n0) * DIMC * KNNC);
        float4* dstv = reinterpret_cast<float4*>(s_vg);
        for (int e = tid; e < PPB * DIMC * KNNC / 4; e += 256) dstv[e] = srcv[e];
    }
    __syncthreads();

    // ---- att = awt^T @ a over all 256 channels; softmax in registers ----
    int row = tid & 127;
    int p = tid >> 7;
    {
        unsigned long long acc[10];
#pragma unroll
        for (int j = 0; j < 10; j++) acc[j] = 0ULL;
        const float* ab = s_a + p * HATTC * KNNC;
        const float* wb = awt + row;
#pragma unroll 4
        for (int cc = 0; cc < HATTC; cc++) {
            float w = wb[cc * (DIMC * UPF)];
            unsigned long long wp = pack2(w, w);
            const ulonglong2* ar = reinterpret_cast<const ulonglong2*>(ab + cc * KNNC);
#pragma unroll
            for (int j = 0; j < 5; j++) {
                ulonglong2 av2 = ar[j];
                acc[2 * j]     = ffma2(wp, av2.x, acc[2 * j]);
                acc[2 * j + 1] = ffma2(wp, av2.y, acc[2 * j + 1]);
            }
        }
        int o = row >> 1;
        float abias = abt[o];
        float vals[KNNC];
        float mx = -3.4e38f;
#pragma unroll
        for (int j = 0; j < 10; j++) {
            float lo, hi;
            unpack2(acc[j], lo, hi);
            float t0 = lo + abias;
            float t1 = hi + abias;
            vals[2 * j] = t0;
            vals[2 * j + 1] = t1;
            mx = fmaxf(mx, fmaxf(t0, t1));
        }
        float vr[KNNC];
        {
            const float4* vgr = reinterpret_cast<const float4*>(s_vg + p * DIMC * KNNC + o * KNNC);
#pragma unroll
            for (int j = 0; j < 5; j++) {
                float4 v4 = vgr[j];
                vr[4 * j] = v4.x; vr[4 * j + 1] = v4.y; vr[4 * j + 2] = v4.z; vr[4 * j + 3] = v4.w;
            }
        }
        float s = 0.f, wsum = 0.f;
#pragma unroll
        for (int k = 0; k < KNNC; k++) {
            float e = expf(vals[k] - mx);
            s += e;
            wsum = fmaf(e, vr[k], wsum);
        }
        s_agg[p * DIMC * UPF + row] = wsum / s;   // row = o*2 + r
    }
    __syncthreads();

    // ---- y = we @ agg + be + residual ----
    {
        int c2 = tid >> 1, r = tid & 1;
        float accp[PPB];
#pragma unroll
        for (int pp = 0; pp < PPB; pp++) accp[pp] = 0.f;
        const float4* w4 = reinterpret_cast<const float4*>(we + c2 * DIMC);
#pragma unroll 4
        for (int o4 = 0; o4 < DIMC / 4; o4++) {
            float4 w = w4[o4];
#pragma unroll
            for (int j = 0; j < 4; j++) {
                float wj = (j == 0) ? w.x : (j == 1) ? w.y : (j == 2) ? w.z : w.w;
                int o = o4 * 4 + j;
#pragma unroll
                for (int pp = 0; pp < PPB; pp++)
                    accp[pp] = fmaf(wj, s_agg[pp * DIMC * UPF + o * UPF + r], accp[pp]);
            }
        }
        float bb = be[c2];
#pragma unroll
        for (int pp = 0; pp < PPB; pp++) {
            out[((size_t)(b * CINC + c2)) * (NPTS * UPF) + 2 * (size_t)(n0 + pp) + r] =
                accp[pp] + bb + query[(b * CINC + c2) * NPTS + n0 + pp];
        }
    }
}

// ================= launch =================
extern "C" void kernel_launch(void* const* d_in, const int* in_sizes, int n_in,
                              void* d_out, int out_size)
{
    const float* pos1     = (const float*)d_in[0];
    const float* query    = (const float*)d_in[1];
    const float* pos2     = (const float*)d_in[2];
    const float* key_feat = (const float*)d_in[3];
    const float* wq  = (const float*)d_in[4];
    const float* bq  = (const float*)d_in[5];
    const float* wk  = (const float*)d_in[6];
    const float* bk  = (const float*)d_in[7];
    const float* wv  = (const float*)d_in[8];
    const float* bv  = (const float*)d_in[9];
    const float* pw1 = (const float*)d_in[10];
    const float* pb1 = (const float*)d_in[11];
    const float* pg  = (const float*)d_in[12];
    const float* pbt = (const float*)d_in[13];
    const float* pm  = (const float*)d_in[14];
    const float* pv  = (const float*)d_in[15];
    const float* pw2 = (const float*)d_in[16];
    const float* pb2 = (const float*)d_in[17];
    const float* aw1 = (const float*)d_in[18];
    const float* ab1 = (const float*)d_in[19];
    const float* ag  = (const float*)d_in[20];
    const float* abt2= (const float*)d_in[21];
    const float* am  = (const float*)d_in[22];
    const float* av  = (const float*)d_in[23];
    const float* awt = (const float*)d_in[24];
    const float* abt = (const float*)d_in[25];
    const float* we  = (const float*)d_in[26];
    const float* be  = (const float*)d_in[27];
    float* out = (float*)d_out;

    prep_kernel<<<64, 256>>>(aw1, pw2, wq, wk, wv);
    qkv_kernel<<<dim3(NPTS / 128, BATCH), 256>>>(query, key_feat, bq, bk, bv);
    knn_kernel<<<dim3(NPTS / 256, BATCH), 512>>>(pos1, pos2);
    attn_a_kernel<<<dim3(NPTS / PPB, BATCH), 256>>>(
        pos1, pos2,
        pw1, pb1, pg, pbt, pm, pv, pb2,
        ab1, ag, abt2, am, av);
    attn_b_kernel<<<dim3(NPTS / PPB, BATCH), 256>>>(
        awt, abt, we, be, query, out);
}

// round 5
// speedup vs baseline: 1.3705x; 1.3705x over previous
#include <cuda_runtime.h>
#include <math.h>

#define BATCH 4
#define NPTS 4096
#define NPTS2 4096
#define CINC 128
#define DIMC 64
#define KNNC 20
#define UPF 2
#define HPOSC 64
#define HATTC 256
#define EPSV 1e-5f
#define PPB 2          // points per block in attn

// ---------------- scratch (static device memory; no allocations) ----------------
__device__ float g_qt[BATCH * NPTS * DIMC];     // (b, n, o) point-major
__device__ float g_kt[BATCH * NPTS2 * DIMC];
__device__ float g_vt[BATCH * NPTS2 * DIMC];
__device__ int   g_idx[BATCH * NPTS * KNNC];
__device__ float g_aw1p[DIMC * HATTC];          // paired: [o][2c']=(aw1[c'][o], aw1[c'+128][o])
__device__ float g_pw2t[HPOSC * DIMC];          // pw2 transposed: [h][o]
__device__ float g_wqt[CINC * DIMC];            // wq transposed: [c][o]
__device__ float g_wkt[CINC * DIMC];
__device__ float g_wvt[CINC * DIMC];

// ---------------- packed f32x2 helpers ----------------
__device__ __forceinline__ unsigned long long ffma2(
    unsigned long long a, unsigned long long b, unsigned long long c) {
    unsigned long long d;
    asm("fma.rn.f32x2 %0, %1, %2, %3;" : "=l"(d) : "l"(a), "l"(b), "l"(c));
    return d;
}
__device__ __forceinline__ unsigned long long pack2(float lo, float hi) {
    unsigned long long d;
    asm("mov.b64 %0, {%1, %2};" : "=l"(d) : "f"(lo), "f"(hi));
    return d;
}
__device__ __forceinline__ void unpack2(unsigned long long v, float& lo, float& hi) {
    asm("mov.b64 {%0, %1}, %2;" : "=f"(lo), "=f"(hi) : "l"(v));
}

// ================= prep: transpose/pair small weights =================
__global__ __launch_bounds__(256) void prep_kernel(
    const float* __restrict__ aw1, const float* __restrict__ pw2,
    const float* __restrict__ wq, const float* __restrict__ wk,
    const float* __restrict__ wv)
{
    int i = blockIdx.x * 256 + threadIdx.x;
    if (i < DIMC * 128) {              // pair aw1 columns c and c+128
        int o = i >> 7, c = i & 127;
        g_aw1p[o * HATTC + 2 * c]     = aw1[c * DIMC + o];
        g_aw1p[o * HATTC + 2 * c + 1] = aw1[(c + 128) * DIMC + o];
    }
    if (i < DIMC * HPOSC) {            // pw2[o][h] -> g_pw2t[h][o]
        int o = i >> 6, h = i & 63;
        g_pw2t[h * DIMC + o] = pw2[i];
    }
    if (i < DIMC * CINC) {             // w[o][c] -> g_wt[c][o]
        int o = i >> 7, c = i & 127;
        g_wqt[c * DIMC + o] = wq[i];
        g_wkt[c * DIMC + o] = wk[i];
        g_wvt[c * DIMC + o] = wv[i];
    }
}

// ================= QKV projection kernel =================
// grid (N/128, B), block 256. thread = (o, point-quarter).
__global__ __launch_bounds__(256) void qkv_kernel(
    const float* __restrict__ query, const float* __restrict__ key_feat,
    const float* __restrict__ bq, const float* __restrict__ bk,
    const float* __restrict__ bv)
{
    int b = blockIdx.y;
    int n0 = blockIdx.x * 128;
    int tid = threadIdx.x;
    __shared__ __align__(16) float tile[CINC * 128];   // 64 KB

    int o = tid & 63;
    int jb = tid >> 6;                 // 0..3 -> points jb*32 .. jb*32+31

    for (int i = tid; i < CINC * 128; i += 256) {
        int c = i >> 7, j = i & 127;
        tile[i] = query[(b * CINC + c) * NPTS + n0 + j];
    }
    __syncthreads();
    {
        unsigned long long acc[16];
#pragma unroll
        for (int m = 0; m < 16; m++) acc[m] = 0ULL;
#pragma unroll 4
        for (int c = 0; c < CINC; c++) {
            float w = g_wqt[c * DIMC + o];
            unsigned long long wp = pack2(w, w);
            const ulonglong2* tp = reinterpret_cast<const ulonglong2*>(tile + c * 128 + jb * 32);
#pragma unroll
            for (int jj = 0; jj < 8; jj++) {
                ulonglong2 t = tp[jj];
                acc[2 * jj]     = ffma2(wp, t.x, acc[2 * jj]);
                acc[2 * jj + 1] = ffma2(wp, t.y, acc[2 * jj + 1]);
            }
        }
        float bias = bq[o];
#pragma unroll
        for (int m = 0; m < 16; m++) {
            float lo, hi;
            unpack2(acc[m], lo, hi);
            int j = jb * 32 + 2 * m;
            g_qt[(b * NPTS + n0 + j) * DIMC + o]     = lo + bias;
            g_qt[(b * NPTS + n0 + j + 1) * DIMC + o] = hi + bias;
        }
    }
    __syncthreads();
    for (int i = tid; i < CINC * 128; i += 256) {
        int c = i >> 7, j = i & 127;
        tile[i] = key_feat[(b * CINC + c) * NPTS2 + n0 + j];
    }
    __syncthreads();
#pragma unroll
    for (int which = 0; which < 2; which++) {
        const float* wt = which ? g_wvt : g_wkt;
        float* gout = which ? g_vt : g_kt;
        float bias = which ? bv[o] : bk[o];
        unsigned long long acc[16];
#pragma unroll
        for (int m = 0; m < 16; m++) acc[m] = 0ULL;
#pragma unroll 4
        for (int c = 0; c < CINC; c++) {
            float w = wt[c * DIMC + o];
            unsigned long long wp = pack2(w, w);
            const ulonglong2* tp = reinterpret_cast<const ulonglong2*>(tile + c * 128 + jb * 32);
#pragma unroll
            for (int jj = 0; jj < 8; jj++) {
                ulonglong2 t = tp[jj];
                acc[2 * jj]     = ffma2(wp, t.x, acc[2 * jj]);
                acc[2 * jj + 1] = ffma2(wp, t.y, acc[2 * jj + 1]);
            }
        }
#pragma unroll
        for (int m = 0; m < 16; m++) {
            float lo, hi;
            unpack2(acc[m], lo, hi);
            int j = jb * 32 + 2 * m;
            gout[(b * NPTS2 + n0 + j) * DIMC + o]     = lo + bias;
            gout[(b * NPTS2 + n0 + j + 1) * DIMC + o] = hi + bias;
        }
    }
}

// ================= KNN kernel =================
// grid (N/128, B), block 512. Four threads per query, each scans a quarter of support.
__global__ __launch_bounds__(512) void knn_kernel(
    const float* __restrict__ pos1, const float* __restrict__ pos2)
{
    int b = blockIdx.y;
    int tid = threadIdx.x;
    int q = tid & 127;
    int quarter = tid >> 7;            // 0..3
    int n = blockIdx.x * 128 + q;

    __shared__ float sx[4096], sy[4096], sz[4096], sq2[4096];  // 64 KB
    __shared__ float smd[512][KNNC];                           // 40 KB
    __shared__ int   smi[512][KNNC];                           // 40 KB

    for (int i = tid; i < 4096; i += 512) {
        float x = pos2[(b * 3 + 0) * NPTS2 + i];
        float y = pos2[(b * 3 + 1) * NPTS2 + i];
        float z = pos2[(b * 3 + 2) * NPTS2 + i];
        sx[i] = x; sy[i] = y; sz[i] = z;
        sq2[i] = x * x + y * y + z * z;
    }

    float qx = pos1[(b * 3 + 0) * NPTS + n];
    float qy = pos1[(b * 3 + 1) * NPTS + n];
    float qz = pos1[(b * 3 + 2) * NPTS + n];
    float n1 = qx * qx + qy * qy + qz * qz;

    float bd[KNNC];
    int bi[KNNC];
#pragma unroll
    for (int j = 0; j < KNNC; j++) { bd[j] = 3.4e38f; bi[j] = 0; }

    __syncthreads();
    int base = quarter * 1024;
#pragma unroll 4
    for (int m = 0; m < 1024; m++) {
        int mm = base + m;
        float dot = fmaf(qx, sx[mm], fmaf(qy, sy[mm], qz * sz[mm]));
        float d = n1 + sq2[mm] - 2.f * dot;
        if (d < bd[KNNC - 1]) {
            float cd = d; int ci = mm;
#pragma unroll
            for (int j = 0; j < KNNC; j++) {
                if (cd < bd[j]) {
                    float td = bd[j]; bd[j] = cd; cd = td;
                    int ti = bi[j]; bi[j] = ci; ci = ti;
                }
            }
        }
    }
#pragma unroll
    for (int j = 0; j < KNNC; j++) { smd[tid][j] = bd[j]; smi[tid][j] = bi[j]; }
    __syncthreads();

    if (quarter == 0) {
        // stable 4-way merge; earlier quarter (lower index range) wins ties
        int head[4] = {0, 0, 0, 0};
#pragma unroll
        for (int t = 0; t < KNNC; t++) {
            float best = 3.5e38f;
            int bqv = 0;
#pragma unroll
            for (int qu = 0; qu < 4; qu++) {
                if (head[qu] < KNNC) {
                    float v = smd[qu * 128 + q][head[qu]];
                    if (v < best) { best = v; bqv = qu; }
                }
            }
            g_idx[(b * NPTS + n) * KNNC + t] = smi[bqv * 128 + q][head[bqv]];
            head[bqv]++;
        }
    }
}

// ================= Fused per-point attention kernel =================
// grid (N/PPB, B), block 256, 3 blocks/SM target.
__global__ __launch_bounds__(256, 3) void attn_kernel(
    const float* __restrict__ pos1, const float* __restrict__ pos2,
    const float* __restrict__ query,
    const float* __restrict__ pw1, const float* __restrict__ pb1,
    const float* __restrict__ pg,  const float* __restrict__ pbt,
    const float* __restrict__ pm,  const float* __restrict__ pv,
    const float* __restrict__ pb2,
    const float* __restrict__ ab1,
    const float* __restrict__ ag,  const float* __restrict__ abt2,
    const float* __restrict__ am,  const float* __restrict__ av,
    const float* __restrict__ awt, const float* __restrict__ abt,
    const float* __restrict__ we,  const float* __restrict__ be,
    float* __restrict__ out)
{
    int b = blockIdx.y;
    int n0 = blockIdx.x * PPB;
    int tid = threadIdx.x;

    __shared__ __align__(16) float s_h[PPB * DIMC * KNNC];    // 10 KB
    __shared__ __align__(16) float s_vg[PPB * DIMC * KNNC];   // 10 KB
    __shared__ __align__(16) float s_a[PPB * HATTC * KNNC];   // 40 KB; reused for phase-3 partials
    __shared__ __align__(16) float s_pe1[HPOSC * 24];         // 6 KB, reused per point
    __shared__ float s_q[PPB * DIMC];
    __shared__ float s_prel[PPB * 3 * KNNC];
    __shared__ float s_agg[PPB * DIMC * UPF];
    __shared__ int   s_idx[PPB * KNNC];

    // ---- Phase 0: load idx, q, pos_rel, gathers ----
    if (tid < PPB * KNNC) {
        int p = tid / KNNC, k = tid - p * KNNC;
        s_idx[tid] = g_idx[(b * NPTS + n0 + p) * KNNC + k];
    }
    if (tid < PPB * DIMC) {
        int p = tid >> 6, o = tid & 63;
        s_q[tid] = g_qt[(b * NPTS + n0 + p) * DIMC + o];
    }
    __syncthreads();

    if (tid < PPB * 3 * KNNC) {
        int p = tid / (3 * KNNC), rem = tid - p * 3 * KNNC;
        int c = rem / KNNC, k = rem - c * KNNC;
        s_prel[tid] = pos1[(b * 3 + c) * NPTS + n0 + p]
                    - pos2[(b * 3 + c) * NPTS2 + s_idx[p * KNNC + k]];
    }
#pragma unroll
    for (int p = 0; p < PPB; p++) {
        for (int e = tid; e < DIMC * KNNC; e += 256) {
            int k = e >> 6, o = e & 63;
            int m = s_idx[p * KNNC + k];
            s_h[p * DIMC * KNNC + o * KNNC + k]  = s_q[p * DIMC + o] - g_kt[(b * NPTS2 + m) * DIMC + o];
            s_vg[p * DIMC * KNNC + o * KNNC + k] = g_vt[(b * NPTS2 + m) * DIMC + o];
        }
    }
    __syncthreads();

    // ---- Phase 1 + 1b per point (s_pe1 reused) ----
#pragma unroll
    for (int p = 0; p < PPB; p++) {
        for (int e = tid; e < HPOSC * 24; e += 256) {
            int h = e / 24, k = e - h * 24;
            float val = 0.f;
            if (k < KNNC) {
                const float* pr = s_prel + p * 3 * KNNC;
                float acc = fmaf(pw1[h * 3 + 0], pr[k],
                            fmaf(pw1[h * 3 + 1], pr[KNNC + k],
                                 pw1[h * 3 + 2] * pr[2 * KNNC + k])) + pb1[h];
                float inv = pg[h] * rsqrtf(pv[h] + EPSV);
                acc = fmaf(acc, inv, pbt[h] - pm[h] * inv);
                val = fmaxf(acc, 0.f);
            }
            s_pe1[e] = val;
        }
        __syncthreads();
        {
            int op = tid & 31, kg = tid >> 5;   // 32 o-pairs x 8 groups of 3 k
            int o0 = op * 2, k0 = kg * 3;
            unsigned long long acc[3] = {0ULL, 0ULL, 0ULL};
#pragma unroll 4
            for (int h = 0; h < HPOSC; h++) {
                unsigned long long w2 =
                    *reinterpret_cast<const unsigned long long*>(g_pw2t + h * DIMC + o0);
                const float* br = s_pe1 + h * 24 + k0;
                acc[0] = ffma2(w2, pack2(br[0], br[0]), acc[0]);
                acc[1] = ffma2(w2, pack2(br[1], br[1]), acc[1]);
                acc[2] = ffma2(w2, pack2(br[2], br[2]), acc[2]);
            }
            float b0 = pb2[o0], b1 = pb2[o0 + 1];
            float* hb = s_h + p * DIMC * KNNC;
            float* vb = s_vg + p * DIMC * KNNC;
#pragma unroll
            for (int j = 0; j < 3; j++) {
                int k = k0 + j;
                if (k < KNNC) {
                    float lo, hi;
                    unpack2(acc[j], lo, hi);
                    float v0 = lo + b0, v1 = hi + b1;
                    hb[o0 * KNNC + k] += v0;
                    vb[o0 * KNNC + k] += v0;
                    hb[(o0 + 1) * KNNC + k] += v1;
                    vb[(o0 + 1) * KNNC + k] += v1;
                }
            }
        }
        __syncthreads();
    }

    // ---- Phase 2: a = relu(bn(aw1 @ h)); thread=(p, c); computes c and c+128 ----
    {
        int c = tid & 127, p = tid >> 7;
        unsigned long long acc[2][10];
#pragma unroll
        for (int j = 0; j < 10; j++) { acc[0][j] = 0ULL; acc[1][j] = 0ULL; }
        const float* hb = s_h + p * DIMC * KNNC;
#pragma unroll 4
        for (int o = 0; o < DIMC; o++) {
            unsigned long long wpair =
                *reinterpret_cast<const unsigned long long*>(g_aw1p + o * HATTC + 2 * c);
            float w0, w1;
            unpack2(wpair, w0, w1);
            unsigned long long wp0 = pack2(w0, w0);
            unsigned long long wp1 = pack2(w1, w1);
            const ulonglong2* hr = reinterpret_cast<const ulonglong2*>(hb + o * KNNC);
#pragma unroll
            for (int j = 0; j < 5; j++) {
                ulonglong2 hv = hr[j];
                acc[0][2 * j]     = ffma2(wp0, hv.x, acc[0][2 * j]);
                acc[0][2 * j + 1] = ffma2(wp0, hv.y, acc[0][2 * j + 1]);
                acc[1][2 * j]     = ffma2(wp1, hv.x, acc[1][2 * j]);
                acc[1][2 * j + 1] = ffma2(wp1, hv.y, acc[1][2 * j + 1]);
            }
        }
#pragma unroll
        for (int cc = 0; cc < 2; cc++) {
            int cg = c + cc * 128;
            float inv = ag[cg] * rsqrtf(av[cg] + EPSV);
            float bias = fmaf(ab1[cg], inv, abt2[cg]) - am[cg] * inv;
            unsigned long long* row =
                reinterpret_cast<unsigned long long*>(s_a + p * HATTC * KNNC + cg * KNNC);
#pragma unroll
            for (int j = 0; j < 10; j++) {
                float lo, hi;
                unpack2(acc[cc][j], lo, hi);
                lo = fmaxf(fmaf(lo, inv, bias), 0.f);
                hi = fmaxf(fmaf(hi, inv, bias), 0.f);
                row[j] = pack2(lo, hi);
            }
        }
    }
    __syncthreads();

    // ---- Phase 3: att partial = awt^T @ a; thread = (rowpair t, chalf, point) ----
    int t = tid & 63;               // rows 2t, 2t+1
    int chalf = (tid >> 6) & 1;     // channel half
    int p3 = tid >> 7;              // point
    unsigned long long acc3[2][10];
    {
#pragma unroll
        for (int j = 0; j < 10; j++) { acc3[0][j] = 0ULL; acc3[1][j] = 0ULL; }
        const float* wb = awt + (chalf * 128) * (DIMC * UPF) + 2 * t;
        const float* ab = s_a + p3 * HATTC * KNNC + (chalf * 128) * KNNC;
#pragma unroll 4
        for (int cc = 0; cc < 128; cc++) {
            float2 w2 = *reinterpret_cast<const float2*>(wb + cc * (DIMC * UPF));
            unsigned long long wp0 = pack2(w2.x, w2.x);
            unsigned long long wp1 = pack2(w2.y, w2.y);
            const ulonglong2* ar = reinterpret_cast<const ulonglong2*>(ab + cc * KNNC);
#pragma unroll
            for (int j = 0; j < 5; j++) {
                ulonglong2 av2 = ar[j];
                acc3[0][2 * j]     = ffma2(wp0, av2.x, acc3[0][2 * j]);
                acc3[0][2 * j + 1] = ffma2(wp0, av2.y, acc3[0][2 * j + 1]);
                acc3[1][2 * j]     = ffma2(wp1, av2.x, acc3[1][2 * j]);
                acc3[1][2 * j + 1] = ffma2(wp1, av2.y, acc3[1][2 * j + 1]);
            }
        }
    }
    __syncthreads();   // all s_a reads done; safe to reuse as partial buffer
    if (chalf) {
        unsigned long long* dst =
            reinterpret_cast<unsigned long long*>(s_a + p3 * HATTC * KNNC) + t * 20;
#pragma unroll
        for (int j = 0; j < 10; j++) { dst[j] = acc3[0][j]; dst[10 + j] = acc3[1][j]; }
    }
    __syncthreads();

    // ---- Phase 4: combine halves, softmax over K, weighted sum with vg ----
    if (!chalf) {
        float ab = abt[t];
        const unsigned long long* part =
            reinterpret_cast<const unsigned long long*>(s_a + p3 * HATTC * KNNC) + t * 20;
        const float* vgr = s_vg + p3 * DIMC * KNNC + t * KNNC;
#pragma unroll
        for (int r = 0; r < 2; r++) {
            float vals[KNNC];
            float mx = -3.4e38f;
#pragma unroll
            for (int j = 0; j < 10; j++) {
                float lo, hi, plo, phi;
                unpack2(acc3[r][j], lo, hi);
                unpack2(part[r * 10 + j], plo, phi);
                float t0 = lo + plo + ab;
                float t1 = hi + phi + ab;
                vals[2 * j] = t0;
                vals[2 * j + 1] = t1;
                mx = fmaxf(mx, fmaxf(t0, t1));
            }
            float s = 0.f, wsum = 0.f;
#pragma unroll
            for (int k = 0; k < KNNC; k++) {
                float e = expf(vals[k] - mx);
                s += e;
                wsum = fmaf(e, vgr[k], wsum);
            }
            s_agg[p3 * DIMC * UPF + t * 2 + r] = wsum / s;   // row = o*2 + r
        }
    }
    __syncthreads();

    // ---- Phase 5: y = we @ agg + be + residual ----
    {
        int c2 = tid >> 1, r = tid & 1;
        float accp[PPB];
#pragma unroll
        for (int pp = 0; pp < PPB; pp++) accp[pp] = 0.f;
        const float4* w4 = reinterpret_cast<const float4*>(we + c2 * DIMC);
#pragma unroll 4
        for (int o4 = 0; o4 < DIMC / 4; o4++) {
            float4 w = w4[o4];
#pragma unroll
            for (int j = 0; j < 4; j++) {
                float wj = (j == 0) ? w.x : (j == 1) ? w.y : (j == 2) ? w.z : w.w;
                int o = o4 * 4 + j;
#pragma unroll
                for (int pp = 0; pp < PPB; pp++)
                    accp[pp] = fmaf(wj, s_agg[pp * DIMC * UPF + o * UPF + r], accp[pp]);
            }
        }
        float bb = be[c2];
#pragma unroll
        for (int pp = 0; pp < PPB; pp++) {
            out[((size_t)(b * CINC + c2)) * (NPTS * UPF) + 2 * (size_t)(n0 + pp) + r] =
                accp[pp] + bb + query[(b * CINC + c2) * NPTS + n0 + pp];
        }
    }
}

// ================= launch =================
extern "C" void kernel_launch(void* const* d_in, const int* in_sizes, int n_in,
                              void* d_out, int out_size)
{
    const float* pos1     = (const float*)d_in[0];
    const float* query    = (const float*)d_in[1];
    const float* pos2     = (const float*)d_in[2];
    const float* key_feat = (const float*)d_in[3];
    const float* wq  = (const float*)d_in[4];
    const float* bq  = (const float*)d_in[5];
    const float* wk  = (const float*)d_in[6];
    const float* bk  = (const float*)d_in[7];
    const float* wv  = (const float*)d_in[8];
    const float* bv  = (const float*)d_in[9];
    const float* pw1 = (const float*)d_in[10];
    const float* pb1 = (const float*)d_in[11];
    const float* pg  = (const float*)d_in[12];
    const float* pbt = (const float*)d_in[13];
    const float* pm  = (const float*)d_in[14];
    const float* pv  = (const float*)d_in[15];
    const float* pw2 = (const float*)d_in[16];
    const float* pb2 = (const float*)d_in[17];
    const float* aw1 = (const float*)d_in[18];
    const float* ab1 = (const float*)d_in[19];
    const float* ag  = (const float*)d_in[20];
    const float* abt2= (const float*)d_in[21];
    const float* am  = (const float*)d_in[22];
    const float* av  = (const float*)d_in[23];
    const float* awt = (const float*)d_in[24];
    const float* abt = (const float*)d_in[25];
    const float* we  = (const float*)d_in[26];
    const float* be  = (const float*)d_in[27];
    float* out = (float*)d_out;

    prep_kernel<<<64, 256>>>(aw1, pw2, wq, wk, wv);
    qkv_kernel<<<dim3(NPTS / 128, BATCH), 256>>>(query, key_feat, bq, bk, bv);
    knn_kernel<<<dim3(NPTS / 128, BATCH), 512>>>(pos1, pos2);
    attn_kernel<<<dim3(NPTS / PPB, BATCH), 256>>>(
        pos1, pos2, query,
        pw1, pb1, pg, pbt, pm, pv, pb2,
        ab1, ag, abt2, am, av, awt, abt, we, be, out);
}

// round 6
// speedup vs baseline: 1.3723x; 1.0013x over previous
#include <cuda_runtime.h>
#include <math.h>

#define BATCH 4
#define NPTS 4096
#define NPTS2 4096
#define CINC 128
#define DIMC 64
#define KNNC 20
#define UPF 2
#define HPOSC 64
#define HATTC 256
#define EPSV 1e-5f
#define PPB 2          // points per block in attn

// ---------------- scratch (static device memory; no allocations) ----------------
__device__ float g_qt[BATCH * NPTS * DIMC];     // (b, n, o) point-major
__device__ float g_kt[BATCH * NPTS2 * DIMC];
__device__ float g_vt[BATCH * NPTS2 * DIMC];
__device__ int   g_idx[BATCH * NPTS * KNNC];
__device__ float g_aw1p[DIMC * HATTC];          // paired: [o][2c']=(aw1[c'][o], aw1[c'+128][o])
__device__ float g_pw2t[HPOSC * DIMC];          // pw2 transposed: [h][o]
__device__ float g_wqt[CINC * DIMC];            // wq transposed: [c][o]
__device__ float g_wkt[CINC * DIMC];
__device__ float g_wvt[CINC * DIMC];

// ---------------- packed f32x2 helpers ----------------
__device__ __forceinline__ unsigned long long ffma2(
    unsigned long long a, unsigned long long b, unsigned long long c) {
    unsigned long long d;
    asm("fma.rn.f32x2 %0, %1, %2, %3;" : "=l"(d) : "l"(a), "l"(b), "l"(c));
    return d;
}
__device__ __forceinline__ unsigned long long pack2(float lo, float hi) {
    unsigned long long d;
    asm("mov.b64 %0, {%1, %2};" : "=l"(d) : "f"(lo), "f"(hi));
    return d;
}
__device__ __forceinline__ void unpack2(unsigned long long v, float& lo, float& hi) {
    asm("mov.b64 {%0, %1}, %2;" : "=f"(lo), "=f"(hi) : "l"(v));
}

// ================= prep: transpose/pair small weights =================
__global__ __launch_bounds__(256) void prep_kernel(
    const float* __restrict__ aw1, const float* __restrict__ pw2,
    const float* __restrict__ wq, const float* __restrict__ wk,
    const float* __restrict__ wv)
{
    int i = blockIdx.x * 256 + threadIdx.x;
    if (i < DIMC * 128) {              // pair aw1 columns c and c+128
        int o = i >> 7, c = i & 127;
        g_aw1p[o * HATTC + 2 * c]     = aw1[c * DIMC + o];
        g_aw1p[o * HATTC + 2 * c + 1] = aw1[(c + 128) * DIMC + o];
    }
    if (i < DIMC * HPOSC) {            // pw2[o][h] -> g_pw2t[h][o]
        int o = i >> 6, h = i & 63;
        g_pw2t[h * DIMC + o] = pw2[i];
    }
    if (i < DIMC * CINC) {             // w[o][c] -> g_wt[c][o]
        int o = i >> 7, c = i & 127;
        g_wqt[c * DIMC + o] = wq[i];
        g_wkt[c * DIMC + o] = wk[i];
        g_wvt[c * DIMC + o] = wv[i];
    }
}

// ================= QKV projection kernel =================
// grid (N/128, B), block 256. thread = (o, point-quarter).
__global__ __launch_bounds__(256) void qkv_kernel(
    const float* __restrict__ query, const float* __restrict__ key_feat,
    const float* __restrict__ bq, const float* __restrict__ bk,
    const float* __restrict__ bv)
{
    int b = blockIdx.y;
    int n0 = blockIdx.x * 128;
    int tid = threadIdx.x;
    __shared__ __align__(16) float tile[CINC * 128];   // 64 KB

    int o = tid & 63;
    int jb = tid >> 6;                 // 0..3 -> points jb*32 .. jb*32+31

    for (int i = tid; i < CINC * 128; i += 256) {
        int c = i >> 7, j = i & 127;
        tile[i] = query[(b * CINC + c) * NPTS + n0 + j];
    }
    __syncthreads();
    {
        unsigned long long acc[16];
#pragma unroll
        for (int m = 0; m < 16; m++) acc[m] = 0ULL;
#pragma unroll 4
        for (int c = 0; c < CINC; c++) {
            float w = g_wqt[c * DIMC + o];
            unsigned long long wp = pack2(w, w);
            const ulonglong2* tp = reinterpret_cast<const ulonglong2*>(tile + c * 128 + jb * 32);
#pragma unroll
            for (int jj = 0; jj < 8; jj++) {
                ulonglong2 t = tp[jj];
                acc[2 * jj]     = ffma2(wp, t.x, acc[2 * jj]);
                acc[2 * jj + 1] = ffma2(wp, t.y, acc[2 * jj + 1]);
            }
        }
        float bias = bq[o];
#pragma unroll
        for (int m = 0; m < 16; m++) {
            float lo, hi;
            unpack2(acc[m], lo, hi);
            int j = jb * 32 + 2 * m;
            g_qt[(b * NPTS + n0 + j) * DIMC + o]     = lo + bias;
            g_qt[(b * NPTS + n0 + j + 1) * DIMC + o] = hi + bias;
        }
    }
    __syncthreads();
    for (int i = tid; i < CINC * 128; i += 256) {
        int c = i >> 7, j = i & 127;
        tile[i] = key_feat[(b * CINC + c) * NPTS2 + n0 + j];
    }
    __syncthreads();
#pragma unroll
    for (int which = 0; which < 2; which++) {
        const float* wt = which ? g_wvt : g_wkt;
        float* gout = which ? g_vt : g_kt;
        float bias = which ? bv[o] : bk[o];
        unsigned long long acc[16];
#pragma unroll
        for (int m = 0; m < 16; m++) acc[m] = 0ULL;
#pragma unroll 4
        for (int c = 0; c < CINC; c++) {
            float w = wt[c * DIMC + o];
            unsigned long long wp = pack2(w, w);
            const ulonglong2* tp = reinterpret_cast<const ulonglong2*>(tile + c * 128 + jb * 32);
#pragma unroll
            for (int jj = 0; jj < 8; jj++) {
                ulonglong2 t = tp[jj];
                acc[2 * jj]     = ffma2(wp, t.x, acc[2 * jj]);
                acc[2 * jj + 1] = ffma2(wp, t.y, acc[2 * jj + 1]);
            }
        }
#pragma unroll
        for (int m = 0; m < 16; m++) {
            float lo, hi;
            unpack2(acc[m], lo, hi);
            int j = jb * 32 + 2 * m;
            gout[(b * NPTS2 + n0 + j) * DIMC + o]     = lo + bias;
            gout[(b * NPTS2 + n0 + j + 1) * DIMC + o] = hi + bias;
        }
    }
}

// ================= KNN kernel =================
// grid (N/128, B), block 512. Four threads per query, each scans a quarter of support.
__global__ __launch_bounds__(512) void knn_kernel(
    const float* __restrict__ pos1, const float* __restrict__ pos2)
{
    int b = blockIdx.y;
    int tid = threadIdx.x;
    int q = tid & 127;
    int quarter = tid >> 7;            // 0..3
    int n = blockIdx.x * 128 + q;

    __shared__ float sx[4096], sy[4096], sz[4096], sq2[4096];  // 64 KB
    __shared__ float smd[512][KNNC];                           // 40 KB
    __shared__ int   smi[512][KNNC];                           // 40 KB

    for (int i = tid; i < 4096; i += 512) {
        float x = pos2[(b * 3 + 0) * NPTS2 + i];
        float y = pos2[(b * 3 + 1) * NPTS2 + i];
        float z = pos2[(b * 3 + 2) * NPTS2 + i];
        sx[i] = x; sy[i] = y; sz[i] = z;
        sq2[i] = x * x + y * y + z * z;
    }

    float qx = pos1[(b * 3 + 0) * NPTS + n];
    float qy = pos1[(b * 3 + 1) * NPTS + n];
    float qz = pos1[(b * 3 + 2) * NPTS + n];
    float n1 = qx * qx + qy * qy + qz * qz;

    float bd[KNNC];
    int bi[KNNC];
#pragma unroll
    for (int j = 0; j < KNNC; j++) { bd[j] = 3.4e38f; bi[j] = 0; }

    __syncthreads();
    int base = quarter * 1024;
#pragma unroll 4
    for (int m = 0; m < 1024; m++) {
        int mm = base + m;
        float dot = fmaf(qx, sx[mm], fmaf(qy, sy[mm], qz * sz[mm]));
        float d = n1 + sq2[mm] - 2.f * dot;
        if (d < bd[KNNC - 1]) {
            float cd = d; int ci = mm;
#pragma unroll
            for (int j = 0; j < KNNC; j++) {
                if (cd < bd[j]) {
                    float td = bd[j]; bd[j] = cd; cd = td;
                    int ti = bi[j]; bi[j] = ci; ci = ti;
                }
            }
        }
    }
#pragma unroll
    for (int j = 0; j < KNNC; j++) { smd[tid][j] = bd[j]; smi[tid][j] = bi[j]; }
    __syncthreads();

    if (quarter == 0) {
        // stable 4-way merge; earlier quarter (lower index range) wins ties
        int head[4] = {0, 0, 0, 0};
#pragma unroll
        for (int t = 0; t < KNNC; t++) {
            float best = 3.5e38f;
            int bqv = 0;
#pragma unroll
            for (int qu = 0; qu < 4; qu++) {
                if (head[qu] < KNNC) {
                    float v = smd[qu * 128 + q][head[qu]];
                    if (v < best) { best = v; bqv = qu; }
                }
            }
            g_idx[(b * NPTS + n) * KNNC + t] = smi[bqv * 128 + q][head[bqv]];
            head[bqv]++;
        }
    }
}

// ================= Fused per-point attention kernel =================
// grid (N/PPB, B), block 256, 3 blocks/SM target.
__global__ __launch_bounds__(256, 3) void attn_kernel(
    const float* __restrict__ pos1, const float* __restrict__ pos2,
    const float* __restrict__ query,
    const float* __restrict__ pw1, const float* __restrict__ pb1,
    const float* __restrict__ pg,  const float* __restrict__ pbt,
    const float* __restrict__ pm,  const float* __restrict__ pv,
    const float* __restrict__ pb2,
    const float* __restrict__ ab1,
    const float* __restrict__ ag,  const float* __restrict__ abt2,
    const float* __restrict__ am,  const float* __restrict__ av,
    const float* __restrict__ awt, const float* __restrict__ abt,
    const float* __restrict__ we,  const float* __restrict__ be,
    float* __restrict__ out)
{
    int b = blockIdx.y;
    int n0 = blockIdx.x * PPB;
    int tid = threadIdx.x;

    __shared__ __align__(16) float s_h[PPB * DIMC * KNNC];    // 10 KB
    __shared__ __align__(16) float s_vg[PPB * DIMC * KNNC];   // 10 KB
    __shared__ __align__(16) float s_a[PPB * HATTC * KNNC];   // 40 KB; reused for phase-3 partials
    __shared__ __align__(16) float s_pe1[HPOSC * 24];         // 6 KB, reused per point
    __shared__ float s_q[PPB * DIMC];
    __shared__ float s_prel[PPB * 3 * KNNC];
    __shared__ float s_agg[PPB * DIMC * UPF];
    __shared__ int   s_idx[PPB * KNNC];

    // ---- Phase 0: load idx, q, pos_rel, gathers ----
    if (tid < PPB * KNNC) {
        int p = tid / KNNC, k = tid - p * KNNC;
        s_idx[tid] = g_idx[(b * NPTS + n0 + p) * KNNC + k];
    }
    if (tid < PPB * DIMC) {
        int p = tid >> 6, o = tid & 63;
        s_q[tid] = g_qt[(b * NPTS + n0 + p) * DIMC + o];
    }
    __syncthreads();

    if (tid < PPB * 3 * KNNC) {
        int p = tid / (3 * KNNC), rem = tid - p * 3 * KNNC;
        int c = rem / KNNC, k = rem - c * KNNC;
        s_prel[tid] = pos1[(b * 3 + c) * NPTS + n0 + p]
                    - pos2[(b * 3 + c) * NPTS2 + s_idx[p * KNNC + k]];
    }
#pragma unroll
    for (int p = 0; p < PPB; p++) {
        for (int e = tid; e < DIMC * KNNC; e += 256) {
            int k = e >> 6, o = e & 63;
            int m = s_idx[p * KNNC + k];
            s_h[p * DIMC * KNNC + o * KNNC + k]  = s_q[p * DIMC + o] - g_kt[(b * NPTS2 + m) * DIMC + o];
            s_vg[p * DIMC * KNNC + o * KNNC + k] = g_vt[(b * NPTS2 + m) * DIMC + o];
        }
    }
    __syncthreads();

    // ---- Phase 1 + 1b per point (s_pe1 reused) ----
#pragma unroll
    for (int p = 0; p < PPB; p++) {
        for (int e = tid; e < HPOSC * 24; e += 256) {
            int h = e / 24, k = e - h * 24;
            float val = 0.f;
            if (k < KNNC) {
                const float* pr = s_prel + p * 3 * KNNC;
                float acc = fmaf(pw1[h * 3 + 0], pr[k],
                            fmaf(pw1[h * 3 + 1], pr[KNNC + k],
                                 pw1[h * 3 + 2] * pr[2 * KNNC + k])) + pb1[h];
                float inv = pg[h] * rsqrtf(pv[h] + EPSV);
                acc = fmaf(acc, inv, pbt[h] - pm[h] * inv);
                val = fmaxf(acc, 0.f);
            }
            s_pe1[e] = val;
        }
        __syncthreads();
        {
            int op = tid & 31, kg = tid >> 5;   // 32 o-pairs x 8 groups of 3 k
            int o0 = op * 2, k0 = kg * 3;
            unsigned long long acc[3] = {0ULL, 0ULL, 0ULL};
#pragma unroll 4
            for (int h = 0; h < HPOSC; h++) {
                unsigned long long w2 =
                    *reinterpret_cast<const unsigned long long*>(g_pw2t + h * DIMC + o0);
                const float* br = s_pe1 + h * 24 + k0;
                acc[0] = ffma2(w2, pack2(br[0], br[0]), acc[0]);
                acc[1] = ffma2(w2, pack2(br[1], br[1]), acc[1]);
                acc[2] = ffma2(w2, pack2(br[2], br[2]), acc[2]);
            }
            float b0 = pb2[o0], b1 = pb2[o0 + 1];
            float* hb = s_h + p * DIMC * KNNC;
            float* vb = s_vg + p * DIMC * KNNC;
#pragma unroll
            for (int j = 0; j < 3; j++) {
                int k = k0 + j;
                if (k < KNNC) {
                    float lo, hi;
                    unpack2(acc[j], lo, hi);
                    float v0 = lo + b0, v1 = hi + b1;
                    hb[o0 * KNNC + k] += v0;
                    vb[o0 * KNNC + k] += v0;
                    hb[(o0 + 1) * KNNC + k] += v1;
                    vb[(o0 + 1) * KNNC + k] += v1;
                }
            }
        }
        __syncthreads();
    }

    // ---- Phase 2: a = relu(bn(aw1 @ h)); thread=(p, c); computes c and c+128 ----
    {
        int c = tid & 127, p = tid >> 7;
        unsigned long long acc[2][10];
#pragma unroll
        for (int j = 0; j < 10; j++) { acc[0][j] = 0ULL; acc[1][j] = 0ULL; }
        const float* hb = s_h + p * DIMC * KNNC;
#pragma unroll 4
        for (int o = 0; o < DIMC; o++) {
            unsigned long long wpair =
                *reinterpret_cast<const unsigned long long*>(g_aw1p + o * HATTC + 2 * c);
            float w0, w1;
            unpack2(wpair, w0, w1);
            unsigned long long wp0 = pack2(w0, w0);
            unsigned long long wp1 = pack2(w1, w1);
            const ulonglong2* hr = reinterpret_cast<const ulonglong2*>(hb + o * KNNC);
#pragma unroll
            for (int j = 0; j < 5; j++) {
                ulonglong2 hv = hr[j];
                acc[0][2 * j]     = ffma2(wp0, hv.x, acc[0][2 * j]);
                acc[0][2 * j + 1] = ffma2(wp0, hv.y, acc[0][2 * j + 1]);
                acc[1][2 * j]     = ffma2(wp1, hv.x, acc[1][2 * j]);
                acc[1][2 * j + 1] = ffma2(wp1, hv.y, acc[1][2 * j + 1]);
            }
        }
#pragma unroll
        for (int cc = 0; cc < 2; cc++) {
            int cg = c + cc * 128;
            float inv = ag[cg] * rsqrtf(av[cg] + EPSV);
            float bias = fmaf(ab1[cg], inv, abt2[cg]) - am[cg] * inv;
            unsigned long long* row =
                reinterpret_cast<unsigned long long*>(s_a + p * HATTC * KNNC + cg * KNNC);
#pragma unroll
            for (int j = 0; j < 10; j++) {
                float lo, hi;
                unpack2(acc[cc][j], lo, hi);
                lo = fmaxf(fmaf(lo, inv, bias), 0.f);
                hi = fmaxf(fmaf(hi, inv, bias), 0.f);
                row[j] = pack2(lo, hi);
            }
        }
    }
    __syncthreads();

    // ---- Phase 3: att partial = awt^T @ a; thread = (rowpair t, chalf, point) ----
    int t = tid & 63;               // rows 2t, 2t+1
    int chalf = (tid >> 6) & 1;     // channel half
    int p3 = tid >> 7;              // point
    unsigned long long acc3[2][10];
    {
#pragma unroll
        for (int j = 0; j < 10; j++) { acc3[0][j] = 0ULL; acc3[1][j] = 0ULL; }
        const float* wb = awt + (chalf * 128) * (DIMC * UPF) + 2 * t;
        const float* ab = s_a + p3 * HATTC * KNNC + (chalf * 128) * KNNC;
#pragma unroll 4
        for (int cc = 0; cc < 128; cc++) {
            float2 w2 = *reinterpret_cast<const float2*>(wb + cc * (DIMC * UPF));
            unsigned long long wp0 = pack2(w2.x, w2.x);
            unsigned long long wp1 = pack2(w2.y, w2.y);
            const ulonglong2* ar = reinterpret_cast<const ulonglong2*>(ab + cc * KNNC);
#pragma unroll
            for (int j = 0; j < 5; j++) {
                ulonglong2 av2 = ar[j];
                acc3[0][2 * j]     = ffma2(wp0, av2.x, acc3[0][2 * j]);
                acc3[0][2 * j + 1] = ffma2(wp0, av2.y, acc3[0][2 * j + 1]);
                acc3[1][2 * j]     = ffma2(wp1, av2.x, acc3[1][2 * j]);
                acc3[1][2 * j + 1] = ffma2(wp1, av2.y, acc3[1][2 * j + 1]);
            }
        }
    }
    __syncthreads();   // all s_a reads done; safe to reuse as partial buffer
    if (chalf) {
        unsigned long long* dst =
            reinterpret_cast<unsigned long long*>(s_a + p3 * HATTC * KNNC) + t * 20;
#pragma unroll
        for (int j = 0; j < 10; j++) { dst[j] = acc3[0][j]; dst[10 + j] = acc3[1][j]; }
    }
    __syncthreads();

    // ---- Phase 4: combine halves, softmax over K, weighted sum with vg ----
    if (!chalf) {
        float ab = abt[t];
        const unsigned long long* part =
            reinterpret_cast<const unsigned long long*>(s_a + p3 * HATTC * KNNC) + t * 20;
        const float* vgr = s_vg + p3 * DIMC * KNNC + t * KNNC;
#pragma unroll
        for (int r = 0; r < 2; r++) {
            float vals[KNNC];
            float mx = -3.4e38f;
#pragma unroll
            for (int j = 0; j < 10; j++) {
                float lo, hi, plo, phi;
                unpack2(acc3[r][j], lo, hi);
                unpack2(part[r * 10 + j], plo, phi);
                float t0 = lo + plo + ab;
                float t1 = hi + phi + ab;
                vals[2 * j] = t0;
                vals[2 * j + 1] = t1;
                mx = fmaxf(mx, fmaxf(t0, t1));
            }
            float s = 0.f, wsum = 0.f;
#pragma unroll
            for (int k = 0; k < KNNC; k++) {
                float e = expf(vals[k] - mx);
                s += e;
                wsum = fmaf(e, vgr[k], wsum);
            }
            s_agg[p3 * DIMC * UPF + t * 2 + r] = wsum / s;   // row = o*2 + r
        }
    }
    __syncthreads();

    // ---- Phase 5: y = we @ agg + be + residual ----
    {
        int c2 = tid >> 1, r = tid & 1;
        float accp[PPB];
#pragma unroll
        for (int pp = 0; pp < PPB; pp++) accp[pp] = 0.f;
        const float4* w4 = reinterpret_cast<const float4*>(we + c2 * DIMC);
#pragma unroll 4
        for (int o4 = 0; o4 < DIMC / 4; o4++) {
            float4 w = w4[o4];
#pragma unroll
            for (int j = 0; j < 4; j++) {
                float wj = (j == 0) ? w.x : (j == 1) ? w.y : (j == 2) ? w.z : w.w;
                int o = o4 * 4 + j;
#pragma unroll
                for (int pp = 0; pp < PPB; pp++)
                    accp[pp] = fmaf(wj, s_agg[pp * DIMC * UPF + o * UPF + r], accp[pp]);
            }
        }
        float bb = be[c2];
#pragma unroll
        for (int pp = 0; pp < PPB; pp++) {
            out[((size_t)(b * CINC + c2)) * (NPTS * UPF) + 2 * (size_t)(n0 + pp) + r] =
                accp[pp] + bb + query[(b * CINC + c2) * NPTS + n0 + pp];
        }
    }
}

// ================= launch =================
extern "C" void kernel_launch(void* const* d_in, const int* in_sizes, int n_in,
                              void* d_out, int out_size)
{
    const float* pos1     = (const float*)d_in[0];
    const float* query    = (const float*)d_in[1];
    const float* pos2     = (const float*)d_in[2];
    const float* key_feat = (const float*)d_in[3];
    const float* wq  = (const float*)d_in[4];
    const float* bq  = (const float*)d_in[5];
    const float* wk  = (const float*)d_in[6];
    const float* bk  = (const float*)d_in[7];
    const float* wv  = (const float*)d_in[8];
    const float* bv  = (const float*)d_in[9];
    const float* pw1 = (const float*)d_in[10];
    const float* pb1 = (const float*)d_in[11];
    const float* pg  = (const float*)d_in[12];
    const float* pbt = (const float*)d_in[13];
    const float* pm  = (const float*)d_in[14];
    const float* pv  = (const float*)d_in[15];
    const float* pw2 = (const float*)d_in[16];
    const float* pb2 = (const float*)d_in[17];
    const float* aw1 = (const float*)d_in[18];
    const float* ab1 = (const float*)d_in[19];
    const float* ag  = (const float*)d_in[20];
    const float* abt2= (const float*)d_in[21];
    const float* am  = (const float*)d_in[22];
    const float* av  = (const float*)d_in[23];
    const float* awt = (const float*)d_in[24];
    const float* abt = (const float*)d_in[25];
    const float* we  = (const float*)d_in[26];
    const float* be  = (const float*)d_in[27];
    float* out = (float*)d_out;

    prep_kernel<<<64, 256>>>(aw1, pw2, wq, wk, wv);
    qkv_kernel<<<dim3(NPTS / 128, BATCH), 256>>>(query, key_feat, bq, bk, bv);
    knn_kernel<<<dim3(NPTS / 128, BATCH), 512>>>(pos1, pos2);
    attn_kernel<<<dim3(NPTS / PPB, BATCH), 256>>>(
        pos1, pos2, query,
        pw1, pb1, pg, pbt, pm, pv, pb2,
        ab1, ag, abt2, am, av, awt, abt, we, be, out);
}

// round 8
// speedup vs baseline: 1.5985x; 1.1649x over previous
#include <cuda_runtime.h>
#include <cuda_bf16.h>
#include <math.h>
#include <stdint.h>

#define BATCH 4
#define NPTS 4096
#define NPTS2 4096
#define CINC 128
#define DIMC 64
#define KNNC 20
#define UPF 2
#define HPOSC 64
#define HATTC 256
#define EPSV 1e-5f
#define PPB 2
#define ABF_STRIDE 264   // padded channels per neighbor row (bank-conflict-free)

// ---------------- scratch ----------------
__device__ float g_qt[BATCH * NPTS * DIMC];
__device__ float g_kt[BATCH * NPTS2 * DIMC];
__device__ float g_vt[BATCH * NPTS2 * DIMC];
__device__ int   g_idx[BATCH * NPTS * KNNC];
__device__ float g_aw1q[DIMC * HATTC];      // [o][2c']=(aw1[2c'][o], aw1[2c'+1][o])
__device__ float g_pw2t[HPOSC * DIMC];
__device__ float g_wqt[CINC * DIMC];
__device__ float g_wkt[CINC * DIMC];
__device__ float g_wvt[CINC * DIMC];
// W2 (= awt^T, [128 rows][256 c]) in m16n8k16 A-fragment order, bf16 hi/lo planes:
// index (((plane*8 + mt)*16 + ks)*32 + lane)*4 + reg
__device__ unsigned g_w2frag[2 * 8 * 16 * 32 * 4];

// ---------------- f32x2 helpers ----------------
__device__ __forceinline__ unsigned long long ffma2(
    unsigned long long a, unsigned long long b, unsigned long long c) {
    unsigned long long d;
    asm("fma.rn.f32x2 %0, %1, %2, %3;" : "=l"(d) : "l"(a), "l"(b), "l"(c));
    return d;
}
__device__ __forceinline__ unsigned long long pack2(float lo, float hi) {
    unsigned long long d;
    asm("mov.b64 %0, {%1, %2};" : "=l"(d) : "f"(lo), "f"(hi));
    return d;
}
__device__ __forceinline__ void unpack2(unsigned long long v, float& lo, float& hi) {
    asm("mov.b64 {%0, %1}, %2;" : "=f"(lo), "=f"(hi) : "l"(v));
}

// ---------------- mma.sync helper (bf16, m16n8k16, fp32 accum) ----------------
__device__ __forceinline__ void mma16816(float* c, const uint4& a, unsigned b0, unsigned b1) {
    asm volatile(
        "mma.sync.aligned.m16n8k16.row.col.f32.bf16.bf16.f32 "
        "{%0,%1,%2,%3}, {%4,%5,%6,%7}, {%8,%9}, {%0,%1,%2,%3};"
        : "+f"(c[0]), "+f"(c[1]), "+f"(c[2]), "+f"(c[3])
        : "r"(a.x), "r"(a.y), "r"(a.z), "r"(a.w), "r"(b0), "r"(b1));
}
__device__ __forceinline__ unsigned bfpack(float x0, float x1) {
    return (unsigned)__bfloat16_as_ushort(__float2bfloat16_rn(x0)) |
           ((unsigned)__bfloat16_as_ushort(__float2bfloat16_rn(x1)) << 16);
}

// ================= prep =================
__global__ __launch_bounds__(256) void prep_kernel(
    const float* __restrict__ aw1, const float* __restrict__ pw2,
    const float* __restrict__ wq, const float* __restrict__ wk,
    const float* __restrict__ wv, const float* __restrict__ awt)
{
    int i = blockIdx.x * 256 + threadIdx.x;
    if (i < DIMC * 128) {                  // adjacent-channel pairs for GEMM1
        int o = i >> 7, cp = i & 127;
        g_aw1q[o * HATTC + 2 * cp]     = aw1[(2 * cp) * DIMC + o];
        g_aw1q[o * HATTC + 2 * cp + 1] = aw1[(2 * cp + 1) * DIMC + o];
    }
    if (i < DIMC * HPOSC) {
        int o = i >> 6, h = i & 63;
        g_pw2t[h * DIMC + o] = pw2[i];
    }
    if (i < DIMC * CINC) {
        int o = i >> 7, c = i & 127;
        g_wqt[c * DIMC + o] = wq[i];
        g_wkt[c * DIMC + o] = wk[i];
        g_wvt[c * DIMC + o] = wv[i];
    }
    if (i < 32768) {                       // W2 A-fragments
        int reg = i & 3, lane = (i >> 2) & 31, ks = (i >> 7) & 15;
        int mt = (i >> 11) & 7, plane = (i >> 14) & 1;
        int gr = lane >> 2, gc = lane & 3;
        int row = mt * 16 + gr + (reg & 1) * 8;
        int col = ks * 16 + 2 * gc + ((reg >> 1) & 1) * 8;
        float x0 = awt[col * 128 + row];
        float x1 = awt[(col + 1) * 128 + row];
        unsigned v;
        if (plane == 0) {
            v = bfpack(x0, x1);
        } else {
            float h0 = __bfloat162float(__float2bfloat16_rn(x0));
            float h1 = __bfloat162float(__float2bfloat16_rn(x1));
            v = bfpack(x0 - h0, x1 - h1);
        }
        g_w2frag[i] = v;
    }
}

// ================= QKV =================
__global__ __launch_bounds__(256) void qkv_kernel(
    const float* __restrict__ query, const float* __restrict__ key_feat,
    const float* __restrict__ bq, const float* __restrict__ bk, const float* __restrict__ bv)
{
    int b = blockIdx.y;
    int n0 = blockIdx.x * 128;
    int tid = threadIdx.x;
    __shared__ __align__(16) float tile[CINC * 128];
    int o = tid & 63, jb = tid >> 6;

    for (int i = tid; i < CINC * 128; i += 256) {
        int c = i >> 7, j = i & 127;
        tile[i] = query[(b * CINC + c) * NPTS + n0 + j];
    }
    __syncthreads();
    {
        unsigned long long acc[16];
#pragma unroll
        for (int m = 0; m < 16; m++) acc[m] = 0ULL;
#pragma unroll 4
        for (int c = 0; c < CINC; c++) {
            float w = g_wqt[c * DIMC + o];
            unsigned long long wp = pack2(w, w);
            const ulonglong2* tp = reinterpret_cast<const ulonglong2*>(tile + c * 128 + jb * 32);
#pragma unroll
            for (int jj = 0; jj < 8; jj++) {
                ulonglong2 t = tp[jj];
                acc[2 * jj]     = ffma2(wp, t.x, acc[2 * jj]);
                acc[2 * jj + 1] = ffma2(wp, t.y, acc[2 * jj + 1]);
            }
        }
        float bias = bq[o];
#pragma unroll
        for (int m = 0; m < 16; m++) {
            float lo, hi;
            unpack2(acc[m], lo, hi);
            int j = jb * 32 + 2 * m;
            g_qt[(b * NPTS + n0 + j) * DIMC + o]     = lo + bias;
            g_qt[(b * NPTS + n0 + j + 1) * DIMC + o] = hi + bias;
        }
    }
    __syncthreads();
    for (int i = tid; i < CINC * 128; i += 256) {
        int c = i >> 7, j = i & 127;
        tile[i] = key_feat[(b * CINC + c) * NPTS2 + n0 + j];
    }
    __syncthreads();
#pragma unroll
    for (int which = 0; which < 2; which++) {
        const float* wt = which ? g_wvt : g_wkt;
        float* gout = which ? g_vt : g_kt;
        float bias = which ? bv[o] : bk[o];
        unsigned long long acc[16];
#pragma unroll
        for (int m = 0; m < 16; m++) acc[m] = 0ULL;
#pragma unroll 4
        for (int c = 0; c < CINC; c++) {
            float w = wt[c * DIMC + o];
            unsigned long long wp = pack2(w, w);
            const ulonglong2* tp = reinterpret_cast<const ulonglong2*>(tile + c * 128 + jb * 32);
#pragma unroll
            for (int jj = 0; jj < 8; jj++) {
                ulonglong2 t = tp[jj];
                acc[2 * jj]     = ffma2(wp, t.x, acc[2 * jj]);
                acc[2 * jj + 1] = ffma2(wp, t.y, acc[2 * jj + 1]);
            }
        }
#pragma unroll
        for (int m = 0; m < 16; m++) {
            float lo, hi;
            unpack2(acc[m], lo, hi);
            int j = jb * 32 + 2 * m;
            gout[(b * NPTS2 + n0 + j) * DIMC + o]     = lo + bias;
            gout[(b * NPTS2 + n0 + j + 1) * DIMC + o] = hi + bias;
        }
    }
}

// ================= KNN =================
__global__ __launch_bounds__(512) void knn_kernel(
    const float* __restrict__ pos1, const float* __restrict__ pos2)
{
    int b = blockIdx.y;
    int tid = threadIdx.x;
    int q = tid & 127, quarter = tid >> 7;
    int n = blockIdx.x * 128 + q;

    __shared__ float sx[4096], sy[4096], sz[4096], sq2[4096];
    __shared__ float smd[512][KNNC];
    __shared__ int   smi[512][KNNC];

    for (int i = tid; i < 4096; i += 512) {
        float x = pos2[(b * 3 + 0) * NPTS2 + i];
        float y = pos2[(b * 3 + 1) * NPTS2 + i];
        float z = pos2[(b * 3 + 2) * NPTS2 + i];
        sx[i] = x; sy[i] = y; sz[i] = z;
        sq2[i] = x * x + y * y + z * z;
    }
    float qx = pos1[(b * 3 + 0) * NPTS + n];
    float qy = pos1[(b * 3 + 1) * NPTS + n];
    float qz = pos1[(b * 3 + 2) * NPTS + n];
    float n1 = qx * qx + qy * qy + qz * qz;

    float bd[KNNC];
    int bi[KNNC];
#pragma unroll
    for (int j = 0; j < KNNC; j++) { bd[j] = 3.4e38f; bi[j] = 0; }
    __syncthreads();
    int base = quarter * 1024;
#pragma unroll 4
    for (int m = 0; m < 1024; m++) {
        int mm = base + m;
        float dot = fmaf(qx, sx[mm], fmaf(qy, sy[mm], qz * sz[mm]));
        float d = n1 + sq2[mm] - 2.f * dot;
        if (d < bd[KNNC - 1]) {
            float cd = d; int ci = mm;
#pragma unroll
            for (int j = 0; j < KNNC; j++) {
                if (cd < bd[j]) {
                    float td = bd[j]; bd[j] = cd; cd = td;
                    int ti = bi[j]; bi[j] = ci; ci = ti;
                }
            }
        }
    }
#pragma unroll
    for (int j = 0; j < KNNC; j++) { smd[tid][j] = bd[j]; smi[tid][j] = bi[j]; }
    __syncthreads();
    if (quarter == 0) {
        int head[4] = {0, 0, 0, 0};
#pragma unroll
        for (int t = 0; t < KNNC; t++) {
            float best = 3.5e38f;
            int bqv = 0;
#pragma unroll
            for (int qu = 0; qu < 4; qu++) {
                if (head[qu] < KNNC) {
                    float v = smd[qu * 128 + q][head[qu]];
                    if (v < best) { best = v; bqv = qu; }
                }
            }
            g_idx[(b * NPTS + n) * KNNC + t] = smi[bqv * 128 + q][head[bqv]];
            head[bqv]++;
        }
    }
}

// ================= fused attention kernel =================
// grid (N/PPB, B), block 256, 3 blocks/SM.
__global__ __launch_bounds__(256, 3) void attn_kernel(
    const float* __restrict__ pos1, const float* __restrict__ pos2,
    const float* __restrict__ query,
    const float* __restrict__ pw1, const float* __restrict__ pb1,
    const float* __restrict__ pg,  const float* __restrict__ pbt,
    const float* __restrict__ pm,  const float* __restrict__ pv,
    const float* __restrict__ pb2,
    const float* __restrict__ ab1,
    const float* __restrict__ ag,  const float* __restrict__ abt2,
    const float* __restrict__ am,  const float* __restrict__ av,
    const float* __restrict__ abt,
    const float* __restrict__ we,  const float* __restrict__ be,
    float* __restrict__ out)
{
    int b = blockIdx.y;
    int n0 = blockIdx.x * PPB;
    int tid = threadIdx.x;

    __shared__ __align__(16) float s_h[PPB * DIMC * KNNC];     // 10 KB
    __shared__ __align__(16) float s_vg[PPB * DIMC * KNNC];    // 10 KB
    // overlay: s_pe1 (6 KB, phases 1) lives at the start of s_big; s_abf (phases 2-3) owns it after
    __shared__ __align__(16) unsigned char s_big[PPB * 2 * 24 * ABF_STRIDE * 2];  // 50688 B
    __shared__ float s_q[PPB * DIMC];
    __shared__ float s_prel[PPB * 3 * KNNC];
    __shared__ float s_agg[PPB * DIMC * UPF];
    __shared__ int   s_idx[PPB * KNNC];

    float* s_pe1 = reinterpret_cast<float*>(s_big);
    __nv_bfloat16* s_abf = reinterpret_cast<__nv_bfloat16*>(s_big);
    // abf index: ((p*2 + plane)*24 + k)*ABF_STRIDE + c

    // ---- Phase 0 ----
    if (tid < PPB * KNNC) {
        int p = tid / KNNC, k = tid - p * KNNC;
        s_idx[tid] = g_idx[(b * NPTS + n0 + p) * KNNC + k];
    }
    if (tid < PPB * DIMC) {
        int p = tid >> 6, o = tid & 63;
        s_q[tid] = g_qt[(b * NPTS + n0 + p) * DIMC + o];
    }
    __syncthreads();
    if (tid < PPB * 3 * KNNC) {
        int p = tid / (3 * KNNC), rem = tid - p * 3 * KNNC;
        int c = rem / KNNC, k = rem - c * KNNC;
        s_prel[tid] = pos1[(b * 3 + c) * NPTS + n0 + p]
                    - pos2[(b * 3 + c) * NPTS2 + s_idx[p * KNNC + k]];
    }
#pragma unroll
    for (int p = 0; p < PPB; p++) {
        for (int e = tid; e < DIMC * KNNC; e += 256) {
            int k = e >> 6, o = e & 63;
            int m = s_idx[p * KNNC + k];
            s_h[p * DIMC * KNNC + o * KNNC + k]  = s_q[p * DIMC + o] - g_kt[(b * NPTS2 + m) * DIMC + o];
            s_vg[p * DIMC * KNNC + o * KNNC + k] = g_vt[(b * NPTS2 + m) * DIMC + o];
        }
    }
    __syncthreads();

    // ---- Phase 1 + 1b per point ----
#pragma unroll
    for (int p = 0; p < PPB; p++) {
        for (int e = tid; e < HPOSC * 24; e += 256) {
            int h = e / 24, k = e - h * 24;
            float val = 0.f;
            if (k < KNNC) {
                const float* pr = s_prel + p * 3 * KNNC;
                float acc = fmaf(pw1[h * 3 + 0], pr[k],
                            fmaf(pw1[h * 3 + 1], pr[KNNC + k],
                                 pw1[h * 3 + 2] * pr[2 * KNNC + k])) + pb1[h];
                float inv = pg[h] * rsqrtf(pv[h] + EPSV);
                acc = fmaf(acc, inv, pbt[h] - pm[h] * inv);
                val = fmaxf(acc, 0.f);
            }
            s_pe1[e] = val;
        }
        __syncthreads();
        {
            int op = tid & 31, kg = tid >> 5;
            int o0 = op * 2, k0 = kg * 3;
            unsigned long long acc[3] = {0ULL, 0ULL, 0ULL};
#pragma unroll 4
            for (int h = 0; h < HPOSC; h++) {
                unsigned long long w2 =
                    *reinterpret_cast<const unsigned long long*>(g_pw2t + h * DIMC + o0);
                const float* br = s_pe1 + h * 24 + k0;
                acc[0] = ffma2(w2, pack2(br[0], br[0]), acc[0]);
                acc[1] = ffma2(w2, pack2(br[1], br[1]), acc[1]);
                acc[2] = ffma2(w2, pack2(br[2], br[2]), acc[2]);
            }
            float b0 = pb2[o0], b1 = pb2[o0 + 1];
            float* hb = s_h + p * DIMC * KNNC;
            float* vb = s_vg + p * DIMC * KNNC;
#pragma unroll
            for (int j = 0; j < 3; j++) {
                int k = k0 + j;
                if (k < KNNC) {
                    float lo, hi;
                    unpack2(acc[j], lo, hi);
                    float v0 = lo + b0, v1 = hi + b1;
                    hb[o0 * KNNC + k] += v0;
                    vb[o0 * KNNC + k] += v0;
                    hb[(o0 + 1) * KNNC + k] += v1;
                    vb[(o0 + 1) * KNNC + k] += v1;
                }
            }
        }
        __syncthreads();
    }

    // ---- Phase 2: a = relu(bn(aw1 @ h)) -> s_abf bf16 hi/lo, [neighbor][channel] ----
    {
        int cp = tid & 127, p = tid >> 7;       // channels 2cp, 2cp+1
        unsigned long long acc[2][10];
#pragma unroll
        for (int j = 0; j < 10; j++) { acc[0][j] = 0ULL; acc[1][j] = 0ULL; }
        const float* hb = s_h + p * DIMC * KNNC;
#pragma unroll 4
        for (int o = 0; o < DIMC; o++) {
            unsigned long long wpair =
                *reinterpret_cast<const unsigned long long*>(g_aw1q + o * HATTC + 2 * cp);
            float w0, w1;
            unpack2(wpair, w0, w1);
            unsigned long long wp0 = pack2(w0, w0);
            unsigned long long wp1 = pack2(w1, w1);
            const ulonglong2* hr = reinterpret_cast<const ulonglong2*>(hb + o * KNNC);
#pragma unroll
            for (int j = 0; j < 5; j++) {
                ulonglong2 hv = hr[j];
                acc[0][2 * j]     = ffma2(wp0, hv.x, acc[0][2 * j]);
                acc[0][2 * j + 1] = ffma2(wp0, hv.y, acc[0][2 * j + 1]);
                acc[1][2 * j]     = ffma2(wp1, hv.x, acc[1][2 * j]);
                acc[1][2 * j + 1] = ffma2(wp1, hv.y, acc[1][2 * j + 1]);
            }
        }
        int c0 = 2 * cp, c1 = 2 * cp + 1;
        float inv0 = ag[c0] * rsqrtf(av[c0] + EPSV);
        float bias0 = fmaf(ab1[c0], inv0, abt2[c0]) - am[c0] * inv0;
        float inv1 = ag[c1] * rsqrtf(av[c1] + EPSV);
        float bias1 = fmaf(ab1[c1], inv1, abt2[c1]) - am[c1] * inv1;
        unsigned hibase = (unsigned)((p * 2 + 0) * 24) * ABF_STRIDE;
        unsigned lobase = (unsigned)((p * 2 + 1) * 24) * ABF_STRIDE;
#pragma unroll
        for (int j = 0; j < 10; j++) {
            float a00, a01, a10, a11;
            unpack2(acc[0][j], a00, a01);   // channel c0, k=2j, 2j+1
            unpack2(acc[1][j], a10, a11);   // channel c1
            float v0k0 = fmaxf(fmaf(a00, inv0, bias0), 0.f);
            float v1k0 = fmaxf(fmaf(a10, inv1, bias1), 0.f);
            float v0k1 = fmaxf(fmaf(a01, inv0, bias0), 0.f);
            float v1k1 = fmaxf(fmaf(a11, inv1, bias1), 0.f);
#pragma unroll
            for (int kk = 0; kk < 2; kk++) {
                float x0 = kk ? v0k1 : v0k0;
                float x1 = kk ? v1k1 : v1k0;
                int k = 2 * j + kk;
                float h0f = __bfloat162float(__float2bfloat16_rn(x0));
                float h1f = __bfloat162float(__float2bfloat16_rn(x1));
                *reinterpret_cast<unsigned*>(&s_abf[hibase + k * ABF_STRIDE + c0]) = bfpack(x0, x1);
                *reinterpret_cast<unsigned*>(&s_abf[lobase + k * ABF_STRIDE + c0]) = bfpack(x0 - h0f, x1 - h1f);
            }
        }
    }
    __syncthreads();

    // ---- Phase 3: logits = W2 @ a via mma.sync; softmax+aggregate in epilogue ----
    {
        int w = tid >> 5, lane = tid & 31;
        int gr = lane >> 2, gc = lane & 3;
        float C[PPB][3][4];
#pragma unroll
        for (int p = 0; p < PPB; p++)
#pragma unroll
            for (int nt = 0; nt < 3; nt++)
#pragma unroll
                for (int r = 0; r < 4; r++) C[p][nt][r] = 0.f;

        const uint4* Ahi_p = reinterpret_cast<const uint4*>(g_w2frag) + ((0 * 8 + w) * 16) * 32;
        const uint4* Alo_p = reinterpret_cast<const uint4*>(g_w2frag) + ((1 * 8 + w) * 16) * 32;
#pragma unroll 4
        for (int ks = 0; ks < 16; ks++) {
            uint4 Ah = Ahi_p[ks * 32 + lane];
            uint4 Al = Alo_p[ks * 32 + lane];
#pragma unroll
            for (int p = 0; p < PPB; p++) {
#pragma unroll
                for (int nt = 0; nt < 3; nt++) {
                    int nrow = nt * 8 + gr;
                    const __nv_bfloat16* bh =
                        s_abf + ((p * 2 + 0) * 24 + nrow) * ABF_STRIDE + ks * 16 + 2 * gc;
                    const __nv_bfloat16* bl =
                        s_abf + ((p * 2 + 1) * 24 + nrow) * ABF_STRIDE + ks * 16 + 2 * gc;
                    unsigned b0h = *reinterpret_cast<const unsigned*>(bh);
                    unsigned b1h = *reinterpret_cast<const unsigned*>(bh + 8);
                    unsigned b0l = *reinterpret_cast<const unsigned*>(bl);
                    unsigned b1l = *reinterpret_cast<const unsigned*>(bl + 8);
                    mma16816(C[p][nt], Ah, b0h, b1h);
                    mma16816(C[p][nt], Ah, b0l, b1l);
                    mma16816(C[p][nt], Al, b0h, b1h);
                }
            }
        }
        // epilogue: per point, per row-half, quad softmax + aggregate
#pragma unroll
        for (int p = 0; p < PPB; p++) {
#pragma unroll
            for (int half = 0; half < 2; half++) {
                int r = w * 16 + gr + half * 8;
                int o = r >> 1;
                float ab = abt[o];
                float vals[6];
                int nvalid = (gc < 2) ? 6 : 4;   // ntile2 cols >=20 masked for gc>=2
#pragma unroll
                for (int nt = 0; nt < 3; nt++) {
#pragma unroll
                    for (int j = 0; j < 2; j++)
                        vals[nt * 2 + j] = C[p][nt][half * 2 + j] + ab;
                }
                float mx = -3.4e38f;
                for (int i = 0; i < nvalid; i++) {
                    int idx = (i < 4) ? i : (4 + (i - 4));  // vals 0..3 always valid; 4,5 from ntile2
                    mx = fmaxf(mx, vals[idx]);
                }
                mx = fmaxf(mx, __shfl_xor_sync(0xffffffffu, mx, 1));
                mx = fmaxf(mx, __shfl_xor_sync(0xffffffffu, mx, 2));
                const float* vgr = s_vg + p * DIMC * KNNC + o * KNNC;
                float s = 0.f, ws = 0.f;
                for (int i = 0; i < nvalid; i++) {
                    int nt = i >> 1, j = i & 1;
                    int nb = nt * 8 + 2 * gc + j;
                    float e = expf(vals[i] - mx);
                    s += e;
                    ws = fmaf(e, vgr[nb], ws);
                }
                s += __shfl_xor_sync(0xffffffffu, s, 1);
                s += __shfl_xor_sync(0xffffffffu, s, 2);
                ws += __shfl_xor_sync(0xffffffffu, ws, 1);
                ws += __shfl_xor_sync(0xffffffffu, ws, 2);
                if (gc == 0) s_agg[p * 128 + r] = ws / s;
            }
        }
    }
    __syncthreads();

    // ---- Phase 5: y = we @ agg + be + residual ----
    {
        int c2 = tid >> 1, rr = tid & 1;
        float accp[PPB];
#pragma unroll
        for (int pp = 0; pp < PPB; pp++) accp[pp] = 0.f;
        const float4* w4 = reinterpret_cast<const float4*>(we + c2 * DIMC);
#pragma unroll 4
        for (int o4 = 0; o4 < DIMC / 4; o4++) {
            float4 w = w4[o4];
#pragma unroll
            for (int j = 0; j < 4; j++) {
                float wj = (j == 0) ? w.x : (j == 1) ? w.y : (j == 2) ? w.z : w.w;
                int o = o4 * 4 + j;
#pragma unroll
                for (int pp = 0; pp < PPB; pp++)
                    accp[pp] = fmaf(wj, s_agg[pp * 128 + o * UPF + rr], accp[pp]);
            }
        }
        float bb = be[c2];
#pragma unroll
        for (int pp = 0; pp < PPB; pp++) {
            out[((size_t)(b * CINC + c2)) * (NPTS * UPF) + 2 * (size_t)(n0 + pp) + rr] =
                accp[pp] + bb + query[(b * CINC + c2) * NPTS + n0 + pp];
        }
    }
}

// ================= launch =================
extern "C" void kernel_launch(void* const* d_in, const int* in_sizes, int n_in,
                              void* d_out, int out_size)
{
    const float* pos1     = (const float*)d_in[0];
    const float* query    = (const float*)d_in[1];
    const float* pos2     = (const float*)d_in[2];
    const float* key_feat = (const float*)d_in[3];
    const float* wq  = (const float*)d_in[4];
    const float* bq  = (const float*)d_in[5];
    const float* wk  = (const float*)d_in[6];
    const float* bk  = (const float*)d_in[7];
    const float* wv  = (const float*)d_in[8];
    const float* bv  = (const float*)d_in[9];
    const float* pw1 = (const float*)d_in[10];
    const float* pb1 = (const float*)d_in[11];
    const float* pg  = (const float*)d_in[12];
    const float* pbt = (const float*)d_in[13];
    const float* pm  = (const float*)d_in[14];
    const float* pv  = (const float*)d_in[15];
    const float* pw2 = (const float*)d_in[16];
    const float* pb2 = (const float*)d_in[17];
    const float* aw1 = (const float*)d_in[18];
    const float* ab1 = (const float*)d_in[19];
    const float* ag  = (const float*)d_in[20];
    const float* abt2= (const float*)d_in[21];
    const float* am  = (const float*)d_in[22];
    const float* av  = (const float*)d_in[23];
    const float* awt = (const float*)d_in[24];
    const float* abt = (const float*)d_in[25];
    const float* we  = (const float*)d_in[26];
    const float* be  = (const float*)d_in[27];
    float* out = (float*)d_out;

    prep_kernel<<<128, 256>>>(aw1, pw2, wq, wk, wv, awt);
    qkv_kernel<<<dim3(NPTS / 128, BATCH), 256>>>(query, key_feat, bq, bk, bv);
    knn_kernel<<<dim3(NPTS / 128, BATCH), 512>>>(pos1, pos2);
    attn_kernel<<<dim3(NPTS / PPB, BATCH), 256>>>(
        pos1, pos2, query,
        pw1, pb1, pg, pbt, pm, pv, pb2,
        ab1, ag, abt2, am, av, abt, we, be, out);
}

// round 9
// speedup vs baseline: 1.7408x; 1.0890x over previous
#include <cuda_runtime.h>
#include <cuda_bf16.h>
#include <math.h>
#include <stdint.h>

#define BATCH 4
#define NPTS 4096
#define NPTS2 4096
#define CINC 128
#define DIMC 64
#define KNNC 20
#define UPF 2
#define HPOSC 64
#define HATTC 256
#define EPSV 1e-5f
#define PPB 2
#define ABF_STRIDE 264   // channels stride in s_abf rows
#define HBF_STRIDE 72    // o stride in s_hbf rows

// ---------------- scratch ----------------
__device__ float g_qt[BATCH * NPTS * DIMC];
__device__ float g_kt[BATCH * NPTS2 * DIMC];
__device__ float g_vt[BATCH * NPTS2 * DIMC];
__device__ int   g_idx[BATCH * NPTS * KNNC];
__device__ float g_pw2t[HPOSC * DIMC];
__device__ float g_wqt[CINC * DIMC];
__device__ float g_wkt[CINC * DIMC];
__device__ float g_wvt[CINC * DIMC];
// W2 (= awt^T, [128 rows][256 c]) A-fragments: (((plane*8 + mt)*16 + ks)*32 + lane)*4 + reg
__device__ unsigned g_w2frag[2 * 8 * 16 * 32 * 4];
// W1 (= aw1, [256 rows][64 o]) A-fragments: (((plane*16 + mt)*4 + ks)*32 + lane)*4 + reg
__device__ unsigned g_w1frag[2 * 16 * 4 * 32 * 4];
__device__ float g_c1inv[HATTC];
__device__ float g_c1bias[HATTC];

// ---------------- f32x2 helpers ----------------
__device__ __forceinline__ unsigned long long ffma2(
    unsigned long long a, unsigned long long b, unsigned long long c) {
    unsigned long long d;
    asm("fma.rn.f32x2 %0, %1, %2, %3;" : "=l"(d) : "l"(a), "l"(b), "l"(c));
    return d;
}
__device__ __forceinline__ unsigned long long pack2(float lo, float hi) {
    unsigned long long d;
    asm("mov.b64 %0, {%1, %2};" : "=l"(d) : "f"(lo), "f"(hi));
    return d;
}
__device__ __forceinline__ void unpack2(unsigned long long v, float& lo, float& hi) {
    asm("mov.b64 {%0, %1}, %2;" : "=f"(lo), "=f"(hi) : "l"(v));
}

// ---------------- mma.sync helper ----------------
__device__ __forceinline__ void mma16816(float* c, const uint4& a, unsigned b0, unsigned b1) {
    asm volatile(
        "mma.sync.aligned.m16n8k16.row.col.f32.bf16.bf16.f32 "
        "{%0,%1,%2,%3}, {%4,%5,%6,%7}, {%8,%9}, {%0,%1,%2,%3};"
        : "+f"(c[0]), "+f"(c[1]), "+f"(c[2]), "+f"(c[3])
        : "r"(a.x), "r"(a.y), "r"(a.z), "r"(a.w), "r"(b0), "r"(b1));
}
__device__ __forceinline__ unsigned bfpack(float x0, float x1) {
    return (unsigned)__bfloat16_as_ushort(__float2bfloat16_rn(x0)) |
           ((unsigned)__bfloat16_as_ushort(__float2bfloat16_rn(x1)) << 16);
}

// ================= prep =================
__global__ __launch_bounds__(256) void prep_kernel(
    const float* __restrict__ aw1, const float* __restrict__ pw2,
    const float* __restrict__ wq, const float* __restrict__ wk,
    const float* __restrict__ wv, const float* __restrict__ awt,
    const float* __restrict__ ab1, const float* __restrict__ ag,
    const float* __restrict__ abt2, const float* __restrict__ am,
    const float* __restrict__ av)
{
    int i = blockIdx.x * 256 + threadIdx.x;
    if (i < DIMC * HPOSC) {
        int o = i >> 6, h = i & 63;
        g_pw2t[h * DIMC + o] = pw2[i];
    }
    if (i < DIMC * CINC) {
        int o = i >> 7, c = i & 127;
        g_wqt[c * DIMC + o] = wq[i];
        g_wkt[c * DIMC + o] = wk[i];
        g_wvt[c * DIMC + o] = wv[i];
    }
    if (i < HATTC) {
        float inv = ag[i] * rsqrtf(av[i] + EPSV);
        g_c1inv[i] = inv;
        g_c1bias[i] = fmaf(ab1[i], inv, abt2[i]) - am[i] * inv;
    }
    if (i < 32768) {                       // W2 A-fragments
        int reg = i & 3, lane = (i >> 2) & 31, ks = (i >> 7) & 15;
        int mt = (i >> 11) & 7, plane = (i >> 14) & 1;
        int gr = lane >> 2, gc = lane & 3;
        int row = mt * 16 + gr + (reg & 1) * 8;
        int col = ks * 16 + 2 * gc + ((reg >> 1) & 1) * 8;
        float x0 = awt[col * 128 + row];
        float x1 = awt[(col + 1) * 128 + row];
        unsigned v;
        if (plane == 0) v = bfpack(x0, x1);
        else {
            float h0 = __bfloat162float(__float2bfloat16_rn(x0));
            float h1 = __bfloat162float(__float2bfloat16_rn(x1));
            v = bfpack(x0 - h0, x1 - h1);
        }
        g_w2frag[i] = v;
    }
    if (i < 16384) {                       // W1 A-fragments
        int reg = i & 3, lane = (i >> 2) & 31, ks = (i >> 7) & 3;
        int mt = (i >> 9) & 15, plane = (i >> 13) & 1;
        int gr = lane >> 2, gc = lane & 3;
        int row = mt * 16 + gr + (reg & 1) * 8;
        int col = ks * 16 + 2 * gc + ((reg >> 1) & 1) * 8;
        float x0 = aw1[row * DIMC + col];
        float x1 = aw1[row * DIMC + col + 1];
        unsigned v;
        if (plane == 0) v = bfpack(x0, x1);
        else {
            float h0 = __bfloat162float(__float2bfloat16_rn(x0));
            float h1 = __bfloat162float(__float2bfloat16_rn(x1));
            v = bfpack(x0 - h0, x1 - h1);
        }
        g_w1frag[i] = v;
    }
}

// ================= QKV =================
__global__ __launch_bounds__(256) void qkv_kernel(
    const float* __restrict__ query, const float* __restrict__ key_feat,
    const float* __restrict__ bq, const float* __restrict__ bk, const float* __restrict__ bv)
{
    int b = blockIdx.y;
    int n0 = blockIdx.x * 128;
    int tid = threadIdx.x;
    __shared__ __align__(16) float tile[CINC * 128];
    int o = tid & 63, jb = tid >> 6;

    for (int i = tid; i < CINC * 128; i += 256) {
        int c = i >> 7, j = i & 127;
        tile[i] = query[(b * CINC + c) * NPTS + n0 + j];
    }
    __syncthreads();
    {
        unsigned long long acc[16];
#pragma unroll
        for (int m = 0; m < 16; m++) acc[m] = 0ULL;
#pragma unroll 4
        for (int c = 0; c < CINC; c++) {
            float w = g_wqt[c * DIMC + o];
            unsigned long long wp = pack2(w, w);
            const ulonglong2* tp = reinterpret_cast<const ulonglong2*>(tile + c * 128 + jb * 32);
#pragma unroll
            for (int jj = 0; jj < 8; jj++) {
                ulonglong2 t = tp[jj];
                acc[2 * jj]     = ffma2(wp, t.x, acc[2 * jj]);
                acc[2 * jj + 1] = ffma2(wp, t.y, acc[2 * jj + 1]);
            }
        }
        float bias = bq[o];
#pragma unroll
        for (int m = 0; m < 16; m++) {
            float lo, hi;
            unpack2(acc[m], lo, hi);
            int j = jb * 32 + 2 * m;
            g_qt[(b * NPTS + n0 + j) * DIMC + o]     = lo + bias;
            g_qt[(b * NPTS + n0 + j + 1) * DIMC + o] = hi + bias;
        }
    }
    __syncthreads();
    for (int i = tid; i < CINC * 128; i += 256) {
        int c = i >> 7, j = i & 127;
        tile[i] = key_feat[(b * CINC + c) * NPTS2 + n0 + j];
    }
    __syncthreads();
#pragma unroll
    for (int which = 0; which < 2; which++) {
        const float* wt = which ? g_wvt : g_wkt;
        float* gout = which ? g_vt : g_kt;
        float bias = which ? bv[o] : bk[o];
        unsigned long long acc[16];
#pragma unroll
        for (int m = 0; m < 16; m++) acc[m] = 0ULL;
#pragma unroll 4
        for (int c = 0; c < CINC; c++) {
            float w = wt[c * DIMC + o];
            unsigned long long wp = pack2(w, w);
            const ulonglong2* tp = reinterpret_cast<const ulonglong2*>(tile + c * 128 + jb * 32);
#pragma unroll
            for (int jj = 0; jj < 8; jj++) {
                ulonglong2 t = tp[jj];
                acc[2 * jj]     = ffma2(wp, t.x, acc[2 * jj]);
                acc[2 * jj + 1] = ffma2(wp, t.y, acc[2 * jj + 1]);
            }
        }
#pragma unroll
        for (int m = 0; m < 16; m++) {
            float lo, hi;
            unpack2(acc[m], lo, hi);
            int j = jb * 32 + 2 * m;
            gout[(b * NPTS2 + n0 + j) * DIMC + o]     = lo + bias;
            gout[(b * NPTS2 + n0 + j + 1) * DIMC + o] = hi + bias;
        }
    }
}

// ================= KNN =================
__global__ __launch_bounds__(512) void knn_kernel(
    const float* __restrict__ pos1, const float* __restrict__ pos2)
{
    int b = blockIdx.y;
    int tid = threadIdx.x;
    int q = tid & 127, quarter = tid >> 7;
    int n = blockIdx.x * 128 + q;

    __shared__ float sx[4096], sy[4096], sz[4096], sq2[4096];
    __shared__ float smd[512][KNNC];
    __shared__ int   smi[512][KNNC];

    for (int i = tid; i < 4096; i += 512) {
        float x = pos2[(b * 3 + 0) * NPTS2 + i];
        float y = pos2[(b * 3 + 1) * NPTS2 + i];
        float z = pos2[(b * 3 + 2) * NPTS2 + i];
        sx[i] = x; sy[i] = y; sz[i] = z;
        sq2[i] = x * x + y * y + z * z;
    }
    float qx = pos1[(b * 3 + 0) * NPTS + n];
    float qy = pos1[(b * 3 + 1) * NPTS + n];
    float qz = pos1[(b * 3 + 2) * NPTS + n];
    float n1 = qx * qx + qy * qy + qz * qz;

    float bd[KNNC];
    int bi[KNNC];
#pragma unroll
    for (int j = 0; j < KNNC; j++) { bd[j] = 3.4e38f; bi[j] = 0; }
    __syncthreads();
    int base = quarter * 1024;
#pragma unroll 4
    for (int m = 0; m < 1024; m++) {
        int mm = base + m;
        float dot = fmaf(qx, sx[mm], fmaf(qy, sy[mm], qz * sz[mm]));
        float d = n1 + sq2[mm] - 2.f * dot;
        if (d < bd[KNNC - 1]) {
            float cd = d; int ci = mm;
#pragma unroll
            for (int j = 0; j < KNNC; j++) {
                if (cd < bd[j]) {
                    float td = bd[j]; bd[j] = cd; cd = td;
                    int ti = bi[j]; bi[j] = ci; ci = ti;
                }
            }
        }
    }
#pragma unroll
    for (int j = 0; j < KNNC; j++) { smd[tid][j] = bd[j]; smi[tid][j] = bi[j]; }
    __syncthreads();
    if (quarter == 0) {
        int head[4] = {0, 0, 0, 0};
#pragma unroll
        for (int t = 0; t < KNNC; t++) {
            float best = 3.5e38f;
            int bqv = 0;
#pragma unroll
            for (int qu = 0; qu < 4; qu++) {
                if (head[qu] < KNNC) {
                    float v = smd[qu * 128 + q][head[qu]];
                    if (v < best) { best = v; bqv = qu; }
                }
            }
            g_idx[(b * NPTS + n) * KNNC + t] = smi[bqv * 128 + q][head[bqv]];
            head[bqv]++;
        }
    }
}

// ================= fused attention kernel =================
__global__ __launch_bounds__(256, 3) void attn_kernel(
    const float* __restrict__ pos1, const float* __restrict__ pos2,
    const float* __restrict__ query,
    const float* __restrict__ pw1, const float* __restrict__ pb1,
    const float* __restrict__ pg,  const float* __restrict__ pbt,
    const float* __restrict__ pm,  const float* __restrict__ pv,
    const float* __restrict__ pb2,
    const float* __restrict__ abt,
    const float* __restrict__ we,  const float* __restrict__ be,
    float* __restrict__ out)
{
    int b = blockIdx.y;
    int n0 = blockIdx.x * PPB;
    int tid = threadIdx.x;

    __shared__ __align__(16) float s_h[PPB * DIMC * KNNC];     // qk_rel fp32 (10 KB)
    __shared__ __align__(16) float s_vg[PPB * DIMC * KNNC];    // 10 KB
    __shared__ __align__(16) unsigned char s_big[2 * 24 * ABF_STRIDE * 2]; // 25344 B (pe1 overlays)
    __shared__ __align__(16) __nv_bfloat16 s_hbf[PPB * 2 * 24 * HBF_STRIDE]; // 13824 B
    __shared__ float s_q[PPB * DIMC];
    __shared__ float s_prel[PPB * 3 * KNNC];
    __shared__ float s_agg[PPB * DIMC * UPF];
    __shared__ int   s_idx[PPB * KNNC];

    float* s_pe1 = reinterpret_cast<float*>(s_big);
    __nv_bfloat16* s_abf = reinterpret_cast<__nv_bfloat16*>(s_big);

    // ---- Phase 0 ----
    if (tid < PPB * KNNC) {
        int p = tid / KNNC, k = tid - p * KNNC;
        s_idx[tid] = g_idx[(b * NPTS + n0 + p) * KNNC + k];
    }
    if (tid < PPB * DIMC) {
        int p = tid >> 6, o = tid & 63;
        s_q[tid] = g_qt[(b * NPTS + n0 + p) * DIMC + o];
    }
    // zero padded neighbor rows (20..23) of s_hbf
    {
        unsigned* hz = reinterpret_cast<unsigned*>(s_hbf);
        for (int e = tid; e < PPB * 2 * 4 * (HBF_STRIDE / 2); e += 256) {
            int woff = e % (HBF_STRIDE / 2);
            int rsel = e / (HBF_STRIDE / 2);       // 0..15: p(2) x plane(2) x r(4)
            int r = rsel & 3, pl = (rsel >> 2) & 1, p = rsel >> 3;
            hz[((p * 2 + pl) * 24 + 20 + r) * (HBF_STRIDE / 2) + woff] = 0u;
        }
    }
    __syncthreads();
    if (tid < PPB * 3 * KNNC) {
        int p = tid / (3 * KNNC), rem = tid - p * 3 * KNNC;
        int c = rem / KNNC, k = rem - c * KNNC;
        s_prel[tid] = pos1[(b * 3 + c) * NPTS + n0 + p]
                    - pos2[(b * 3 + c) * NPTS2 + s_idx[p * KNNC + k]];
    }
#pragma unroll
    for (int p = 0; p < PPB; p++) {
        for (int e = tid; e < DIMC * KNNC; e += 256) {
            int k = e >> 6, o = e & 63;
            int m = s_idx[p * KNNC + k];
            s_h[p * DIMC * KNNC + o * KNNC + k]  = s_q[p * DIMC + o] - g_kt[(b * NPTS2 + m) * DIMC + o];
            s_vg[p * DIMC * KNNC + o * KNNC + k] = g_vt[(b * NPTS2 + m) * DIMC + o];
        }
    }
    __syncthreads();

    // ---- Phase 1 + 1b per point: pe; h -> s_hbf (bf16 hi/lo), vg += pe ----
#pragma unroll
    for (int p = 0; p < PPB; p++) {
        for (int e = tid; e < HPOSC * 24; e += 256) {
            int h = e / 24, k = e - h * 24;
            float val = 0.f;
            if (k < KNNC) {
                const float* pr = s_prel + p * 3 * KNNC;
                float acc = fmaf(pw1[h * 3 + 0], pr[k],
                            fmaf(pw1[h * 3 + 1], pr[KNNC + k],
                                 pw1[h * 3 + 2] * pr[2 * KNNC + k])) + pb1[h];
                float inv = pg[h] * rsqrtf(pv[h] + EPSV);
                acc = fmaf(acc, inv, pbt[h] - pm[h] * inv);
                val = fmaxf(acc, 0.f);
            }
            s_pe1[e] = val;
        }
        __syncthreads();
        {
            int op = tid & 31, kg = tid >> 5;
            int o0 = op * 2, k0 = kg * 3;
            unsigned long long acc[3] = {0ULL, 0ULL, 0ULL};
#pragma unroll 4
            for (int h = 0; h < HPOSC; h++) {
                unsigned long long w2 =
                    *reinterpret_cast<const unsigned long long*>(g_pw2t + h * DIMC + o0);
                const float* br = s_pe1 + h * 24 + k0;
                acc[0] = ffma2(w2, pack2(br[0], br[0]), acc[0]);
                acc[1] = ffma2(w2, pack2(br[1], br[1]), acc[1]);
                acc[2] = ffma2(w2, pack2(br[2], br[2]), acc[2]);
            }
            float b0 = pb2[o0], b1 = pb2[o0 + 1];
            const float* hb = s_h + p * DIMC * KNNC;
            float* vb = s_vg + p * DIMC * KNNC;
            unsigned* hbf_hi = reinterpret_cast<unsigned*>(
                s_hbf + (p * 2 + 0) * 24 * HBF_STRIDE) ;
            unsigned* hbf_lo = reinterpret_cast<unsigned*>(
                s_hbf + (p * 2 + 1) * 24 * HBF_STRIDE);
#pragma unroll
            for (int j = 0; j < 3; j++) {
                int k = k0 + j;
                if (k < KNNC) {
                    float lo, hi;
                    unpack2(acc[j], lo, hi);
                    float v0 = lo + b0, v1 = hi + b1;
                    float h0 = hb[o0 * KNNC + k] + v0;
                    float h1 = hb[(o0 + 1) * KNNC + k] + v1;
                    vb[o0 * KNNC + k] += v0;
                    vb[(o0 + 1) * KNNC + k] += v1;
                    float h0hi = __bfloat162float(__float2bfloat16_rn(h0));
                    float h1hi = __bfloat162float(__float2bfloat16_rn(h1));
                    hbf_hi[(k * HBF_STRIDE + o0) >> 1] = bfpack(h0, h1);
                    hbf_lo[(k * HBF_STRIDE + o0) >> 1] = bfpack(h0 - h0hi, h1 - h1hi);
                }
            }
        }
        __syncthreads();
    }

    // ---- Phases 2+3 per point: GEMM1 (mma) -> s_abf; GEMM2 (mma) -> C3 ----
    int w = tid >> 5, lane = tid & 31;
    int gr = lane >> 2, gc = lane & 3;
    float C3[PPB][3][4];
#pragma unroll
    for (int p = 0; p < PPB; p++)
#pragma unroll
        for (int nt = 0; nt < 3; nt++)
#pragma unroll
            for (int r = 0; r < 4; r++) C3[p][nt][r] = 0.f;

    const uint4* W1 = reinterpret_cast<const uint4*>(g_w1frag);
    const uint4* Ahi_p = reinterpret_cast<const uint4*>(g_w2frag) + ((0 * 8 + w) * 16) * 32;
    const uint4* Alo_p = reinterpret_cast<const uint4*>(g_w2frag) + ((1 * 8 + w) * 16) * 32;

#pragma unroll
    for (int p = 0; p < PPB; p++) {
        __syncthreads();   // prior phase-3 reads of s_abf done
        float C2[2][3][4];
#pragma unroll
        for (int mi = 0; mi < 2; mi++)
#pragma unroll
            for (int nt = 0; nt < 3; nt++)
#pragma unroll
                for (int r = 0; r < 4; r++) C2[mi][nt][r] = 0.f;

#pragma unroll
        for (int ks = 0; ks < 4; ks++) {
            unsigned bh0[3], bh1[3], bl0[3], bl1[3];
#pragma unroll
            for (int nt = 0; nt < 3; nt++) {
                const __nv_bfloat16* bh =
                    s_hbf + ((p * 2 + 0) * 24 + nt * 8 + gr) * HBF_STRIDE + ks * 16 + 2 * gc;
                const __nv_bfloat16* bl =
                    s_hbf + ((p * 2 + 1) * 24 + nt * 8 + gr) * HBF_STRIDE + ks * 16 + 2 * gc;
                bh0[nt] = *reinterpret_cast<const unsigned*>(bh);
                bh1[nt] = *reinterpret_cast<const unsigned*>(bh + 8);
                bl0[nt] = *reinterpret_cast<const unsigned*>(bl);
                bl1[nt] = *reinterpret_cast<const unsigned*>(bl + 8);
            }
#pragma unroll
            for (int mi = 0; mi < 2; mi++) {
                int mt = w * 2 + mi;
                uint4 Ah = W1[((0 * 16 + mt) * 4 + ks) * 32 + lane];
                uint4 Al = W1[((1 * 16 + mt) * 4 + ks) * 32 + lane];
#pragma unroll
                for (int nt = 0; nt < 3; nt++) {
                    mma16816(C2[mi][nt], Ah, bh0[nt], bh1[nt]);
                    mma16816(C2[mi][nt], Ah, bl0[nt], bl1[nt]);
                    mma16816(C2[mi][nt], Al, bh0[nt], bh1[nt]);
                }
            }
        }
        // epilogue: BN + relu + bf16 split -> s_abf [plane][n][c]
#pragma unroll
        for (int mi = 0; mi < 2; mi++) {
#pragma unroll
            for (int i = 0; i < 2; i++) {
                int row = (w * 2 + mi) * 16 + gr + i * 8;
                float inv = g_c1inv[row], bias = g_c1bias[row];
#pragma unroll
                for (int nt = 0; nt < 3; nt++) {
#pragma unroll
                    for (int j = 0; j < 2; j++) {
                        float x = fmaxf(fmaf(C2[mi][nt][i * 2 + j], inv, bias), 0.f);
                        int n = nt * 8 + 2 * gc + j;
                        float xhi = __bfloat162float(__float2bfloat16_rn(x));
                        s_abf[(0 * 24 + n) * ABF_STRIDE + row] = __float2bfloat16_rn(x);
                        s_abf[(1 * 24 + n) * ABF_STRIDE + row] = __float2bfloat16_rn(x - xhi);
                    }
                }
            }
        }
        __syncthreads();
        // GEMM2 accumulation for this point
#pragma unroll 4
        for (int ks = 0; ks < 16; ks++) {
            uint4 Ah = Ahi_p[ks * 32 + lane];
            uint4 Al = Alo_p[ks * 32 + lane];
#pragma unroll
            for (int nt = 0; nt < 3; nt++) {
                const __nv_bfloat16* bh = s_abf + (0 * 24 + nt * 8 + gr) * ABF_STRIDE + ks * 16 + 2 * gc;
                const __nv_bfloat16* bl = s_abf + (1 * 24 + nt * 8 + gr) * ABF_STRIDE + ks * 16 + 2 * gc;
                unsigned b0h = *reinterpret_cast<const unsigned*>(bh);
                unsigned b1h = *reinterpret_cast<const unsigned*>(bh + 8);
                unsigned b0l = *reinterpret_cast<const unsigned*>(bl);
                unsigned b1l = *reinterpret_cast<const unsigned*>(bl + 8);
                mma16816(C3[p][nt], Ah, b0h, b1h);
                mma16816(C3[p][nt], Ah, b0l, b1l);
                mma16816(C3[p][nt], Al, b0h, b1h);
            }
        }
    }

    // ---- epilogue: softmax over K per (row, point), aggregate with vg ----
    {
#pragma unroll
        for (int p = 0; p < PPB; p++) {
#pragma unroll
            for (int half = 0; half < 2; half++) {
                int r = w * 16 + gr + half * 8;
                int o = r >> 1;
                float ab = abt[o];
                float vals[6];
                int nvalid = (gc < 2) ? 6 : 4;
#pragma unroll
                for (int nt = 0; nt < 3; nt++)
#pragma unroll
                    for (int j = 0; j < 2; j++)
                        vals[nt * 2 + j] = C3[p][nt][half * 2 + j] + ab;
                float mx = -3.4e38f;
                for (int i = 0; i < nvalid; i++) mx = fmaxf(mx, vals[i]);
                mx = fmaxf(mx, __shfl_xor_sync(0xffffffffu, mx, 1));
                mx = fmaxf(mx, __shfl_xor_sync(0xffffffffu, mx, 2));
                const float* vgr = s_vg + p * DIMC * KNNC + o * KNNC;
                float s = 0.f, ws = 0.f;
                for (int i = 0; i < nvalid; i++) {
                    int nt = i >> 1, j = i & 1;
                    int nb = nt * 8 + 2 * gc + j;
                    float e = expf(vals[i] - mx);
                    s += e;
                    ws = fmaf(e, vgr[nb], ws);
                }
                s += __shfl_xor_sync(0xffffffffu, s, 1);
                s += __shfl_xor_sync(0xffffffffu, s, 2);
                ws += __shfl_xor_sync(0xffffffffu, ws, 1);
                ws += __shfl_xor_sync(0xffffffffu, ws, 2);
                if (gc == 0) s_agg[p * 128 + r] = ws / s;
            }
        }
    }
    __syncthreads();

    // ---- Phase 5: y = we @ agg + be + residual ----
    {
        int c2 = tid >> 1, rr = tid & 1;
        float accp[PPB];
#pragma unroll
        for (int pp = 0; pp < PPB; pp++) accp[pp] = 0.f;
        const float4* w4 = reinterpret_cast<const float4*>(we + c2 * DIMC);
#pragma unroll 4
        for (int o4 = 0; o4 < DIMC / 4; o4++) {
            float4 w = w4[o4];
#pragma unroll
            for (int j = 0; j < 4; j++) {
                float wj = (j == 0) ? w.x : (j == 1) ? w.y : (j == 2) ? w.z : w.w;
                int o = o4 * 4 + j;
#pragma unroll
                for (int pp = 0; pp < PPB; pp++)
                    accp[pp] = fmaf(wj, s_agg[pp * 128 + o * UPF + rr], accp[pp]);
            }
        }
        float bb = be[c2];
#pragma unroll
        for (int pp = 0; pp < PPB; pp++) {
            out[((size_t)(b * CINC + c2)) * (NPTS * UPF) + 2 * (size_t)(n0 + pp) + rr] =
                accp[pp] + bb + query[(b * CINC + c2) * NPTS + n0 + pp];
        }
    }
}

// ================= launch =================
extern "C" void kernel_launch(void* const* d_in, const int* in_sizes, int n_in,
                              void* d_out, int out_size)
{
    const float* pos1     = (const float*)d_in[0];
    const float* query    = (const float*)d_in[1];
    const float* pos2     = (const float*)d_in[2];
    const float* key_feat = (const float*)d_in[3];
    const float* wq  = (const float*)d_in[4];
    const float* bq  = (const float*)d_in[5];
    const float* wk  = (const float*)d_in[6];
    const float* bk  = (const float*)d_in[7];
    const float* wv  = (const float*)d_in[8];
    const float* bv  = (const float*)d_in[9];
    const float* pw1 = (const float*)d_in[10];
    const float* pb1 = (const float*)d_in[11];
    const float* pg  = (const float*)d_in[12];
    const float* pbt = (const float*)d_in[13];
    const float* pm  = (const float*)d_in[14];
    const float* pv  = (const float*)d_in[15];
    const float* pw2 = (const float*)d_in[16];
    const float* pb2 = (const float*)d_in[17];
    const float* aw1 = (const float*)d_in[18];
    const float* ab1 = (const float*)d_in[19];
    const float* ag  = (const float*)d_in[20];
    const float* abt2= (const float*)d_in[21];
    const float* am  = (const float*)d_in[22];
    const float* av  = (const float*)d_in[23];
    const float* awt = (const float*)d_in[24];
    const float* abt = (const float*)d_in[25];
    const float* we  = (const float*)d_in[26];
    const float* be  = (const float*)d_in[27];
    float* out = (float*)d_out;

    prep_kernel<<<128, 256>>>(aw1, pw2, wq, wk, wv, awt, ab1, ag, abt2, am, av);
    qkv_kernel<<<dim3(NPTS / 128, BATCH), 256>>>(query, key_feat, bq, bk, bv);
    knn_kernel<<<dim3(NPTS / 128, BATCH), 512>>>(pos1, pos2);
    attn_kernel<<<dim3(NPTS / PPB, BATCH), 256>>>(
        pos1, pos2, query,
        pw1, pb1, pg, pbt, pm, pv, pb2,
        abt, we, be, out);
}

// round 10
// speedup vs baseline: 2.2316x; 1.2819x over previous
#include <cuda_runtime.h>
#include <cuda_bf16.h>
#include <math.h>
#include <stdint.h>

#define BATCH 4
#define NPTS 4096
#define NPTS2 4096
#define CINC 128
#define DIMC 64
#define KNNC 20
#define UPF 2
#define HPOSC 64
#define HATTC 256
#define EPSV 1e-5f
#define PPB 2
#define ABF_STRIDE 264   // channels stride in s_abf rows
#define HBF_STRIDE 72    // o stride in s_hbf rows

// ---------------- scratch ----------------
__device__ float g_qt[BATCH * NPTS * DIMC];
__device__ float g_kt[BATCH * NPTS2 * DIMC];
__device__ float g_vt[BATCH * NPTS2 * DIMC];
__device__ int   g_idx[BATCH * NPTS * KNNC];
__device__ float g_pw2t[HPOSC * DIMC];
__device__ float g_wqt[CINC * DIMC];
__device__ float g_wkt[CINC * DIMC];
__device__ float g_wvt[CINC * DIMC];
// W2 (= awt^T, [128 rows][256 c]) A-fragments: (((plane*8 + mt)*16 + ks)*32 + lane)*4 + reg
__device__ unsigned g_w2frag[2 * 8 * 16 * 32 * 4];
// W1 (= aw1, [256 rows][64 o]) A-fragments: (((plane*16 + mt)*4 + ks)*32 + lane)*4 + reg
__device__ unsigned g_w1frag[2 * 16 * 4 * 32 * 4];
__device__ float g_c1inv[HATTC];
__device__ float g_c1bias[HATTC];

// ---------------- f32x2 helpers ----------------
__device__ __forceinline__ unsigned long long ffma2(
    unsigned long long a, unsigned long long b, unsigned long long c) {
    unsigned long long d;
    asm("fma.rn.f32x2 %0, %1, %2, %3;" : "=l"(d) : "l"(a), "l"(b), "l"(c));
    return d;
}
__device__ __forceinline__ unsigned long long pack2(float lo, float hi) {
    unsigned long long d;
    asm("mov.b64 %0, {%1, %2};" : "=l"(d) : "f"(lo), "f"(hi));
    return d;
}
__device__ __forceinline__ void unpack2(unsigned long long v, float& lo, float& hi) {
    asm("mov.b64 {%0, %1}, %2;" : "=f"(lo), "=f"(hi) : "l"(v));
}

// ---------------- mma.sync helper ----------------
__device__ __forceinline__ void mma16816(float* c, const uint4& a, unsigned b0, unsigned b1) {
    asm volatile(
        "mma.sync.aligned.m16n8k16.row.col.f32.bf16.bf16.f32 "
        "{%0,%1,%2,%3}, {%4,%5,%6,%7}, {%8,%9}, {%0,%1,%2,%3};"
        : "+f"(c[0]), "+f"(c[1]), "+f"(c[2]), "+f"(c[3])
        : "r"(a.x), "r"(a.y), "r"(a.z), "r"(a.w), "r"(b0), "r"(b1));
}
__device__ __forceinline__ unsigned bfpack(float x0, float x1) {
    return (unsigned)__bfloat16_as_ushort(__float2bfloat16_rn(x0)) |
           ((unsigned)__bfloat16_as_ushort(__float2bfloat16_rn(x1)) << 16);
}

// ================= prep =================
__global__ __launch_bounds__(256) void prep_kernel(
    const float* __restrict__ aw1, const float* __restrict__ pw2,
    const float* __restrict__ wq, const float* __restrict__ wk,
    const float* __restrict__ wv, const float* __restrict__ awt,
    const float* __restrict__ ab1, const float* __restrict__ ag,
    const float* __restrict__ abt2, const float* __restrict__ am,
    const float* __restrict__ av)
{
    int i = blockIdx.x * 256 + threadIdx.x;
    if (i < DIMC * HPOSC) {
        int o = i >> 6, h = i & 63;
        g_pw2t[h * DIMC + o] = pw2[i];
    }
    if (i < DIMC * CINC) {
        int o = i >> 7, c = i & 127;
        g_wqt[c * DIMC + o] = wq[i];
        g_wkt[c * DIMC + o] = wk[i];
        g_wvt[c * DIMC + o] = wv[i];
    }
    if (i < HATTC) {
        float inv = ag[i] * rsqrtf(av[i] + EPSV);
        g_c1inv[i] = inv;
        g_c1bias[i] = fmaf(ab1[i], inv, abt2[i]) - am[i] * inv;
    }
    if (i < 32768) {                       // W2 A-fragments
        int reg = i & 3, lane = (i >> 2) & 31, ks = (i >> 7) & 15;
        int mt = (i >> 11) & 7, plane = (i >> 14) & 1;
        int gr = lane >> 2, gc = lane & 3;
        int row = mt * 16 + gr + (reg & 1) * 8;
        int col = ks * 16 + 2 * gc + ((reg >> 1) & 1) * 8;
        float x0 = awt[col * 128 + row];
        float x1 = awt[(col + 1) * 128 + row];
        unsigned v;
        if (plane == 0) v = bfpack(x0, x1);
        else {
            float h0 = __bfloat162float(__float2bfloat16_rn(x0));
            float h1 = __bfloat162float(__float2bfloat16_rn(x1));
            v = bfpack(x0 - h0, x1 - h1);
        }
        g_w2frag[i] = v;
    }
    if (i < 16384) {                       // W1 A-fragments
        int reg = i & 3, lane = (i >> 2) & 31, ks = (i >> 7) & 3;
        int mt = (i >> 9) & 15, plane = (i >> 13) & 1;
        int gr = lane >> 2, gc = lane & 3;
        int row = mt * 16 + gr + (reg & 1) * 8;
        int col = ks * 16 + 2 * gc + ((reg >> 1) & 1) * 8;
        float x0 = aw1[row * DIMC + col];
        float x1 = aw1[row * DIMC + col + 1];
        unsigned v;
        if (plane == 0) v = bfpack(x0, x1);
        else {
            float h0 = __bfloat162float(__float2bfloat16_rn(x0));
            float h1 = __bfloat162float(__float2bfloat16_rn(x1));
            v = bfpack(x0 - h0, x1 - h1);
        }
        g_w1frag[i] = v;
    }
}

// ================= QKV =================
__global__ __launch_bounds__(256) void qkv_kernel(
    const float* __restrict__ query, const float* __restrict__ key_feat,
    const float* __restrict__ bq, const float* __restrict__ bk, const float* __restrict__ bv)
{
    int b = blockIdx.y;
    int n0 = blockIdx.x * 128;
    int tid = threadIdx.x;
    __shared__ __align__(16) float tile[CINC * 128];
    int o = tid & 63, jb = tid >> 6;

    for (int i = tid; i < CINC * 128; i += 256) {
        int c = i >> 7, j = i & 127;
        tile[i] = query[(b * CINC + c) * NPTS + n0 + j];
    }
    __syncthreads();
    {
        unsigned long long acc[16];
#pragma unroll
        for (int m = 0; m < 16; m++) acc[m] = 0ULL;
#pragma unroll 4
        for (int c = 0; c < CINC; c++) {
            float w = g_wqt[c * DIMC + o];
            unsigned long long wp = pack2(w, w);
            const ulonglong2* tp = reinterpret_cast<const ulonglong2*>(tile + c * 128 + jb * 32);
#pragma unroll
            for (int jj = 0; jj < 8; jj++) {
                ulonglong2 t = tp[jj];
                acc[2 * jj]     = ffma2(wp, t.x, acc[2 * jj]);
                acc[2 * jj + 1] = ffma2(wp, t.y, acc[2 * jj + 1]);
            }
        }
        float bias = bq[o];
#pragma unroll
        for (int m = 0; m < 16; m++) {
            float lo, hi;
            unpack2(acc[m], lo, hi);
            int j = jb * 32 + 2 * m;
            g_qt[(b * NPTS + n0 + j) * DIMC + o]     = lo + bias;
            g_qt[(b * NPTS + n0 + j + 1) * DIMC + o] = hi + bias;
        }
    }
    __syncthreads();
    for (int i = tid; i < CINC * 128; i += 256) {
        int c = i >> 7, j = i & 127;
        tile[i] = key_feat[(b * CINC + c) * NPTS2 + n0 + j];
    }
    __syncthreads();
#pragma unroll
    for (int which = 0; which < 2; which++) {
        const float* wt = which ? g_wvt : g_wkt;
        float* gout = which ? g_vt : g_kt;
        float bias = which ? bv[o] : bk[o];
        unsigned long long acc[16];
#pragma unroll
        for (int m = 0; m < 16; m++) acc[m] = 0ULL;
#pragma unroll 4
        for (int c = 0; c < CINC; c++) {
            float w = wt[c * DIMC + o];
            unsigned long long wp = pack2(w, w);
            const ulonglong2* tp = reinterpret_cast<const ulonglong2*>(tile + c * 128 + jb * 32);
#pragma unroll
            for (int jj = 0; jj < 8; jj++) {
                ulonglong2 t = tp[jj];
                acc[2 * jj]     = ffma2(wp, t.x, acc[2 * jj]);
                acc[2 * jj + 1] = ffma2(wp, t.y, acc[2 * jj + 1]);
            }
        }
#pragma unroll
        for (int m = 0; m < 16; m++) {
            float lo, hi;
            unpack2(acc[m], lo, hi);
            int j = jb * 32 + 2 * m;
            gout[(b * NPTS2 + n0 + j) * DIMC + o]     = lo + bias;
            gout[(b * NPTS2 + n0 + j + 1) * DIMC + o] = hi + bias;
        }
    }
}

// ================= KNN =================
#define INSERT_CHAIN(d_, i_) do { \
    float cd = (d_); int ci = (i_); \
    _Pragma("unroll") \
    for (int j = 0; j < KNNC; j++) { \
        if (cd < bd[j]) { \
            float td = bd[j]; bd[j] = cd; cd = td; \
            int ti = bi[j]; bi[j] = ci; ci = ti; \
        } \
    } \
} while (0)

__global__ __launch_bounds__(512) void knn_kernel(
    const float* __restrict__ pos1, const float* __restrict__ pos2)
{
    int b = blockIdx.y;
    int tid = threadIdx.x;
    int q = tid & 127, quarter = tid >> 7;
    int n = blockIdx.x * 128 + q;

    __shared__ float sx[4096], sy[4096], sz[4096], sq2[4096];
    __shared__ float smd[512][KNNC];
    __shared__ int   smi[512][KNNC];

    for (int i = tid; i < 4096; i += 512) {
        float x = pos2[(b * 3 + 0) * NPTS2 + i];
        float y = pos2[(b * 3 + 1) * NPTS2 + i];
        float z = pos2[(b * 3 + 2) * NPTS2 + i];
        sx[i] = x; sy[i] = y; sz[i] = z;
        sq2[i] = x * x + y * y + z * z;
    }
    float qx = pos1[(b * 3 + 0) * NPTS + n];
    float qy = pos1[(b * 3 + 1) * NPTS + n];
    float qz = pos1[(b * 3 + 2) * NPTS + n];
    float n1 = qx * qx + qy * qy + qz * qz;

    float bd[KNNC];
    int bi[KNNC];
#pragma unroll
    for (int j = 0; j < KNNC; j++) { bd[j] = 3.4e38f; bi[j] = 0; }
    __syncthreads();
    int base = quarter * 1024;

    // bootstrap: first 64 candidates via direct chain
    for (int m = 0; m < 64; m++) {
        int mm = base + m;
        float dot = fmaf(qx, sx[mm], fmaf(qy, sy[mm], qz * sz[mm]));
        float d = n1 + sq2[mm] - 2.f * dot;
        if (d < bd[KNNC - 1]) INSERT_CHAIN(d, mm);
    }
    // buffered chunks: frozen threshold over-collects (never misses), drain via chain
    {
        float fb[32];
        int ib[32];
        for (int chunk = 0; chunk < 15; chunk++) {
            int s0 = 64 + chunk * 64;
            float thr = bd[KNNC - 1];
            int cnt = 0;
            for (int m = s0; m < s0 + 64; m++) {
                int mm = base + m;
                float dot = fmaf(qx, sx[mm], fmaf(qy, sy[mm], qz * sz[mm]));
                float d = n1 + sq2[mm] - 2.f * dot;
                if (d < thr) {
                    if (cnt < 32) { fb[cnt] = d; ib[cnt] = mm; cnt++; }
                    else if (d < bd[KNNC - 1]) INSERT_CHAIN(d, mm);
                }
            }
            for (int t = 0; t < cnt; t++) {
                float d = fb[t];
                int mm = ib[t];
                if (d < bd[KNNC - 1]) INSERT_CHAIN(d, mm);
            }
        }
    }
#pragma unroll
    for (int j = 0; j < KNNC; j++) { smd[tid][j] = bd[j]; smi[tid][j] = bi[j]; }
    __syncthreads();
    if (quarter == 0) {
        int head[4] = {0, 0, 0, 0};
#pragma unroll
        for (int t = 0; t < KNNC; t++) {
            float best = 3.5e38f;
            int bqv = 0;
#pragma unroll
            for (int qu = 0; qu < 4; qu++) {
                if (head[qu] < KNNC) {
                    float v = smd[qu * 128 + q][head[qu]];
                    if (v < best) { best = v; bqv = qu; }
                }
            }
            g_idx[(b * NPTS + n) * KNNC + t] = smi[bqv * 128 + q][head[bqv]];
            head[bqv]++;
        }
    }
}

// ================= fused attention kernel =================
__global__ __launch_bounds__(256, 3) void attn_kernel(
    const float* __restrict__ pos1, const float* __restrict__ pos2,
    const float* __restrict__ query,
    const float* __restrict__ pw1, const float* __restrict__ pb1,
    const float* __restrict__ pg,  const float* __restrict__ pbt,
    const float* __restrict__ pm,  const float* __restrict__ pv,
    const float* __restrict__ pb2,
    const float* __restrict__ abt,
    const float* __restrict__ we,  const float* __restrict__ be,
    float* __restrict__ out)
{
    int b = blockIdx.y;
    int n0 = blockIdx.x * PPB;
    int tid = threadIdx.x;

    __shared__ __align__(16) float s_h[PPB * DIMC * KNNC];     // qk_rel fp32 (10 KB)
    __shared__ __align__(16) float s_vg[PPB * DIMC * KNNC];    // 10 KB
    // overlay: s_pe1 (6 KB) then s_abf [p][n(24)][c(ABF_STRIDE)] single bf16 plane (25.3 KB)
    __shared__ __align__(16) unsigned char s_big[PPB * 24 * ABF_STRIDE * 2];
    __shared__ __align__(16) __nv_bfloat16 s_hbf[PPB * 2 * 24 * HBF_STRIDE]; // 13.8 KB
    __shared__ float s_q[PPB * DIMC];
    __shared__ float s_prel[PPB * 3 * KNNC];
    __shared__ float s_agg[PPB * DIMC * UPF];
    __shared__ int   s_idx[PPB * KNNC];

    float* s_pe1 = reinterpret_cast<float*>(s_big);
    __nv_bfloat16* s_abf = reinterpret_cast<__nv_bfloat16*>(s_big);

    // ---- Phase 0 ----
    if (tid < PPB * KNNC) {
        int p = tid / KNNC, k = tid - p * KNNC;
        s_idx[tid] = g_idx[(b * NPTS + n0 + p) * KNNC + k];
    }
    if (tid < PPB * DIMC) {
        int p = tid >> 6, o = tid & 63;
        s_q[tid] = g_qt[(b * NPTS + n0 + p) * DIMC + o];
    }
    // zero padded neighbor rows (20..23) of s_hbf
    {
        unsigned* hz = reinterpret_cast<unsigned*>(s_hbf);
        for (int e = tid; e < PPB * 2 * 4 * (HBF_STRIDE / 2); e += 256) {
            int woff = e % (HBF_STRIDE / 2);
            int rsel = e / (HBF_STRIDE / 2);
            int r = rsel & 3, pl = (rsel >> 2) & 1, p = rsel >> 3;
            hz[((p * 2 + pl) * 24 + 20 + r) * (HBF_STRIDE / 2) + woff] = 0u;
        }
    }
    __syncthreads();
    if (tid < PPB * 3 * KNNC) {
        int p = tid / (3 * KNNC), rem = tid - p * 3 * KNNC;
        int c = rem / KNNC, k = rem - c * KNNC;
        s_prel[tid] = pos1[(b * 3 + c) * NPTS + n0 + p]
                    - pos2[(b * 3 + c) * NPTS2 + s_idx[p * KNNC + k]];
    }
#pragma unroll
    for (int p = 0; p < PPB; p++) {
        for (int e = tid; e < DIMC * KNNC; e += 256) {
            int k = e >> 6, o = e & 63;
            int m = s_idx[p * KNNC + k];
            s_h[p * DIMC * KNNC + o * KNNC + k]  = s_q[p * DIMC + o] - g_kt[(b * NPTS2 + m) * DIMC + o];
            s_vg[p * DIMC * KNNC + o * KNNC + k] = g_vt[(b * NPTS2 + m) * DIMC + o];
        }
    }
    __syncthreads();

    // ---- Phase 1 + 1b per point: pe; h -> s_hbf (bf16 hi/lo), vg += pe ----
#pragma unroll
    for (int p = 0; p < PPB; p++) {
        for (int e = tid; e < HPOSC * 24; e += 256) {
            int h = e / 24, k = e - h * 24;
            float val = 0.f;
            if (k < KNNC) {
                const float* pr = s_prel + p * 3 * KNNC;
                float acc = fmaf(pw1[h * 3 + 0], pr[k],
                            fmaf(pw1[h * 3 + 1], pr[KNNC + k],
                                 pw1[h * 3 + 2] * pr[2 * KNNC + k])) + pb1[h];
                float inv = pg[h] * rsqrtf(pv[h] + EPSV);
                acc = fmaf(acc, inv, pbt[h] - pm[h] * inv);
                val = fmaxf(acc, 0.f);
            }
            s_pe1[e] = val;
        }
        __syncthreads();
        {
            int op = tid & 31, kg = tid >> 5;
            int o0 = op * 2, k0 = kg * 3;
            unsigned long long acc[3] = {0ULL, 0ULL, 0ULL};
#pragma unroll 4
            for (int h = 0; h < HPOSC; h++) {
                unsigned long long w2 =
                    *reinterpret_cast<const unsigned long long*>(g_pw2t + h * DIMC + o0);
                const float* br = s_pe1 + h * 24 + k0;
                acc[0] = ffma2(w2, pack2(br[0], br[0]), acc[0]);
                acc[1] = ffma2(w2, pack2(br[1], br[1]), acc[1]);
                acc[2] = ffma2(w2, pack2(br[2], br[2]), acc[2]);
            }
            float b0 = pb2[o0], b1 = pb2[o0 + 1];
            const float* hb = s_h + p * DIMC * KNNC;
            float* vb = s_vg + p * DIMC * KNNC;
            unsigned* hbf_hi = reinterpret_cast<unsigned*>(
                s_hbf + (p * 2 + 0) * 24 * HBF_STRIDE);
            unsigned* hbf_lo = reinterpret_cast<unsigned*>(
                s_hbf + (p * 2 + 1) * 24 * HBF_STRIDE);
#pragma unroll
            for (int j = 0; j < 3; j++) {
                int k = k0 + j;
                if (k < KNNC) {
                    float lo, hi;
                    unpack2(acc[j], lo, hi);
                    float v0 = lo + b0, v1 = hi + b1;
                    float h0 = hb[o0 * KNNC + k] + v0;
                    float h1 = hb[(o0 + 1) * KNNC + k] + v1;
                    vb[o0 * KNNC + k] += v0;
                    vb[(o0 + 1) * KNNC + k] += v1;
                    float h0hi = __bfloat162float(__float2bfloat16_rn(h0));
                    float h1hi = __bfloat162float(__float2bfloat16_rn(h1));
                    hbf_hi[(k * HBF_STRIDE + o0) >> 1] = bfpack(h0, h1);
                    hbf_lo[(k * HBF_STRIDE + o0) >> 1] = bfpack(h0 - h0hi, h1 - h1hi);
                }
            }
        }
        __syncthreads();
    }

    // ---- Phase 2: GEMM1 (3-term mma) both points -> s_abf single bf16 plane ----
    int w = tid >> 5, lane = tid & 31;
    int gr = lane >> 2, gc = lane & 3;
    const uint4* W1 = reinterpret_cast<const uint4*>(g_w1frag);
    const uint4* Ahi_p = reinterpret_cast<const uint4*>(g_w2frag) + ((0 * 8 + w) * 16) * 32;
    const uint4* Alo_p = reinterpret_cast<const uint4*>(g_w2frag) + ((1 * 8 + w) * 16) * 32;

#pragma unroll
    for (int p = 0; p < PPB; p++) {
        float C2[2][3][4];
#pragma unroll
        for (int mi = 0; mi < 2; mi++)
#pragma unroll
            for (int nt = 0; nt < 3; nt++)
#pragma unroll
                for (int r = 0; r < 4; r++) C2[mi][nt][r] = 0.f;

#pragma unroll
        for (int ks = 0; ks < 4; ks++) {
            unsigned bh0[3], bh1[3], bl0[3], bl1[3];
#pragma unroll
            for (int nt = 0; nt < 3; nt++) {
                const __nv_bfloat16* bh =
                    s_hbf + ((p * 2 + 0) * 24 + nt * 8 + gr) * HBF_STRIDE + ks * 16 + 2 * gc;
                const __nv_bfloat16* bl =
                    s_hbf + ((p * 2 + 1) * 24 + nt * 8 + gr) * HBF_STRIDE + ks * 16 + 2 * gc;
                bh0[nt] = *reinterpret_cast<const unsigned*>(bh);
                bh1[nt] = *reinterpret_cast<const unsigned*>(bh + 8);
                bl0[nt] = *reinterpret_cast<const unsigned*>(bl);
                bl1[nt] = *reinterpret_cast<const unsigned*>(bl + 8);
            }
#pragma unroll
            for (int mi = 0; mi < 2; mi++) {
                int mt = w * 2 + mi;
                uint4 Ah = W1[((0 * 16 + mt) * 4 + ks) * 32 + lane];
                uint4 Al = W1[((1 * 16 + mt) * 4 + ks) * 32 + lane];
#pragma unroll
                for (int nt = 0; nt < 3; nt++) {
                    mma16816(C2[mi][nt], Ah, bh0[nt], bh1[nt]);
                    mma16816(C2[mi][nt], Ah, bl0[nt], bl1[nt]);
                    mma16816(C2[mi][nt], Al, bh0[nt], bh1[nt]);
                }
            }
        }
        // epilogue: BN + relu -> single bf16 plane s_abf[p]
#pragma unroll
        for (int mi = 0; mi < 2; mi++) {
#pragma unroll
            for (int i = 0; i < 2; i++) {
                int row = (w * 2 + mi) * 16 + gr + i * 8;
                float inv = g_c1inv[row], bias = g_c1bias[row];
#pragma unroll
                for (int nt = 0; nt < 3; nt++) {
#pragma unroll
                    for (int j = 0; j < 2; j++) {
                        float x = fmaxf(fmaf(C2[mi][nt][i * 2 + j], inv, bias), 0.f);
                        int nn = nt * 8 + 2 * gc + j;
                        s_abf[(p * 24 + nn) * ABF_STRIDE + row] = __float2bfloat16_rn(x);
                    }
                }
            }
        }
    }
    __syncthreads();

    // ---- Phase 3: GEMM2 (2-term: Whi*a + Wlo*a), ks-outer to reuse A-frags ----
    float C3[PPB][3][4];
#pragma unroll
    for (int p = 0; p < PPB; p++)
#pragma unroll
        for (int nt = 0; nt < 3; nt++)
#pragma unroll
            for (int r = 0; r < 4; r++) C3[p][nt][r] = 0.f;

#pragma unroll 4
    for (int ks = 0; ks < 16; ks++) {
        uint4 Ah = Ahi_p[ks * 32 + lane];
        uint4 Al = Alo_p[ks * 32 + lane];
#pragma unroll
        for (int p = 0; p < PPB; p++) {
#pragma unroll
            for (int nt = 0; nt < 3; nt++) {
                const __nv_bfloat16* bp =
                    s_abf + (p * 24 + nt * 8 + gr) * ABF_STRIDE + ks * 16 + 2 * gc;
                unsigned b0 = *reinterpret_cast<const unsigned*>(bp);
                unsigned b1 = *reinterpret_cast<const unsigned*>(bp + 8);
                mma16816(C3[p][nt], Ah, b0, b1);
                mma16816(C3[p][nt], Al, b0, b1);
            }
        }
    }

    // ---- epilogue: softmax over K per (row, point), aggregate with vg ----
    {
#pragma unroll
        for (int p = 0; p < PPB; p++) {
#pragma unroll
            for (int half = 0; half < 2; half++) {
                int r = w * 16 + gr + half * 8;
                int o = r >> 1;
                float ab = abt[o];
                float vals[6];
                int nvalid = (gc < 2) ? 6 : 4;
#pragma unroll
                for (int nt = 0; nt < 3; nt++)
#pragma unroll
                    for (int j = 0; j < 2; j++)
                        vals[nt * 2 + j] = C3[p][nt][half * 2 + j] + ab;
                float mx = -3.4e38f;
                for (int i = 0; i < nvalid; i++) mx = fmaxf(mx, vals[i]);
                mx = fmaxf(mx, __shfl_xor_sync(0xffffffffu, mx, 1));
                mx = fmaxf(mx, __shfl_xor_sync(0xffffffffu, mx, 2));
                const float* vgr = s_vg + p * DIMC * KNNC + o * KNNC;
                float s = 0.f, ws = 0.f;
                for (int i = 0; i < nvalid; i++) {
                    int nt = i >> 1, j = i & 1;
                    int nb = nt * 8 + 2 * gc + j;
                    float e = expf(vals[i] - mx);
                    s += e;
                    ws = fmaf(e, vgr[nb], ws);
                }
                s += __shfl_xor_sync(0xffffffffu, s, 1);
                s += __shfl_xor_sync(0xffffffffu, s, 2);
                ws += __shfl_xor_sync(0xffffffffu, ws, 1);
                ws += __shfl_xor_sync(0xffffffffu, ws, 2);
                if (gc == 0) s_agg[p * 128 + r] = ws / s;
            }
        }
    }
    __syncthreads();

    // ---- Phase 5: y = we @ agg + be + residual ----
    {
        int c2 = tid >> 1, rr = tid & 1;
        float accp[PPB];
#pragma unroll
        for (int pp = 0; pp < PPB; pp++) accp[pp] = 0.f;
        const float4* w4 = reinterpret_cast<const float4*>(we + c2 * DIMC);
#pragma unroll 4
        for (int o4 = 0; o4 < DIMC / 4; o4++) {
            float4 ww = w4[o4];
#pragma unroll
            for (int j = 0; j < 4; j++) {
                float wj = (j == 0) ? ww.x : (j == 1) ? ww.y : (j == 2) ? ww.z : ww.w;
                int o = o4 * 4 + j;
#pragma unroll
                for (int pp = 0; pp < PPB; pp++)
                    accp[pp] = fmaf(wj, s_agg[pp * 128 + o * UPF + rr], accp[pp]);
            }
        }
        float bb = be[c2];
#pragma unroll
        for (int pp = 0; pp < PPB; pp++) {
            out[((size_t)(b * CINC + c2)) * (NPTS * UPF) + 2 * (size_t)(n0 + pp) + rr] =
                accp[pp] + bb + query[(b * CINC + c2) * NPTS + n0 + pp];
        }
    }
}

// ================= launch =================
extern "C" void kernel_launch(void* const* d_in, const int* in_sizes, int n_in,
                              void* d_out, int out_size)
{
    const float* pos1     = (const float*)d_in[0];
    const float* query    = (const float*)d_in[1];
    const float* pos2     = (const float*)d_in[2];
    const float* key_feat = (const float*)d_in[3];
    const float* wq  = (const float*)d_in[4];
    const float* bq  = (const float*)d_in[5];
    const float* wk  = (const float*)d_in[6];
    const float* bk  = (const float*)d_in[7];
    const float* wv  = (const float*)d_in[8];
    const float* bv  = (const float*)d_in[9];
    const float* pw1 = (const float*)d_in[10];
    const float* pb1 = (const float*)d_in[11];
    const float* pg  = (const float*)d_in[12];
    const float* pbt = (const float*)d_in[13];
    const float* pm  = (const float*)d_in[14];
    const float* pv  = (const float*)d_in[15];
    const float* pw2 = (const float*)d_in[16];
    const float* pb2 = (const float*)d_in[17];
    const float* aw1 = (const float*)d_in[18];
    const float* ab1 = (const float*)d_in[19];
    const float* ag  = (const float*)d_in[20];
    const float* abt2= (const float*)d_in[21];
    const float* am  = (const float*)d_in[22];
    const float* av  = (const float*)d_in[23];
    const float* awt = (const float*)d_in[24];
    const float* abt = (const float*)d_in[25];
    const float* we  = (const float*)d_in[26];
    const float* be  = (const float*)d_in[27];
    float* out = (float*)d_out;

    prep_kernel<<<128, 256>>>(aw1, pw2, wq, wk, wv, awt, ab1, ag, abt2, am, av);
    qkv_kernel<<<dim3(NPTS / 128, BATCH), 256>>>(query, key_feat, bq, bk, bv);
    knn_kernel<<<dim3(NPTS / 128, BATCH), 512>>>(pos1, pos2);
    attn_kernel<<<dim3(NPTS / PPB, BATCH), 256>>>(
        pos1, pos2, query,
        pw1, pb1, pg, pbt, pm, pv, pb2,
        abt, we, be, out);
}

// round 11
// speedup vs baseline: 2.9162x; 1.3068x over previous
#include <cuda_runtime.h>
#include <cuda_bf16.h>
#include <math.h>
#include <stdint.h>

#define BATCH 4
#define NPTS 4096
#define NPTS2 4096
#define CINC 128
#define DIMC 64
#define KNNC 20
#define UPF 2
#define HPOSC 64
#define HATTC 256
#define EPSV 1e-5f
#define PPB 2
#define ABF_STRIDE 264   // channels stride in s_abf rows
#define HBF_STRIDE 72    // o stride in s_hbf / s_pe1bf rows

// ---------------- scratch ----------------
__device__ float g_qt[BATCH * NPTS * DIMC];
__device__ float g_kt[BATCH * NPTS2 * DIMC];
__device__ float g_vt[BATCH * NPTS2 * DIMC];
__device__ int   g_idx[BATCH * NPTS * KNNC];
__device__ float g_wqt[CINC * DIMC];
__device__ float g_wkt[CINC * DIMC];
__device__ float g_wvt[CINC * DIMC];
// W2 (= awt^T, [128 rows][256 c]) A-fragments: (((plane*8 + mt)*16 + ks)*32 + lane)*4 + reg
__device__ unsigned g_w2frag[2 * 8 * 16 * 32 * 4];
// W1 (= aw1, [256 rows][64 o]) A-fragments: (((plane*16 + mt)*4 + ks)*32 + lane)*4 + reg
__device__ unsigned g_w1frag[2 * 16 * 4 * 32 * 4];
// PW2 ([64 rows o][64 cols h]) A-fragments: (((plane*4 + mt)*4 + ks)*32 + lane)*4 + reg
__device__ unsigned g_pwfrag[2 * 4 * 4 * 32 * 4];
__device__ float g_c1inv[HATTC];
__device__ float g_c1bias[HATTC];

// ---------------- f32x2 helpers ----------------
__device__ __forceinline__ unsigned long long ffma2(
    unsigned long long a, unsigned long long b, unsigned long long c) {
    unsigned long long d;
    asm("fma.rn.f32x2 %0, %1, %2, %3;" : "=l"(d) : "l"(a), "l"(b), "l"(c));
    return d;
}
__device__ __forceinline__ unsigned long long pack2(float lo, float hi) {
    unsigned long long d;
    asm("mov.b64 %0, {%1, %2};" : "=l"(d) : "f"(lo), "f"(hi));
    return d;
}
__device__ __forceinline__ void unpack2(unsigned long long v, float& lo, float& hi) {
    asm("mov.b64 {%0, %1}, %2;" : "=f"(lo), "=f"(hi) : "l"(v));
}

// ---------------- mma.sync helper ----------------
__device__ __forceinline__ void mma16816(float* c, const uint4& a, unsigned b0, unsigned b1) {
    asm volatile(
        "mma.sync.aligned.m16n8k16.row.col.f32.bf16.bf16.f32 "
        "{%0,%1,%2,%3}, {%4,%5,%6,%7}, {%8,%9}, {%0,%1,%2,%3};"
        : "+f"(c[0]), "+f"(c[1]), "+f"(c[2]), "+f"(c[3])
        : "r"(a.x), "r"(a.y), "r"(a.z), "r"(a.w), "r"(b0), "r"(b1));
}
__device__ __forceinline__ unsigned bfpack(float x0, float x1) {
    return (unsigned)__bfloat16_as_ushort(__float2bfloat16_rn(x0)) |
           ((unsigned)__bfloat16_as_ushort(__float2bfloat16_rn(x1)) << 16);
}

// ================= prep =================
__global__ __launch_bounds__(256) void prep_kernel(
    const float* __restrict__ aw1, const float* __restrict__ pw2,
    const float* __restrict__ wq, const float* __restrict__ wk,
    const float* __restrict__ wv, const float* __restrict__ awt,
    const float* __restrict__ ab1, const float* __restrict__ ag,
    const float* __restrict__ abt2, const float* __restrict__ am,
    const float* __restrict__ av)
{
    int i = blockIdx.x * 256 + threadIdx.x;
    if (i < DIMC * CINC) {
        int o = i >> 7, c = i & 127;
        g_wqt[c * DIMC + o] = wq[i];
        g_wkt[c * DIMC + o] = wk[i];
        g_wvt[c * DIMC + o] = wv[i];
    }
    if (i < HATTC) {
        float inv = ag[i] * rsqrtf(av[i] + EPSV);
        g_c1inv[i] = inv;
        g_c1bias[i] = fmaf(ab1[i], inv, abt2[i]) - am[i] * inv;
    }
    if (i < 32768) {                       // W2 A-fragments
        int reg = i & 3, lane = (i >> 2) & 31, ks = (i >> 7) & 15;
        int mt = (i >> 11) & 7, plane = (i >> 14) & 1;
        int gr = lane >> 2, gc = lane & 3;
        int row = mt * 16 + gr + (reg & 1) * 8;
        int col = ks * 16 + 2 * gc + ((reg >> 1) & 1) * 8;
        float x0 = awt[col * 128 + row];
        float x1 = awt[(col + 1) * 128 + row];
        unsigned v;
        if (plane == 0) v = bfpack(x0, x1);
        else {
            float h0 = __bfloat162float(__float2bfloat16_rn(x0));
            float h1 = __bfloat162float(__float2bfloat16_rn(x1));
            v = bfpack(x0 - h0, x1 - h1);
        }
        g_w2frag[i] = v;
    }
    if (i < 16384) {                       // W1 A-fragments
        int reg = i & 3, lane = (i >> 2) & 31, ks = (i >> 7) & 3;
        int mt = (i >> 9) & 15, plane = (i >> 13) & 1;
        int gr = lane >> 2, gc = lane & 3;
        int row = mt * 16 + gr + (reg & 1) * 8;
        int col = ks * 16 + 2 * gc + ((reg >> 1) & 1) * 8;
        float x0 = aw1[row * DIMC + col];
        float x1 = aw1[row * DIMC + col + 1];
        unsigned v;
        if (plane == 0) v = bfpack(x0, x1);
        else {
            float h0 = __bfloat162float(__float2bfloat16_rn(x0));
            float h1 = __bfloat162float(__float2bfloat16_rn(x1));
            v = bfpack(x0 - h0, x1 - h1);
        }
        g_w1frag[i] = v;
    }
    if (i < 4096) {                        // PW2 A-fragments
        int reg = i & 3, lane = (i >> 2) & 31, ks = (i >> 7) & 3;
        int mt = (i >> 9) & 3, plane = (i >> 11) & 1;
        int gr = lane >> 2, gc = lane & 3;
        int row = mt * 16 + gr + (reg & 1) * 8;
        int col = ks * 16 + 2 * gc + ((reg >> 1) & 1) * 8;
        float x0 = pw2[row * HPOSC + col];
        float x1 = pw2[row * HPOSC + col + 1];
        unsigned v;
        if (plane == 0) v = bfpack(x0, x1);
        else {
            float h0 = __bfloat162float(__float2bfloat16_rn(x0));
            float h1 = __bfloat162float(__float2bfloat16_rn(x1));
            v = bfpack(x0 - h0, x1 - h1);
        }
        g_pwfrag[i] = v;
    }
}

// ================= QKV =================
__global__ __launch_bounds__(256) void qkv_kernel(
    const float* __restrict__ query, const float* __restrict__ key_feat,
    const float* __restrict__ bq, const float* __restrict__ bk, const float* __restrict__ bv)
{
    int b = blockIdx.y;
    int n0 = blockIdx.x * 128;
    int tid = threadIdx.x;
    __shared__ __align__(16) float tile[CINC * 128];
    int o = tid & 63, jb = tid >> 6;

    for (int i = tid; i < CINC * 128; i += 256) {
        int c = i >> 7, j = i & 127;
        tile[i] = query[(b * CINC + c) * NPTS + n0 + j];
    }
    __syncthreads();
    {
        unsigned long long acc[16];
#pragma unroll
        for (int m = 0; m < 16; m++) acc[m] = 0ULL;
#pragma unroll 4
        for (int c = 0; c < CINC; c++) {
            float w = g_wqt[c * DIMC + o];
            unsigned long long wp = pack2(w, w);
            const ulonglong2* tp = reinterpret_cast<const ulonglong2*>(tile + c * 128 + jb * 32);
#pragma unroll
            for (int jj = 0; jj < 8; jj++) {
                ulonglong2 t = tp[jj];
                acc[2 * jj]     = ffma2(wp, t.x, acc[2 * jj]);
                acc[2 * jj + 1] = ffma2(wp, t.y, acc[2 * jj + 1]);
            }
        }
        float bias = bq[o];
#pragma unroll
        for (int m = 0; m < 16; m++) {
            float lo, hi;
            unpack2(acc[m], lo, hi);
            int j = jb * 32 + 2 * m;
            g_qt[(b * NPTS + n0 + j) * DIMC + o]     = lo + bias;
            g_qt[(b * NPTS + n0 + j + 1) * DIMC + o] = hi + bias;
        }
    }
    __syncthreads();
    for (int i = tid; i < CINC * 128; i += 256) {
        int c = i >> 7, j = i & 127;
        tile[i] = key_feat[(b * CINC + c) * NPTS2 + n0 + j];
    }
    __syncthreads();
#pragma unroll
    for (int which = 0; which < 2; which++) {
        const float* wt = which ? g_wvt : g_wkt;
        float* gout = which ? g_vt : g_kt;
        float bias = which ? bv[o] : bk[o];
        unsigned long long acc[16];
#pragma unroll
        for (int m = 0; m < 16; m++) acc[m] = 0ULL;
#pragma unroll 4
        for (int c = 0; c < CINC; c++) {
            float w = wt[c * DIMC + o];
            unsigned long long wp = pack2(w, w);
            const ulonglong2* tp = reinterpret_cast<const ulonglong2*>(tile + c * 128 + jb * 32);
#pragma unroll
            for (int jj = 0; jj < 8; jj++) {
                ulonglong2 t = tp[jj];
                acc[2 * jj]     = ffma2(wp, t.x, acc[2 * jj]);
                acc[2 * jj + 1] = ffma2(wp, t.y, acc[2 * jj + 1]);
            }
        }
#pragma unroll
        for (int m = 0; m < 16; m++) {
            float lo, hi;
            unpack2(acc[m], lo, hi);
            int j = jb * 32 + 2 * m;
            gout[(b * NPTS2 + n0 + j) * DIMC + o]     = lo + bias;
            gout[(b * NPTS2 + n0 + j + 1) * DIMC + o] = hi + bias;
        }
    }
}

// ================= KNN =================
#define INSERT_CHAIN(d_, i_) do { \
    float cd = (d_); int ci = (i_); \
    _Pragma("unroll") \
    for (int j = 0; j < KNNC; j++) { \
        if (cd < bd[j]) { \
            float td = bd[j]; bd[j] = cd; cd = td; \
            int ti = bi[j]; bi[j] = ci; ci = ti; \
        } \
    } \
} while (0)

__global__ __launch_bounds__(512) void knn_kernel(
    const float* __restrict__ pos1, const float* __restrict__ pos2)
{
    int b = blockIdx.y;
    int tid = threadIdx.x;
    int q = tid & 127, quarter = tid >> 7;
    int n = blockIdx.x * 128 + q;

    __shared__ float sx[4096], sy[4096], sz[4096], sq2[4096];
    __shared__ float smd[512][KNNC];
    __shared__ int   smi[512][KNNC];

    for (int i = tid; i < 4096; i += 512) {
        float x = pos2[(b * 3 + 0) * NPTS2 + i];
        float y = pos2[(b * 3 + 1) * NPTS2 + i];
        float z = pos2[(b * 3 + 2) * NPTS2 + i];
        sx[i] = x; sy[i] = y; sz[i] = z;
        sq2[i] = x * x + y * y + z * z;
    }
    float qx = pos1[(b * 3 + 0) * NPTS + n];
    float qy = pos1[(b * 3 + 1) * NPTS + n];
    float qz = pos1[(b * 3 + 2) * NPTS + n];
    float n1 = qx * qx + qy * qy + qz * qz;

    float bd[KNNC];
    int bi[KNNC];
#pragma unroll
    for (int j = 0; j < KNNC; j++) { bd[j] = 3.4e38f; bi[j] = 0; }
    __syncthreads();
    int base = quarter * 1024;

    for (int m = 0; m < 64; m++) {
        int mm = base + m;
        float dot = fmaf(qx, sx[mm], fmaf(qy, sy[mm], qz * sz[mm]));
        float d = n1 + sq2[mm] - 2.f * dot;
        if (d < bd[KNNC - 1]) INSERT_CHAIN(d, mm);
    }
    {
        float fb[32];
        int ib[32];
        for (int chunk = 0; chunk < 15; chunk++) {
            int s0 = 64 + chunk * 64;
            float thr = bd[KNNC - 1];
            int cnt = 0;
            for (int m = s0; m < s0 + 64; m++) {
                int mm = base + m;
                float dot = fmaf(qx, sx[mm], fmaf(qy, sy[mm], qz * sz[mm]));
                float d = n1 + sq2[mm] - 2.f * dot;
                if (d < thr) {
                    if (cnt < 32) { fb[cnt] = d; ib[cnt] = mm; cnt++; }
                    else if (d < bd[KNNC - 1]) INSERT_CHAIN(d, mm);
                }
            }
            for (int t = 0; t < cnt; t++) {
                float d = fb[t];
                int mm = ib[t];
                if (d < bd[KNNC - 1]) INSERT_CHAIN(d, mm);
            }
        }
    }
#pragma unroll
    for (int j = 0; j < KNNC; j++) { smd[tid][j] = bd[j]; smi[tid][j] = bi[j]; }
    __syncthreads();
    if (quarter == 0) {
        int head[4] = {0, 0, 0, 0};
#pragma unroll
        for (int t = 0; t < KNNC; t++) {
            float best = 3.5e38f;
            int bqv = 0;
#pragma unroll
            for (int qu = 0; qu < 4; qu++) {
                if (head[qu] < KNNC) {
                    float v = smd[qu * 128 + q][head[qu]];
                    if (v < best) { best = v; bqv = qu; }
                }
            }
            g_idx[(b * NPTS + n) * KNNC + t] = smi[bqv * 128 + q][head[bqv]];
            head[bqv]++;
        }
    }
}

// ================= fused attention kernel =================
__global__ __launch_bounds__(256, 3) void attn_kernel(
    const float* __restrict__ pos1, const float* __restrict__ pos2,
    const float* __restrict__ query,
    const float* __restrict__ pw1, const float* __restrict__ pb1,
    const float* __restrict__ pg,  const float* __restrict__ pbt,
    const float* __restrict__ pm,  const float* __restrict__ pv,
    const float* __restrict__ pb2,
    const float* __restrict__ abt,
    const float* __restrict__ we,  const float* __restrict__ be,
    float* __restrict__ out)
{
    int b = blockIdx.y;
    int n0 = blockIdx.x * PPB;
    int tid = threadIdx.x;

    __shared__ __align__(16) float s_h[PPB * DIMC * KNNC];     // qk_rel fp32 (10 KB)
    __shared__ __align__(16) float s_vg[PPB * DIMC * KNNC];    // 10 KB
    // overlay: s_pe1bf (13.8 KB, phases 1-1b) then s_abf (25.3 KB, phases 2-3)
    __shared__ __align__(16) unsigned char s_big[PPB * 24 * ABF_STRIDE * 2];
    __shared__ __align__(16) __nv_bfloat16 s_hbf[PPB * 2 * 24 * HBF_STRIDE]; // 13.8 KB
    __shared__ float s_q[PPB * DIMC];
    __shared__ float s_prel[PPB * 3 * KNNC];
    __shared__ float s_agg[PPB * DIMC * UPF];
    __shared__ int   s_idx[PPB * KNNC];

    __nv_bfloat16* s_pe1bf = reinterpret_cast<__nv_bfloat16*>(s_big); // [(p*2+plane)*24+k][h]
    __nv_bfloat16* s_abf = reinterpret_cast<__nv_bfloat16*>(s_big);   // [p*24+n][c]

    // ---- Phase 0 ----
    if (tid < PPB * KNNC) {
        int p = tid / KNNC, k = tid - p * KNNC;
        s_idx[tid] = g_idx[(b * NPTS + n0 + p) * KNNC + k];
    }
    if (tid < PPB * DIMC) {
        int p = tid >> 6, o = tid & 63;
        s_q[tid] = g_qt[(b * NPTS + n0 + p) * DIMC + o];
    }
    // zero padded neighbor rows (20..23) of s_hbf
    {
        unsigned* hz = reinterpret_cast<unsigned*>(s_hbf);
        for (int e = tid; e < PPB * 2 * 4 * (HBF_STRIDE / 2); e += 256) {
            int woff = e % (HBF_STRIDE / 2);
            int rsel = e / (HBF_STRIDE / 2);
            int r = rsel & 3, pl = (rsel >> 2) & 1, p = rsel >> 3;
            hz[((p * 2 + pl) * 24 + 20 + r) * (HBF_STRIDE / 2) + woff] = 0u;
        }
    }
    __syncthreads();
    if (tid < PPB * 3 * KNNC) {
        int p = tid / (3 * KNNC), rem = tid - p * 3 * KNNC;
        int c = rem / KNNC, k = rem - c * KNNC;
        s_prel[tid] = pos1[(b * 3 + c) * NPTS + n0 + p]
                    - pos2[(b * 3 + c) * NPTS2 + s_idx[p * KNNC + k]];
    }
#pragma unroll
    for (int p = 0; p < PPB; p++) {
        for (int e = tid; e < DIMC * KNNC; e += 256) {
            int k = e >> 6, o = e & 63;
            int m = s_idx[p * KNNC + k];
            s_h[p * DIMC * KNNC + o * KNNC + k]  = s_q[p * DIMC + o] - g_kt[(b * NPTS2 + m) * DIMC + o];
            s_vg[p * DIMC * KNNC + o * KNNC + k] = g_vt[(b * NPTS2 + m) * DIMC + o];
        }
    }
    __syncthreads();

    // ---- Phase 1: pe1 = relu(bn(pw1 @ prel)) -> s_pe1bf bf16 hi/lo [k][h], both points ----
    for (int e = tid; e < PPB * 24 * 32; e += 256) {
        int hp = e & 31;          // h-pair -> h = 2hp, 2hp+1
        int rem = e >> 5;
        int k = rem % 24, p = rem / 24;
        float v0 = 0.f, v1 = 0.f;
        if (k < KNNC) {
            const float* pr = s_prel + p * 3 * KNNC;
            float x = pr[k], y = pr[KNNC + k], z = pr[2 * KNNC + k];
#pragma unroll
            for (int hh = 0; hh < 2; hh++) {
                int h = 2 * hp + hh;
                float acc = fmaf(pw1[h * 3 + 0], x,
                            fmaf(pw1[h * 3 + 1], y,
                                 pw1[h * 3 + 2] * z)) + pb1[h];
                float inv = pg[h] * rsqrtf(pv[h] + EPSV);
                acc = fmaf(acc, inv, pbt[h] - pm[h] * inv);
                acc = fmaxf(acc, 0.f);
                if (hh == 0) v0 = acc; else v1 = acc;
            }
        }
        float v0hi = __bfloat162float(__float2bfloat16_rn(v0));
        float v1hi = __bfloat162float(__float2bfloat16_rn(v1));
        unsigned* w0 = reinterpret_cast<unsigned*>(s_pe1bf);
        w0[((p * 2 + 0) * 24 + k) * (HBF_STRIDE / 2) + hp] = bfpack(v0, v1);
        w0[((p * 2 + 1) * 24 + k) * (HBF_STRIDE / 2) + hp] = bfpack(v0 - v0hi, v1 - v1hi);
    }
    __syncthreads();

    // ---- Phase 1b: pe = pw2 @ pe1 via mma; fold into s_hbf (hi/lo) and s_vg ----
    int w = tid >> 5, lane = tid & 31;
    int gr = lane >> 2, gc = lane & 3;
    {
        int p1 = w >> 2, mt = w & 3;
        float Cpe[3][4];
#pragma unroll
        for (int nt = 0; nt < 3; nt++)
#pragma unroll
            for (int r = 0; r < 4; r++) Cpe[nt][r] = 0.f;
        const uint4* PW = reinterpret_cast<const uint4*>(g_pwfrag);
#pragma unroll
        for (int ks = 0; ks < 4; ks++) {
            uint4 Ah = PW[((0 * 4 + mt) * 4 + ks) * 32 + lane];
            uint4 Al = PW[((1 * 4 + mt) * 4 + ks) * 32 + lane];
#pragma unroll
            for (int nt = 0; nt < 3; nt++) {
                const __nv_bfloat16* bh =
                    s_pe1bf + ((p1 * 2 + 0) * 24 + nt * 8 + gr) * HBF_STRIDE + ks * 16 + 2 * gc;
                const __nv_bfloat16* bl =
                    s_pe1bf + ((p1 * 2 + 1) * 24 + nt * 8 + gr) * HBF_STRIDE + ks * 16 + 2 * gc;
                unsigned bh0 = *reinterpret_cast<const unsigned*>(bh);
                unsigned bh1 = *reinterpret_cast<const unsigned*>(bh + 8);
                unsigned bl0 = *reinterpret_cast<const unsigned*>(bl);
                unsigned bl1 = *reinterpret_cast<const unsigned*>(bl + 8);
                mma16816(Cpe[nt], Ah, bh0, bh1);
                mma16816(Cpe[nt], Ah, bl0, bl1);
                mma16816(Cpe[nt], Al, bh0, bh1);
            }
        }
        // epilogue: h = qk_rel + pe -> s_hbf hi/lo; vg += pe
#pragma unroll
        for (int nt = 0; nt < 3; nt++) {
#pragma unroll
            for (int i = 0; i < 2; i++) {
#pragma unroll
                for (int j = 0; j < 2; j++) {
                    int row = mt * 16 + gr + i * 8;
                    int nb = nt * 8 + 2 * gc + j;
                    if (nb < KNNC) {
                        float val = Cpe[nt][i * 2 + j] + pb2[row];
                        int off = p1 * DIMC * KNNC + row * KNNC + nb;
                        float hv = s_h[off] + val;
                        s_vg[off] += val;
                        float hhi = __bfloat162float(__float2bfloat16_rn(hv));
                        s_hbf[((p1 * 2 + 0) * 24 + nb) * HBF_STRIDE + row] = __float2bfloat16_rn(hv);
                        s_hbf[((p1 * 2 + 1) * 24 + nb) * HBF_STRIDE + row] = __float2bfloat16_rn(hv - hhi);
                    }
                }
            }
        }
    }
    __syncthreads();

    // ---- Phase 2: GEMM1 (3-term mma) both points -> s_abf single bf16 plane ----
    const uint4* W1 = reinterpret_cast<const uint4*>(g_w1frag);
    const uint4* Ahi_p = reinterpret_cast<const uint4*>(g_w2frag) + ((0 * 8 + w) * 16) * 32;
    const uint4* Alo_p = reinterpret_cast<const uint4*>(g_w2frag) + ((1 * 8 + w) * 16) * 32;

#pragma unroll
    for (int p = 0; p < PPB; p++) {
        float C2[2][3][4];
#pragma unroll
        for (int mi = 0; mi < 2; mi++)
#pragma unroll
            for (int nt = 0; nt < 3; nt++)
#pragma unroll
                for (int r = 0; r < 4; r++) C2[mi][nt][r] = 0.f;

#pragma unroll
        for (int ks = 0; ks < 4; ks++) {
            unsigned bh0[3], bh1[3], bl0[3], bl1[3];
#pragma unroll
            for (int nt = 0; nt < 3; nt++) {
                const __nv_bfloat16* bh =
                    s_hbf + ((p * 2 + 0) * 24 + nt * 8 + gr) * HBF_STRIDE + ks * 16 + 2 * gc;
                const __nv_bfloat16* bl =
                    s_hbf + ((p * 2 + 1) * 24 + nt * 8 + gr) * HBF_STRIDE + ks * 16 + 2 * gc;
                bh0[nt] = *reinterpret_cast<const unsigned*>(bh);
                bh1[nt] = *reinterpret_cast<const unsigned*>(bh + 8);
                bl0[nt] = *reinterpret_cast<const unsigned*>(bl);
                bl1[nt] = *reinterpret_cast<const unsigned*>(bl + 8);
            }
#pragma unroll
            for (int mi = 0; mi < 2; mi++) {
                int mt = w * 2 + mi;
                uint4 Ah = W1[((0 * 16 + mt) * 4 + ks) * 32 + lane];
                uint4 Al = W1[((1 * 16 + mt) * 4 + ks) * 32 + lane];
#pragma unroll
                for (int nt = 0; nt < 3; nt++) {
                    mma16816(C2[mi][nt], Ah, bh0[nt], bh1[nt]);
                    mma16816(C2[mi][nt], Ah, bl0[nt], bl1[nt]);
                    mma16816(C2[mi][nt], Al, bh0[nt], bh1[nt]);
                }
            }
        }
        if (p == 0) __syncthreads();   // pe1bf reads done before s_abf overwrite (same smem)
#pragma unroll
        for (int mi = 0; mi < 2; mi++) {
#pragma unroll
            for (int i = 0; i < 2; i++) {
                int row = (w * 2 + mi) * 16 + gr + i * 8;
                float inv = g_c1inv[row], bias = g_c1bias[row];
#pragma unroll
                for (int nt = 0; nt < 3; nt++) {
#pragma unroll
                    for (int j = 0; j < 2; j++) {
                        float x = fmaxf(fmaf(C2[mi][nt][i * 2 + j], inv, bias), 0.f);
                        int nn = nt * 8 + 2 * gc + j;
                        s_abf[(p * 24 + nn) * ABF_STRIDE + row] = __float2bfloat16_rn(x);
                    }
                }
            }
        }
    }
    __syncthreads();

    // ---- Phase 3: GEMM2 (2-term), ks-outer to reuse A-frags ----
    float C3[PPB][3][4];
#pragma unroll
    for (int p = 0; p < PPB; p++)
#pragma unroll
        for (int nt = 0; nt < 3; nt++)
#pragma unroll
            for (int r = 0; r < 4; r++) C3[p][nt][r] = 0.f;

#pragma unroll 4
    for (int ks = 0; ks < 16; ks++) {
        uint4 Ah = Ahi_p[ks * 32 + lane];
        uint4 Al = Alo_p[ks * 32 + lane];
#pragma unroll
        for (int p = 0; p < PPB; p++) {
#pragma unroll
            for (int nt = 0; nt < 3; nt++) {
                const __nv_bfloat16* bp =
                    s_abf + (p * 24 + nt * 8 + gr) * ABF_STRIDE + ks * 16 + 2 * gc;
                unsigned b0 = *reinterpret_cast<const unsigned*>(bp);
                unsigned b1 = *reinterpret_cast<const unsigned*>(bp + 8);
                mma16816(C3[p][nt], Ah, b0, b1);
                mma16816(C3[p][nt], Al, b0, b1);
            }
        }
    }

    // ---- epilogue: softmax over K per (row, point), aggregate with vg ----
    {
#pragma unroll
        for (int p = 0; p < PPB; p++) {
#pragma unroll
            for (int half = 0; half < 2; half++) {
                int r = w * 16 + gr + half * 8;
                int o = r >> 1;
                float ab = abt[o];
                float vals[6];
                int nvalid = (gc < 2) ? 6 : 4;
#pragma unroll
                for (int nt = 0; nt < 3; nt++)
#pragma unroll
                    for (int j = 0; j < 2; j++)
                        vals[nt * 2 + j] = C3[p][nt][half * 2 + j] + ab;
                float mx = -3.4e38f;
                for (int i = 0; i < nvalid; i++) mx = fmaxf(mx, vals[i]);
                mx = fmaxf(mx, __shfl_xor_sync(0xffffffffu, mx, 1));
                mx = fmaxf(mx, __shfl_xor_sync(0xffffffffu, mx, 2));
                const float* vgr = s_vg + p * DIMC * KNNC + o * KNNC;
                float s = 0.f, ws = 0.f;
                for (int i = 0; i < nvalid; i++) {
                    int nt = i >> 1, j = i & 1;
                    int nb = nt * 8 + 2 * gc + j;
                    float e = expf(vals[i] - mx);
                    s += e;
                    ws = fmaf(e, vgr[nb], ws);
                }
                s += __shfl_xor_sync(0xffffffffu, s, 1);
                s += __shfl_xor_sync(0xffffffffu, s, 2);
                ws += __shfl_xor_sync(0xffffffffu, ws, 1);
                ws += __shfl_xor_sync(0xffffffffu, ws, 2);
                if (gc == 0) s_agg[p * 128 + r] = ws / s;
            }
        }
    }
    __syncthreads();

    // ---- Phase 5: y = we @ agg + be + residual ----
    {
        int c2 = tid >> 1, rr = tid & 1;
        float accp[PPB];
#pragma unroll
        for (int pp = 0; pp < PPB; pp++) accp[pp] = 0.f;
        const float4* w4 = reinterpret_cast<const float4*>(we + c2 * DIMC);
#pragma unroll 4
        for (int o4 = 0; o4 < DIMC / 4; o4++) {
            float4 ww = w4[o4];
#pragma unroll
            for (int j = 0; j < 4; j++) {
                float wj = (j == 0) ? ww.x : (j == 1) ? ww.y : (j == 2) ? ww.z : ww.w;
                int o = o4 * 4 + j;
#pragma unroll
                for (int pp = 0; pp < PPB; pp++)
                    accp[pp] = fmaf(wj, s_agg[pp * 128 + o * UPF + rr], accp[pp]);
            }
        }
        float bb = be[c2];
#pragma unroll
        for (int pp = 0; pp < PPB; pp++) {
            out[((size_t)(b * CINC + c2)) * (NPTS * UPF) + 2 * (size_t)(n0 + pp) + rr] =
                accp[pp] + bb + query[(b * CINC + c2) * NPTS + n0 + pp];
        }
    }
}

// ================= launch =================
extern "C" void kernel_launch(void* const* d_in, const int* in_sizes, int n_in,
                              void* d_out, int out_size)
{
    const float* pos1     = (const float*)d_in[0];
    const float* query    = (const float*)d_in[1];
    const float* pos2     = (const float*)d_in[2];
    const float* key_feat = (const float*)d_in[3];
    const float* wq  = (const float*)d_in[4];
    const float* bq  = (const float*)d_in[5];
    const float* wk  = (const float*)d_in[6];
    const float* bk  = (const float*)d_in[7];
    const float* wv  = (const float*)d_in[8];
    const float* bv  = (const float*)d_in[9];
    const float* pw1 = (const float*)d_in[10];
    const float* pb1 = (const float*)d_in[11];
    const float* pg  = (const float*)d_in[12];
    const float* pbt = (const float*)d_in[13];
    const float* pm  = (const float*)d_in[14];
    const float* pv  = (const float*)d_in[15];
    const float* pw2 = (const float*)d_in[16];
    const float* pb2 = (const float*)d_in[17];
    const float* aw1 = (const float*)d_in[18];
    const float* ab1 = (const float*)d_in[19];
    const float* ag  = (const float*)d_in[20];
    const float* abt2= (const float*)d_in[21];
    const float* am  = (const float*)d_in[22];
    const float* av  = (const float*)d_in[23];
    const float* awt = (const float*)d_in[24];
    const float* abt = (const float*)d_in[25];
    const float* we  = (const float*)d_in[26];
    const float* be  = (const float*)d_in[27];
    float* out = (float*)d_out;

    prep_kernel<<<128, 256>>>(aw1, pw2, wq, wk, wv, awt, ab1, ag, abt2, am, av);
    qkv_kernel<<<dim3(NPTS / 128, BATCH), 256>>>(query, key_feat, bq, bk, bv);
    knn_kernel<<<dim3(NPTS / 128, BATCH), 512>>>(pos1, pos2);
    attn_kernel<<<dim3(NPTS / PPB, BATCH), 256>>>(
        pos1, pos2, query,
        pw1, pb1, pg, pbt, pm, pv, pb2,
        abt, we, be, out);
}

// round 12
// speedup vs baseline: 3.0686x; 1.0523x over previous
#include <cuda_runtime.h>
#include <cuda_bf16.h>
#include <math.h>
#include <stdint.h>

#define BATCH 4
#define NPTS 4096
#define NPTS2 4096
#define CINC 128
#define DIMC 64
#define KNNC 20
#define UPF 2
#define HPOSC 64
#define HATTC 256
#define EPSV 1e-5f
#define PPB 2
#define ABF_STRIDE 264   // channels stride in s_abf rows
#define HBF_STRIDE 72    // o stride in s_hbf / s_pe1bf rows

// ---------------- scratch ----------------
__device__ float g_qt[BATCH * NPTS * DIMC];
__device__ float g_kt[BATCH * NPTS2 * DIMC];
__device__ float g_vt[BATCH * NPTS2 * DIMC];
__device__ int   g_idx[BATCH * NPTS * KNNC];
__device__ float g_wqt[CINC * DIMC];
__device__ float g_wkt[CINC * DIMC];
__device__ float g_wvt[CINC * DIMC];
// W2 (= awt^T, [128 rows][256 c]) A-fragments: (((plane*8 + mt)*16 + ks)*32 + lane)*4 + reg
__device__ unsigned g_w2frag[2 * 8 * 16 * 32 * 4];
// W1 (= aw1, [256 rows][64 o]) A-fragments: (((plane*16 + mt)*4 + ks)*32 + lane)*4 + reg
__device__ unsigned g_w1frag[2 * 16 * 4 * 32 * 4];
// PW2 ([64 rows o][64 cols h]) A-fragments: (((plane*4 + mt)*4 + ks)*32 + lane)*4 + reg
__device__ unsigned g_pwfrag[2 * 4 * 4 * 32 * 4];
__device__ float g_c1inv[HATTC];
__device__ float g_c1bias[HATTC];

// ---------------- f32x2 helpers ----------------
__device__ __forceinline__ unsigned long long ffma2(
    unsigned long long a, unsigned long long b, unsigned long long c) {
    unsigned long long d;
    asm("fma.rn.f32x2 %0, %1, %2, %3;" : "=l"(d) : "l"(a), "l"(b), "l"(c));
    return d;
}
__device__ __forceinline__ unsigned long long pack2(float lo, float hi) {
    unsigned long long d;
    asm("mov.b64 %0, {%1, %2};" : "=l"(d) : "f"(lo), "f"(hi));
    return d;
}
__device__ __forceinline__ void unpack2(unsigned long long v, float& lo, float& hi) {
    asm("mov.b64 {%0, %1}, %2;" : "=f"(lo), "=f"(hi) : "l"(v));
}

// ---------------- mma.sync helper ----------------
__device__ __forceinline__ void mma16816(float* c, const uint4& a, unsigned b0, unsigned b1) {
    asm volatile(
        "mma.sync.aligned.m16n8k16.row.col.f32.bf16.bf16.f32 "
        "{%0,%1,%2,%3}, {%4,%5,%6,%7}, {%8,%9}, {%0,%1,%2,%3};"
        : "+f"(c[0]), "+f"(c[1]), "+f"(c[2]), "+f"(c[3])
        : "r"(a.x), "r"(a.y), "r"(a.z), "r"(a.w), "r"(b0), "r"(b1));
}
__device__ __forceinline__ unsigned bfpack(float x0, float x1) {
    return (unsigned)__bfloat16_as_ushort(__float2bfloat16_rn(x0)) |
           ((unsigned)__bfloat16_as_ushort(__float2bfloat16_rn(x1)) << 16);
}

// ================= prep =================
__global__ __launch_bounds__(256) void prep_kernel(
    const float* __restrict__ aw1, const float* __restrict__ pw2,
    const float* __restrict__ wq, const float* __restrict__ wk,
    const float* __restrict__ wv, const float* __restrict__ awt,
    const float* __restrict__ ab1, const float* __restrict__ ag,
    const float* __restrict__ abt2, const float* __restrict__ am,
    const float* __restrict__ av)
{
    int i = blockIdx.x * 256 + threadIdx.x;
    if (i < DIMC * CINC) {
        int o = i >> 7, c = i & 127;
        g_wqt[c * DIMC + o] = wq[i];
        g_wkt[c * DIMC + o] = wk[i];
        g_wvt[c * DIMC + o] = wv[i];
    }
    if (i < HATTC) {
        float inv = ag[i] * rsqrtf(av[i] + EPSV);
        g_c1inv[i] = inv;
        g_c1bias[i] = fmaf(ab1[i], inv, abt2[i]) - am[i] * inv;
    }
    if (i < 32768) {                       // W2 A-fragments
        int reg = i & 3, lane = (i >> 2) & 31, ks = (i >> 7) & 15;
        int mt = (i >> 11) & 7, plane = (i >> 14) & 1;
        int gr = lane >> 2, gc = lane & 3;
        int row = mt * 16 + gr + (reg & 1) * 8;
        int col = ks * 16 + 2 * gc + ((reg >> 1) & 1) * 8;
        float x0 = awt[col * 128 + row];
        float x1 = awt[(col + 1) * 128 + row];
        unsigned v;
        if (plane == 0) v = bfpack(x0, x1);
        else {
            float h0 = __bfloat162float(__float2bfloat16_rn(x0));
            float h1 = __bfloat162float(__float2bfloat16_rn(x1));
            v = bfpack(x0 - h0, x1 - h1);
        }
        g_w2frag[i] = v;
    }
    if (i < 16384) {                       // W1 A-fragments
        int reg = i & 3, lane = (i >> 2) & 31, ks = (i >> 7) & 3;
        int mt = (i >> 9) & 15, plane = (i >> 13) & 1;
        int gr = lane >> 2, gc = lane & 3;
        int row = mt * 16 + gr + (reg & 1) * 8;
        int col = ks * 16 + 2 * gc + ((reg >> 1) & 1) * 8;
        float x0 = aw1[row * DIMC + col];
        float x1 = aw1[row * DIMC + col + 1];
        unsigned v;
        if (plane == 0) v = bfpack(x0, x1);
        else {
            float h0 = __bfloat162float(__float2bfloat16_rn(x0));
            float h1 = __bfloat162float(__float2bfloat16_rn(x1));
            v = bfpack(x0 - h0, x1 - h1);
        }
        g_w1frag[i] = v;
    }
    if (i < 4096) {                        // PW2 A-fragments
        int reg = i & 3, lane = (i >> 2) & 31, ks = (i >> 7) & 3;
        int mt = (i >> 9) & 3, plane = (i >> 11) & 1;
        int gr = lane >> 2, gc = lane & 3;
        int row = mt * 16 + gr + (reg & 1) * 8;
        int col = ks * 16 + 2 * gc + ((reg >> 1) & 1) * 8;
        float x0 = pw2[row * HPOSC + col];
        float x1 = pw2[row * HPOSC + col + 1];
        unsigned v;
        if (plane == 0) v = bfpack(x0, x1);
        else {
            float h0 = __bfloat162float(__float2bfloat16_rn(x0));
            float h1 = __bfloat162float(__float2bfloat16_rn(x1));
            v = bfpack(x0 - h0, x1 - h1);
        }
        g_pwfrag[i] = v;
    }
}

// ================= QKV =================
__global__ __launch_bounds__(256) void qkv_kernel(
    const float* __restrict__ query, const float* __restrict__ key_feat,
    const float* __restrict__ bq, const float* __restrict__ bk, const float* __restrict__ bv)
{
    int b = blockIdx.y;
    int n0 = blockIdx.x * 128;
    int tid = threadIdx.x;
    __shared__ __align__(16) float tile[CINC * 128];
    int o = tid & 63, jb = tid >> 6;

    for (int i = tid; i < CINC * 128; i += 256) {
        int c = i >> 7, j = i & 127;
        tile[i] = query[(b * CINC + c) * NPTS + n0 + j];
    }
    __syncthreads();
    {
        unsigned long long acc[16];
#pragma unroll
        for (int m = 0; m < 16; m++) acc[m] = 0ULL;
#pragma unroll 4
        for (int c = 0; c < CINC; c++) {
            float w = g_wqt[c * DIMC + o];
            unsigned long long wp = pack2(w, w);
            const ulonglong2* tp = reinterpret_cast<const ulonglong2*>(tile + c * 128 + jb * 32);
#pragma unroll
            for (int jj = 0; jj < 8; jj++) {
                ulonglong2 t = tp[jj];
                acc[2 * jj]     = ffma2(wp, t.x, acc[2 * jj]);
                acc[2 * jj + 1] = ffma2(wp, t.y, acc[2 * jj + 1]);
            }
        }
        float bias = bq[o];
#pragma unroll
        for (int m = 0; m < 16; m++) {
            float lo, hi;
            unpack2(acc[m], lo, hi);
            int j = jb * 32 + 2 * m;
            g_qt[(b * NPTS + n0 + j) * DIMC + o]     = lo + bias;
            g_qt[(b * NPTS + n0 + j + 1) * DIMC + o] = hi + bias;
        }
    }
    __syncthreads();
    for (int i = tid; i < CINC * 128; i += 256) {
        int c = i >> 7, j = i & 127;
        tile[i] = key_feat[(b * CINC + c) * NPTS2 + n0 + j];
    }
    __syncthreads();
#pragma unroll
    for (int which = 0; which < 2; which++) {
        const float* wt = which ? g_wvt : g_wkt;
        float* gout = which ? g_vt : g_kt;
        float bias = which ? bv[o] : bk[o];
        unsigned long long acc[16];
#pragma unroll
        for (int m = 0; m < 16; m++) acc[m] = 0ULL;
#pragma unroll 4
        for (int c = 0; c < CINC; c++) {
            float w = wt[c * DIMC + o];
            unsigned long long wp = pack2(w, w);
            const ulonglong2* tp = reinterpret_cast<const ulonglong2*>(tile + c * 128 + jb * 32);
#pragma unroll
            for (int jj = 0; jj < 8; jj++) {
                ulonglong2 t = tp[jj];
                acc[2 * jj]     = ffma2(wp, t.x, acc[2 * jj]);
                acc[2 * jj + 1] = ffma2(wp, t.y, acc[2 * jj + 1]);
            }
        }
#pragma unroll
        for (int m = 0; m < 16; m++) {
            float lo, hi;
            unpack2(acc[m], lo, hi);
            int j = jb * 32 + 2 * m;
            gout[(b * NPTS2 + n0 + j) * DIMC + o]     = lo + bias;
            gout[(b * NPTS2 + n0 + j + 1) * DIMC + o] = hi + bias;
        }
    }
}

// ================= KNN =================
#define INSERT_CHAIN(d_, i_) do { \
    float cd = (d_); int ci = (i_); \
    _Pragma("unroll") \
    for (int j = 0; j < KNNC; j++) { \
        if (cd < bd[j]) { \
            float td = bd[j]; bd[j] = cd; cd = td; \
            int ti = bi[j]; bi[j] = ci; ci = ti; \
        } \
    } \
} while (0)

__global__ __launch_bounds__(512) void knn_kernel(
    const float* __restrict__ pos1, const float* __restrict__ pos2)
{
    int b = blockIdx.y;
    int tid = threadIdx.x;
    int q = tid & 127, quarter = tid >> 7;
    int n = blockIdx.x * 128 + q;

    __shared__ float sx[4096], sy[4096], sz[4096], sq2[4096];
    __shared__ float smd[512][KNNC];
    __shared__ int   smi[512][KNNC];

    for (int i = tid; i < 4096; i += 512) {
        float x = pos2[(b * 3 + 0) * NPTS2 + i];
        float y = pos2[(b * 3 + 1) * NPTS2 + i];
        float z = pos2[(b * 3 + 2) * NPTS2 + i];
        sx[i] = x; sy[i] = y; sz[i] = z;
        sq2[i] = x * x + y * y + z * z;
    }
    float qx = pos1[(b * 3 + 0) * NPTS + n];
    float qy = pos1[(b * 3 + 1) * NPTS + n];
    float qz = pos1[(b * 3 + 2) * NPTS + n];
    float n1 = qx * qx + qy * qy + qz * qz;

    float bd[KNNC];
    int bi[KNNC];
#pragma unroll
    for (int j = 0; j < KNNC; j++) { bd[j] = 3.4e38f; bi[j] = 0; }
    __syncthreads();
    int base = quarter * 1024;

    for (int m = 0; m < 64; m++) {
        int mm = base + m;
        float dot = fmaf(qx, sx[mm], fmaf(qy, sy[mm], qz * sz[mm]));
        float d = n1 + sq2[mm] - 2.f * dot;
        if (d < bd[KNNC - 1]) INSERT_CHAIN(d, mm);
    }
    {
        float fb[32];
        int ib[32];
        for (int chunk = 0; chunk < 15; chunk++) {
            int s0 = 64 + chunk * 64;
            float thr = bd[KNNC - 1];
            int cnt = 0;
            for (int m = s0; m < s0 + 64; m++) {
                int mm = base + m;
                float dot = fmaf(qx, sx[mm], fmaf(qy, sy[mm], qz * sz[mm]));
                float d = n1 + sq2[mm] - 2.f * dot;
                if (d < thr) {
                    if (cnt < 32) { fb[cnt] = d; ib[cnt] = mm; cnt++; }
                    else if (d < bd[KNNC - 1]) INSERT_CHAIN(d, mm);
                }
            }
            for (int t = 0; t < cnt; t++) {
                float d = fb[t];
                int mm = ib[t];
                if (d < bd[KNNC - 1]) INSERT_CHAIN(d, mm);
            }
        }
    }
#pragma unroll
    for (int j = 0; j < KNNC; j++) { smd[tid][j] = bd[j]; smi[tid][j] = bi[j]; }
    __syncthreads();
    if (quarter == 0) {
        int head[4] = {0, 0, 0, 0};
#pragma unroll
        for (int t = 0; t < KNNC; t++) {
            float best = 3.5e38f;
            int bqv = 0;
#pragma unroll
            for (int qu = 0; qu < 4; qu++) {
                if (head[qu] < KNNC) {
                    float v = smd[qu * 128 + q][head[qu]];
                    if (v < best) { best = v; bqv = qu; }
                }
            }
            g_idx[(b * NPTS + n) * KNNC + t] = smi[bqv * 128 + q][head[bqv]];
            head[bqv]++;
        }
    }
}

// ================= fused attention kernel =================
__global__ __launch_bounds__(256, 4) void attn_kernel(
    const float* __restrict__ pos1, const float* __restrict__ pos2,
    const float* __restrict__ query,
    const float* __restrict__ pw1, const float* __restrict__ pb1,
    const float* __restrict__ pg,  const float* __restrict__ pbt,
    const float* __restrict__ pm,  const float* __restrict__ pv,
    const float* __restrict__ pb2,
    const float* __restrict__ abt,
    const float* __restrict__ we,  const float* __restrict__ be,
    float* __restrict__ out)
{
    int b = blockIdx.y;
    int n0 = blockIdx.x * PPB;
    int tid = threadIdx.x;

    __shared__ __align__(16) float s_h[PPB * DIMC * KNNC];     // qk_rel fp32 (10 KB)
    __shared__ __align__(16) float s_vg[PPB * DIMC * KNNC];    // 10 KB
    // overlay: s_pe1bf (6.9 KB, phases 1-1b) then s_abf (25.3 KB, phases 2-3)
    __shared__ __align__(16) unsigned char s_big[PPB * 24 * ABF_STRIDE * 2];
    __shared__ __align__(16) __nv_bfloat16 s_hbf[PPB * 24 * HBF_STRIDE]; // 6.9 KB single plane
    __shared__ float s_q[PPB * DIMC];
    __shared__ float s_prel[PPB * 3 * KNNC];
    __shared__ float s_agg[PPB * DIMC * UPF];
    __shared__ int   s_idx[PPB * KNNC];

    __nv_bfloat16* s_pe1bf = reinterpret_cast<__nv_bfloat16*>(s_big); // [p*24+k][h] single plane
    __nv_bfloat16* s_abf = reinterpret_cast<__nv_bfloat16*>(s_big);   // [p*24+n][c]

    // ---- Phase 0 ----
    if (tid < PPB * KNNC) {
        int p = tid / KNNC, k = tid - p * KNNC;
        s_idx[tid] = g_idx[(b * NPTS + n0 + p) * KNNC + k];
    }
    if (tid < PPB * DIMC) {
        int p = tid >> 6, o = tid & 63;
        s_q[tid] = g_qt[(b * NPTS + n0 + p) * DIMC + o];
    }
    // zero padded neighbor rows (20..23) of s_hbf
    {
        unsigned* hz = reinterpret_cast<unsigned*>(s_hbf);
        for (int e = tid; e < PPB * 4 * (HBF_STRIDE / 2); e += 256) {
            int woff = e % (HBF_STRIDE / 2);
            int rsel = e / (HBF_STRIDE / 2);
            int r = rsel & 3, p = rsel >> 2;
            hz[(p * 24 + 20 + r) * (HBF_STRIDE / 2) + woff] = 0u;
        }
    }
    __syncthreads();
    if (tid < PPB * 3 * KNNC) {
        int p = tid / (3 * KNNC), rem = tid - p * 3 * KNNC;
        int c = rem / KNNC, k = rem - c * KNNC;
        s_prel[tid] = pos1[(b * 3 + c) * NPTS + n0 + p]
                    - pos2[(b * 3 + c) * NPTS2 + s_idx[p * KNNC + k]];
    }
#pragma unroll
    for (int p = 0; p < PPB; p++) {
        for (int e = tid; e < DIMC * KNNC; e += 256) {
            int k = e >> 6, o = e & 63;
            int m = s_idx[p * KNNC + k];
            s_h[p * DIMC * KNNC + o * KNNC + k]  = s_q[p * DIMC + o] - g_kt[(b * NPTS2 + m) * DIMC + o];
            s_vg[p * DIMC * KNNC + o * KNNC + k] = g_vt[(b * NPTS2 + m) * DIMC + o];
        }
    }
    __syncthreads();

    // ---- Phase 1: pe1 = relu(bn(pw1 @ prel)) -> s_pe1bf bf16 single plane [k][h] ----
    for (int e = tid; e < PPB * 24 * 32; e += 256) {
        int hp = e & 31;          // h-pair -> h = 2hp, 2hp+1
        int rem = e >> 5;
        int k = rem % 24, p = rem / 24;
        float v0 = 0.f, v1 = 0.f;
        if (k < KNNC) {
            const float* pr = s_prel + p * 3 * KNNC;
            float x = pr[k], y = pr[KNNC + k], z = pr[2 * KNNC + k];
#pragma unroll
            for (int hh = 0; hh < 2; hh++) {
                int h = 2 * hp + hh;
                float acc = fmaf(pw1[h * 3 + 0], x,
                            fmaf(pw1[h * 3 + 1], y,
                                 pw1[h * 3 + 2] * z)) + pb1[h];
                float inv = pg[h] * rsqrtf(pv[h] + EPSV);
                acc = fmaf(acc, inv, pbt[h] - pm[h] * inv);
                acc = fmaxf(acc, 0.f);
                if (hh == 0) v0 = acc; else v1 = acc;
            }
        }
        unsigned* w0 = reinterpret_cast<unsigned*>(s_pe1bf);
        w0[(p * 24 + k) * (HBF_STRIDE / 2) + hp] = bfpack(v0, v1);
    }
    __syncthreads();

    // ---- Phase 1b: pe = pw2 @ pe1 via mma (2-term); fold into s_hbf and s_vg ----
    int w = tid >> 5, lane = tid & 31;
    int gr = lane >> 2, gc = lane & 3;
    {
        int p1 = w >> 2, mt = w & 3;
        float Cpe[3][4];
#pragma unroll
        for (int nt = 0; nt < 3; nt++)
#pragma unroll
            for (int r = 0; r < 4; r++) Cpe[nt][r] = 0.f;
        const uint4* PW = reinterpret_cast<const uint4*>(g_pwfrag);
#pragma unroll
        for (int ks = 0; ks < 4; ks++) {
            uint4 Ah = PW[((0 * 4 + mt) * 4 + ks) * 32 + lane];
            uint4 Al = PW[((1 * 4 + mt) * 4 + ks) * 32 + lane];
#pragma unroll
            for (int nt = 0; nt < 3; nt++) {
                const __nv_bfloat16* bh =
                    s_pe1bf + (p1 * 24 + nt * 8 + gr) * HBF_STRIDE + ks * 16 + 2 * gc;
                unsigned b0 = *reinterpret_cast<const unsigned*>(bh);
                unsigned b1 = *reinterpret_cast<const unsigned*>(bh + 8);
                mma16816(Cpe[nt], Ah, b0, b1);
                mma16816(Cpe[nt], Al, b0, b1);
            }
        }
        // epilogue: h = qk_rel + pe -> s_hbf (single plane); vg += pe
#pragma unroll
        for (int nt = 0; nt < 3; nt++) {
#pragma unroll
            for (int i = 0; i < 2; i++) {
#pragma unroll
                for (int j = 0; j < 2; j++) {
                    int row = mt * 16 + gr + i * 8;
                    int nb = nt * 8 + 2 * gc + j;
                    if (nb < KNNC) {
                        float val = Cpe[nt][i * 2 + j] + pb2[row];
                        int off = p1 * DIMC * KNNC + row * KNNC + nb;
                        float hv = s_h[off] + val;
                        s_vg[off] += val;
                        s_hbf[(p1 * 24 + nb) * HBF_STRIDE + row] = __float2bfloat16_rn(hv);
                    }
                }
            }
        }
    }
    __syncthreads();

    // ---- Phase 2: GEMM1 (2-term mma) both points -> s_abf single bf16 plane ----
    const uint4* W1 = reinterpret_cast<const uint4*>(g_w1frag);
    const uint4* Ahi_p = reinterpret_cast<const uint4*>(g_w2frag) + ((0 * 8 + w) * 16) * 32;
    const uint4* Alo_p = reinterpret_cast<const uint4*>(g_w2frag) + ((1 * 8 + w) * 16) * 32;

#pragma unroll
    for (int p = 0; p < PPB; p++) {
        float C2[2][3][4];
#pragma unroll
        for (int mi = 0; mi < 2; mi++)
#pragma unroll
            for (int nt = 0; nt < 3; nt++)
#pragma unroll
                for (int r = 0; r < 4; r++) C2[mi][nt][r] = 0.f;

#pragma unroll
        for (int ks = 0; ks < 4; ks++) {
            unsigned bh0[3], bh1[3];
#pragma unroll
            for (int nt = 0; nt < 3; nt++) {
                const __nv_bfloat16* bh =
                    s_hbf + (p * 24 + nt * 8 + gr) * HBF_STRIDE + ks * 16 + 2 * gc;
                bh0[nt] = *reinterpret_cast<const unsigned*>(bh);
                bh1[nt] = *reinterpret_cast<const unsigned*>(bh + 8);
            }
#pragma unroll
            for (int mi = 0; mi < 2; mi++) {
                int mt = w * 2 + mi;
                uint4 Ah = W1[((0 * 16 + mt) * 4 + ks) * 32 + lane];
                uint4 Al = W1[((1 * 16 + mt) * 4 + ks) * 32 + lane];
#pragma unroll
                for (int nt = 0; nt < 3; nt++) {
                    mma16816(C2[mi][nt], Ah, bh0[nt], bh1[nt]);
                    mma16816(C2[mi][nt], Al, bh0[nt], bh1[nt]);
                }
            }
        }
        if (p == 0) __syncthreads();   // pe1bf reads done before s_abf overwrite (same smem)
#pragma unroll
        for (int mi = 0; mi < 2; mi++) {
#pragma unroll
            for (int i = 0; i < 2; i++) {
                int row = (w * 2 + mi) * 16 + gr + i * 8;
                float inv = g_c1inv[row], bias = g_c1bias[row];
#pragma unroll
                for (int nt = 0; nt < 3; nt++) {
#pragma unroll
                    for (int j = 0; j < 2; j++) {
                        float x = fmaxf(fmaf(C2[mi][nt][i * 2 + j], inv, bias), 0.f);
                        int nn = nt * 8 + 2 * gc + j;
                        s_abf[(p * 24 + nn) * ABF_STRIDE + row] = __float2bfloat16_rn(x);
                    }
                }
            }
        }
    }
    __syncthreads();

    // ---- Phase 3: GEMM2 (2-term), ks-outer to reuse A-frags ----
    float C3[PPB][3][4];
#pragma unroll
    for (int p = 0; p < PPB; p++)
#pragma unroll
        for (int nt = 0; nt < 3; nt++)
#pragma unroll
            for (int r = 0; r < 4; r++) C3[p][nt][r] = 0.f;

#pragma unroll 4
    for (int ks = 0; ks < 16; ks++) {
        uint4 Ah = Ahi_p[ks * 32 + lane];
        uint4 Al = Alo_p[ks * 32 + lane];
#pragma unroll
        for (int p = 0; p < PPB; p++) {
#pragma unroll
            for (int nt = 0; nt < 3; nt++) {
                const __nv_bfloat16* bp =
                    s_abf + (p * 24 + nt * 8 + gr) * ABF_STRIDE + ks * 16 + 2 * gc;
                unsigned b0 = *reinterpret_cast<const unsigned*>(bp);
                unsigned b1 = *reinterpret_cast<const unsigned*>(bp + 8);
                mma16816(C3[p][nt], Ah, b0, b1);
                mma16816(C3[p][nt], Al, b0, b1);
            }
        }
    }

    // ---- epilogue: softmax over K per (row, point), aggregate with vg ----
    {
#pragma unroll
        for (int p = 0; p < PPB; p++) {
#pragma unroll
            for (int half = 0; half < 2; half++) {
                int r = w * 16 + gr + half * 8;
                int o = r >> 1;
                float ab = abt[o];
                float vals[6];
                int nvalid = (gc < 2) ? 6 : 4;
#pragma unroll
                for (int nt = 0; nt < 3; nt++)
#pragma unroll
                    for (int j = 0; j < 2; j++)
                        vals[nt * 2 + j] = C3[p][nt][half * 2 + j] + ab;
                float mx = -3.4e38f;
                for (int i = 0; i < nvalid; i++) mx = fmaxf(mx, vals[i]);
                mx = fmaxf(mx, __shfl_xor_sync(0xffffffffu, mx, 1));
                mx = fmaxf(mx, __shfl_xor_sync(0xffffffffu, mx, 2));
                const float* vgr = s_vg + p * DIMC * KNNC + o * KNNC;
                float s = 0.f, ws = 0.f;
                for (int i = 0; i < nvalid; i++) {
                    int nt = i >> 1, j = i & 1;
                    int nb = nt * 8 + 2 * gc + j;
                    float e = expf(vals[i] - mx);
                    s += e;
                    ws = fmaf(e, vgr[nb], ws);
                }
                s += __shfl_xor_sync(0xffffffffu, s, 1);
                s += __shfl_xor_sync(0xffffffffu, s, 2);
                ws += __shfl_xor_sync(0xffffffffu, ws, 1);
                ws += __shfl_xor_sync(0xffffffffu, ws, 2);
                if (gc == 0) s_agg[p * 128 + r] = ws / s;
            }
        }
    }
    __syncthreads();

    // ---- Phase 5: y = we @ agg + be + residual ----
    {
        int c2 = tid >> 1, rr = tid & 1;
        float accp[PPB];
#pragma unroll
        for (int pp = 0; pp < PPB; pp++) accp[pp] = 0.f;
        const float4* w4 = reinterpret_cast<const float4*>(we + c2 * DIMC);
#pragma unroll 4
        for (int o4 = 0; o4 < DIMC / 4; o4++) {
            float4 ww = w4[o4];
#pragma unroll
            for (int j = 0; j < 4; j++) {
                float wj = (j == 0) ? ww.x : (j == 1) ? ww.y : (j == 2) ? ww.z : ww.w;
                int o = o4 * 4 + j;
#pragma unroll
                for (int pp = 0; pp < PPB; pp++)
                    accp[pp] = fmaf(wj, s_agg[pp * 128 + o * UPF + rr], accp[pp]);
            }
        }
        float bb = be[c2];
#pragma unroll
        for (int pp = 0; pp < PPB; pp++) {
            out[((size_t)(b * CINC + c2)) * (NPTS * UPF) + 2 * (size_t)(n0 + pp) + rr] =
                accp[pp] + bb + query[(b * CINC + c2) * NPTS + n0 + pp];
        }
    }
}

// ================= launch =================
extern "C" void kernel_launch(void* const* d_in, const int* in_sizes, int n_in,
                              void* d_out, int out_size)
{
    const float* pos1     = (const float*)d_in[0];
    const float* query    = (const float*)d_in[1];
    const float* pos2     = (const float*)d_in[2];
    const float* key_feat = (const float*)d_in[3];
    const float* wq  = (const float*)d_in[4];
    const float* bq  = (const float*)d_in[5];
    const float* wk  = (const float*)d_in[6];
    const float* bk  = (const float*)d_in[7];
    const float* wv  = (const float*)d_in[8];
    const float* bv  = (const float*)d_in[9];
    const float* pw1 = (const float*)d_in[10];
    const float* pb1 = (const float*)d_in[11];
    const float* pg  = (const float*)d_in[12];
    const float* pbt = (const float*)d_in[13];
    const float* pm  = (const float*)d_in[14];
    const float* pv  = (const float*)d_in[15];
    const float* pw2 = (const float*)d_in[16];
    const float* pb2 = (const float*)d_in[17];
    const float* aw1 = (const float*)d_in[18];
    const float* ab1 = (const float*)d_in[19];
    const float* ag  = (const float*)d_in[20];
    const float* abt2= (const float*)d_in[21];
    const float* am  = (const float*)d_in[22];
    const float* av  = (const float*)d_in[23];
    const float* awt = (const float*)d_in[24];
    const float* abt = (const float*)d_in[25];
    const float* we  = (const float*)d_in[26];
    const float* be  = (const float*)d_in[27];
    float* out = (float*)d_out;

    prep_kernel<<<128, 256>>>(aw1, pw2, wq, wk, wv, awt, ab1, ag, abt2, am, av);
    qkv_kernel<<<dim3(NPTS / 128, BATCH), 256>>>(query, key_feat, bq, bk, bv);
    knn_kernel<<<dim3(NPTS / 128, BATCH), 512>>>(pos1, pos2);
    attn_kernel<<<dim3(NPTS / PPB, BATCH), 256>>>(
        pos1, pos2, query,
        pw1, pb1, pg, pbt, pm, pv, pb2,
        abt, we, be, out);
}

// round 13
// speedup vs baseline: 3.1463x; 1.0253x over previous
#include <cuda_runtime.h>
#include <cuda_bf16.h>
#include <math.h>
#include <stdint.h>

#define BATCH 4
#define NPTS 4096
#define NPTS2 4096
#define CINC 128
#define DIMC 64
#define KNNC 20
#define UPF 2
#define HPOSC 64
#define HATTC 256
#define EPSV 1e-5f
#define PPB 2
#define ABF_STRIDE 264   // channels stride in s_abf rows
#define HBF_STRIDE 72    // o stride in s_hbf / s_pe1bf rows

// ---------------- scratch ----------------
__device__ float g_qt[BATCH * NPTS * DIMC];
__device__ float g_kt[BATCH * NPTS2 * DIMC];
__device__ float g_vt[BATCH * NPTS2 * DIMC];
__device__ int   g_idx[BATCH * NPTS * KNNC];
__device__ float g_wqt[CINC * DIMC];
__device__ float g_wkt[CINC * DIMC];
__device__ float g_wvt[CINC * DIMC];
__device__ unsigned g_w2frag[2 * 8 * 16 * 32 * 4];
__device__ unsigned g_w1frag[2 * 16 * 4 * 32 * 4];
__device__ unsigned g_pwfrag[2 * 4 * 4 * 32 * 4];
__device__ float g_c1inv[HATTC];
__device__ float g_c1bias[HATTC];
__device__ float g_pw1s[HPOSC * 3];   // pw1 prescaled by BN inv
__device__ float g_pbias[HPOSC];      // fused BN bias for pos layer 1

// ---------------- f32x2 helpers ----------------
__device__ __forceinline__ unsigned long long ffma2(
    unsigned long long a, unsigned long long b, unsigned long long c) {
    unsigned long long d;
    asm("fma.rn.f32x2 %0, %1, %2, %3;" : "=l"(d) : "l"(a), "l"(b), "l"(c));
    return d;
}
__device__ __forceinline__ unsigned long long pack2(float lo, float hi) {
    unsigned long long d;
    asm("mov.b64 %0, {%1, %2};" : "=l"(d) : "f"(lo), "f"(hi));
    return d;
}
__device__ __forceinline__ void unpack2(unsigned long long v, float& lo, float& hi) {
    asm("mov.b64 {%0, %1}, %2;" : "=f"(lo), "=f"(hi) : "l"(v));
}

// ---------------- mma.sync helper ----------------
__device__ __forceinline__ void mma16816(float* c, const uint4& a, unsigned b0, unsigned b1) {
    asm volatile(
        "mma.sync.aligned.m16n8k16.row.col.f32.bf16.bf16.f32 "
        "{%0,%1,%2,%3}, {%4,%5,%6,%7}, {%8,%9}, {%0,%1,%2,%3};"
        : "+f"(c[0]), "+f"(c[1]), "+f"(c[2]), "+f"(c[3])
        : "r"(a.x), "r"(a.y), "r"(a.z), "r"(a.w), "r"(b0), "r"(b1));
}
__device__ __forceinline__ unsigned bfpack(float x0, float x1) {
    return (unsigned)__bfloat16_as_ushort(__float2bfloat16_rn(x0)) |
           ((unsigned)__bfloat16_as_ushort(__float2bfloat16_rn(x1)) << 16);
}

// ================= prep =================
__global__ __launch_bounds__(256) void prep_kernel(
    const float* __restrict__ aw1, const float* __restrict__ pw2,
    const float* __restrict__ wq, const float* __restrict__ wk,
    const float* __restrict__ wv, const float* __restrict__ awt,
    const float* __restrict__ ab1, const float* __restrict__ ag,
    const float* __restrict__ abt2, const float* __restrict__ am,
    const float* __restrict__ av,
    const float* __restrict__ pw1, const float* __restrict__ pb1,
    const float* __restrict__ pg,  const float* __restrict__ pbt,
    const float* __restrict__ pm,  const float* __restrict__ pv)
{
    int i = blockIdx.x * 256 + threadIdx.x;
    if (i < DIMC * CINC) {
        int o = i >> 7, c = i & 127;
        g_wqt[c * DIMC + o] = wq[i];
        g_wkt[c * DIMC + o] = wk[i];
        g_wvt[c * DIMC + o] = wv[i];
    }
    if (i < HATTC) {
        float inv = ag[i] * rsqrtf(av[i] + EPSV);
        g_c1inv[i] = inv;
        g_c1bias[i] = fmaf(ab1[i], inv, abt2[i]) - am[i] * inv;
    }
    if (i < HPOSC) {
        float inv = pg[i] * rsqrtf(pv[i] + EPSV);
        g_pbias[i] = (pb1[i] - pm[i]) * inv + pbt[i];
        g_pw1s[i * 3 + 0] = pw1[i * 3 + 0] * inv;
        g_pw1s[i * 3 + 1] = pw1[i * 3 + 1] * inv;
        g_pw1s[i * 3 + 2] = pw1[i * 3 + 2] * inv;
    }
    if (i < 32768) {                       // W2 A-fragments
        int reg = i & 3, lane = (i >> 2) & 31, ks = (i >> 7) & 15;
        int mt = (i >> 11) & 7, plane = (i >> 14) & 1;
        int gr = lane >> 2, gc = lane & 3;
        int row = mt * 16 + gr + (reg & 1) * 8;
        int col = ks * 16 + 2 * gc + ((reg >> 1) & 1) * 8;
        float x0 = awt[col * 128 + row];
        float x1 = awt[(col + 1) * 128 + row];
        unsigned v;
        if (plane == 0) v = bfpack(x0, x1);
        else {
            float h0 = __bfloat162float(__float2bfloat16_rn(x0));
            float h1 = __bfloat162float(__float2bfloat16_rn(x1));
            v = bfpack(x0 - h0, x1 - h1);
        }
        g_w2frag[i] = v;
    }
    if (i < 16384) {                       // W1 A-fragments
        int reg = i & 3, lane = (i >> 2) & 31, ks = (i >> 7) & 3;
        int mt = (i >> 9) & 15, plane = (i >> 13) & 1;
        int gr = lane >> 2, gc = lane & 3;
        int row = mt * 16 + gr + (reg & 1) * 8;
        int col = ks * 16 + 2 * gc + ((reg >> 1) & 1) * 8;
        float x0 = aw1[row * DIMC + col];
        float x1 = aw1[row * DIMC + col + 1];
        unsigned v;
        if (plane == 0) v = bfpack(x0, x1);
        else {
            float h0 = __bfloat162float(__float2bfloat16_rn(x0));
            float h1 = __bfloat162float(__float2bfloat16_rn(x1));
            v = bfpack(x0 - h0, x1 - h1);
        }
        g_w1frag[i] = v;
    }
    if (i < 4096) {                        // PW2 A-fragments
        int reg = i & 3, lane = (i >> 2) & 31, ks = (i >> 7) & 3;
        int mt = (i >> 9) & 3, plane = (i >> 11) & 1;
        int gr = lane >> 2, gc = lane & 3;
        int row = mt * 16 + gr + (reg & 1) * 8;
        int col = ks * 16 + 2 * gc + ((reg >> 1) & 1) * 8;
        float x0 = pw2[row * HPOSC + col];
        float x1 = pw2[row * HPOSC + col + 1];
        unsigned v;
        if (plane == 0) v = bfpack(x0, x1);
        else {
            float h0 = __bfloat162float(__float2bfloat16_rn(x0));
            float h1 = __bfloat162float(__float2bfloat16_rn(x1));
            v = bfpack(x0 - h0, x1 - h1);
        }
        g_pwfrag[i] = v;
    }
}

// ================= QKV =================
__global__ __launch_bounds__(256) void qkv_kernel(
    const float* __restrict__ query, const float* __restrict__ key_feat,
    const float* __restrict__ bq, const float* __restrict__ bk, const float* __restrict__ bv)
{
    int b = blockIdx.y;
    int n0 = blockIdx.x * 128;
    int tid = threadIdx.x;
    __shared__ __align__(16) float tile[CINC * 128];
    int o = tid & 63, jb = tid >> 6;

    for (int i = tid; i < CINC * 128; i += 256) {
        int c = i >> 7, j = i & 127;
        tile[i] = query[(b * CINC + c) * NPTS + n0 + j];
    }
    __syncthreads();
    {
        unsigned long long acc[16];
#pragma unroll
        for (int m = 0; m < 16; m++) acc[m] = 0ULL;
#pragma unroll 4
        for (int c = 0; c < CINC; c++) {
            float w = g_wqt[c * DIMC + o];
            unsigned long long wp = pack2(w, w);
            const ulonglong2* tp = reinterpret_cast<const ulonglong2*>(tile + c * 128 + jb * 32);
#pragma unroll
            for (int jj = 0; jj < 8; jj++) {
                ulonglong2 t = tp[jj];
                acc[2 * jj]     = ffma2(wp, t.x, acc[2 * jj]);
                acc[2 * jj + 1] = ffma2(wp, t.y, acc[2 * jj + 1]);
            }
        }
        float bias = bq[o];
#pragma unroll
        for (int m = 0; m < 16; m++) {
            float lo, hi;
            unpack2(acc[m], lo, hi);
            int j = jb * 32 + 2 * m;
            g_qt[(b * NPTS + n0 + j) * DIMC + o]     = lo + bias;
            g_qt[(b * NPTS + n0 + j + 1) * DIMC + o] = hi + bias;
        }
    }
    __syncthreads();
    for (int i = tid; i < CINC * 128; i += 256) {
        int c = i >> 7, j = i & 127;
        tile[i] = key_feat[(b * CINC + c) * NPTS2 + n0 + j];
    }
    __syncthreads();
#pragma unroll
    for (int which = 0; which < 2; which++) {
        const float* wt = which ? g_wvt : g_wkt;
        float* gout = which ? g_vt : g_kt;
        float bias = which ? bv[o] : bk[o];
        unsigned long long acc[16];
#pragma unroll
        for (int m = 0; m < 16; m++) acc[m] = 0ULL;
#pragma unroll 4
        for (int c = 0; c < CINC; c++) {
            float w = wt[c * DIMC + o];
            unsigned long long wp = pack2(w, w);
            const ulonglong2* tp = reinterpret_cast<const ulonglong2*>(tile + c * 128 + jb * 32);
#pragma unroll
            for (int jj = 0; jj < 8; jj++) {
                ulonglong2 t = tp[jj];
                acc[2 * jj]     = ffma2(wp, t.x, acc[2 * jj]);
                acc[2 * jj + 1] = ffma2(wp, t.y, acc[2 * jj + 1]);
            }
        }
#pragma unroll
        for (int m = 0; m < 16; m++) {
            float lo, hi;
            unpack2(acc[m], lo, hi);
            int j = jb * 32 + 2 * m;
            gout[(b * NPTS2 + n0 + j) * DIMC + o]     = lo + bias;
            gout[(b * NPTS2 + n0 + j + 1) * DIMC + o] = hi + bias;
        }
    }
}

// ================= KNN =================
#define INSERT_CHAIN(d_, i_) do { \
    float cd = (d_); int ci = (i_); \
    _Pragma("unroll") \
    for (int j = 0; j < KNNC; j++) { \
        if (cd < bd[j]) { \
            float td = bd[j]; bd[j] = cd; cd = td; \
            int ti = bi[j]; bi[j] = ci; ci = ti; \
        } \
    } \
} while (0)

__global__ __launch_bounds__(512) void knn_kernel(
    const float* __restrict__ pos1, const float* __restrict__ pos2)
{
    int b = blockIdx.y;
    int tid = threadIdx.x;
    int q = tid & 127, quarter = tid >> 7;
    int n = blockIdx.x * 128 + q;

    __shared__ float sx[4096], sy[4096], sz[4096], sq2[4096];  // 64 KB
    __shared__ float smd[512][KNNC];                           // 40 KB
    __shared__ int   smi[512][KNNC];                           // 40 KB
    __shared__ float sbd[512][13];                             // 26 KB (stride 13: conflict-free)
    __shared__ int   sbi[512][13];                             // 26 KB

    for (int i = tid; i < 4096; i += 512) {
        float x = pos2[(b * 3 + 0) * NPTS2 + i];
        float y = pos2[(b * 3 + 1) * NPTS2 + i];
        float z = pos2[(b * 3 + 2) * NPTS2 + i];
        sx[i] = x; sy[i] = y; sz[i] = z;
        sq2[i] = x * x + y * y + z * z;
    }
    float qx = pos1[(b * 3 + 0) * NPTS + n];
    float qy = pos1[(b * 3 + 1) * NPTS + n];
    float qz = pos1[(b * 3 + 2) * NPTS + n];
    float n1 = qx * qx + qy * qy + qz * qz;

    float bd[KNNC];
    int bi[KNNC];
#pragma unroll
    for (int j = 0; j < KNNC; j++) { bd[j] = 3.4e38f; bi[j] = 0; }
    __syncthreads();
    int base = quarter * 1024;

    for (int m = 0; m < 64; m++) {
        int mm = base + m;
        float dot = fmaf(qx, sx[mm], fmaf(qy, sy[mm], qz * sz[mm]));
        float d = n1 + sq2[mm] - 2.f * dot;
        if (d < bd[KNNC - 1]) INSERT_CHAIN(d, mm);
    }
    for (int chunk = 0; chunk < 15; chunk++) {
        int s0 = 64 + chunk * 64;
        float thr = bd[KNNC - 1];
        int cnt = 0;
        for (int m = s0; m < s0 + 64; m++) {
            int mm = base + m;
            float dot = fmaf(qx, sx[mm], fmaf(qy, sy[mm], qz * sz[mm]));
            float d = n1 + sq2[mm] - 2.f * dot;
            if (d < thr) {
                if (cnt < 13) { sbd[tid][cnt] = d; sbi[tid][cnt] = mm; cnt++; }
                else if (d < bd[KNNC - 1]) INSERT_CHAIN(d, mm);
            }
        }
        for (int t = 0; t < cnt; t++) {
            float d = sbd[tid][t];
            int mm = sbi[tid][t];
            if (d < bd[KNNC - 1]) INSERT_CHAIN(d, mm);
        }
    }
#pragma unroll
    for (int j = 0; j < KNNC; j++) { smd[tid][j] = bd[j]; smi[tid][j] = bi[j]; }
    __syncthreads();
    if (quarter == 0) {
        int head[4] = {0, 0, 0, 0};
#pragma unroll
        for (int t = 0; t < KNNC; t++) {
            float best = 3.5e38f;
            int bqv = 0;
#pragma unroll
            for (int qu = 0; qu < 4; qu++) {
                if (head[qu] < KNNC) {
                    float v = smd[qu * 128 + q][head[qu]];
                    if (v < best) { best = v; bqv = qu; }
                }
            }
            g_idx[(b * NPTS + n) * KNNC + t] = smi[bqv * 128 + q][head[bqv]];
            head[bqv]++;
        }
    }
}

// ================= fused attention kernel =================
__global__ __launch_bounds__(256, 4) void attn_kernel(
    const float* __restrict__ pos1, const float* __restrict__ pos2,
    const float* __restrict__ query,
    const float* __restrict__ pb2,
    const float* __restrict__ abt,
    const float* __restrict__ we,  const float* __restrict__ be,
    float* __restrict__ out)
{
    int b = blockIdx.y;
    int n0 = blockIdx.x * PPB;
    int tid = threadIdx.x;

    __shared__ __align__(16) float s_h[PPB * DIMC * KNNC];
    __shared__ __align__(16) float s_vg[PPB * DIMC * KNNC];
    __shared__ __align__(16) unsigned char s_big[PPB * 24 * ABF_STRIDE * 2];
    __shared__ __align__(16) __nv_bfloat16 s_hbf[PPB * 24 * HBF_STRIDE];
    __shared__ float s_q[PPB * DIMC];
    __shared__ float s_prel[PPB * 3 * KNNC];
    __shared__ __align__(16) float s_agg[PPB * DIMC * UPF];   // [p][rr*64+o]
    __shared__ int   s_idx[PPB * KNNC];

    __nv_bfloat16* s_pe1bf = reinterpret_cast<__nv_bfloat16*>(s_big);
    __nv_bfloat16* s_abf = reinterpret_cast<__nv_bfloat16*>(s_big);

    // ---- Phase 0 ----
    if (tid < PPB * KNNC) {
        int p = tid / KNNC, k = tid - p * KNNC;
        s_idx[tid] = g_idx[(b * NPTS + n0 + p) * KNNC + k];
    }
    if (tid < PPB * DIMC) {
        int p = tid >> 6, o = tid & 63;
        s_q[tid] = g_qt[(b * NPTS + n0 + p) * DIMC + o];
    }
    {
        unsigned* hz = reinterpret_cast<unsigned*>(s_hbf);
        for (int e = tid; e < PPB * 4 * (HBF_STRIDE / 2); e += 256) {
            int woff = e % (HBF_STRIDE / 2);
            int rsel = e / (HBF_STRIDE / 2);
            int r = rsel & 3, p = rsel >> 2;
            hz[(p * 24 + 20 + r) * (HBF_STRIDE / 2) + woff] = 0u;
        }
    }
    __syncthreads();
    if (tid < PPB * 3 * KNNC) {
        int p = tid / (3 * KNNC), rem = tid - p * 3 * KNNC;
        int c = rem / KNNC, k = rem - c * KNNC;
        s_prel[tid] = pos1[(b * 3 + c) * NPTS + n0 + p]
                    - pos2[(b * 3 + c) * NPTS2 + s_idx[p * KNNC + k]];
    }
#pragma unroll
    for (int p = 0; p < PPB; p++) {
        for (int e = tid; e < DIMC * KNNC / 4; e += 256) {   // 320 float4 groups
            int k = e >> 4, o4 = e & 15;
            int m = s_idx[p * KNNC + k];
            const float4 kv = *reinterpret_cast<const float4*>(
                g_kt + ((size_t)(b * NPTS2 + m)) * DIMC + o4 * 4);
            const float4 vv = *reinterpret_cast<const float4*>(
                g_vt + ((size_t)(b * NPTS2 + m)) * DIMC + o4 * 4);
            const float4 qv = *reinterpret_cast<const float4*>(s_q + p * DIMC + o4 * 4);
            float* hb = s_h + p * DIMC * KNNC;
            float* vb = s_vg + p * DIMC * KNNC;
            int o = o4 * 4;
            hb[(o + 0) * KNNC + k] = qv.x - kv.x;
            hb[(o + 1) * KNNC + k] = qv.y - kv.y;
            hb[(o + 2) * KNNC + k] = qv.z - kv.z;
            hb[(o + 3) * KNNC + k] = qv.w - kv.w;
            vb[(o + 0) * KNNC + k] = vv.x;
            vb[(o + 1) * KNNC + k] = vv.y;
            vb[(o + 2) * KNNC + k] = vv.z;
            vb[(o + 3) * KNNC + k] = vv.w;
        }
    }
    __syncthreads();

    // ---- Phase 1: pe1 = relu(pw1s @ prel + pbias) -> s_pe1bf bf16 [k][h] ----
    for (int e = tid; e < PPB * 24 * 32; e += 256) {
        int hp = e & 31;
        int rem = e >> 5;
        int k = rem % 24, p = rem / 24;
        float v0 = 0.f, v1 = 0.f;
        if (k < KNNC) {
            const float* pr = s_prel + p * 3 * KNNC;
            float x = pr[k], y = pr[KNNC + k], z = pr[2 * KNNC + k];
            int h0 = 2 * hp, h1 = 2 * hp + 1;
            v0 = fmaxf(fmaf(g_pw1s[h0 * 3], x,
                       fmaf(g_pw1s[h0 * 3 + 1], y,
                       fmaf(g_pw1s[h0 * 3 + 2], z, g_pbias[h0]))), 0.f);
            v1 = fmaxf(fmaf(g_pw1s[h1 * 3], x,
                       fmaf(g_pw1s[h1 * 3 + 1], y,
                       fmaf(g_pw1s[h1 * 3 + 2], z, g_pbias[h1]))), 0.f);
        }
        unsigned* w0 = reinterpret_cast<unsigned*>(s_pe1bf);
        w0[(p * 24 + k) * (HBF_STRIDE / 2) + hp] = bfpack(v0, v1);
    }
    __syncthreads();

    // ---- Phase 1b: pe = pw2 @ pe1 (2-term mma); fold into s_hbf and s_vg ----
    int w = tid >> 5, lane = tid & 31;
    int gr = lane >> 2, gc = lane & 3;
    {
        int p1 = w >> 2, mt = w & 3;
        float Cpe[3][4];
#pragma unroll
        for (int nt = 0; nt < 3; nt++)
#pragma unroll
            for (int r = 0; r < 4; r++) Cpe[nt][r] = 0.f;
        const uint4* PW = reinterpret_cast<const uint4*>(g_pwfrag);
#pragma unroll
        for (int ks = 0; ks < 4; ks++) {
            uint4 Ah = PW[((0 * 4 + mt) * 4 + ks) * 32 + lane];
            uint4 Al = PW[((1 * 4 + mt) * 4 + ks) * 32 + lane];
#pragma unroll
            for (int nt = 0; nt < 3; nt++) {
                const __nv_bfloat16* bh =
                    s_pe1bf + (p1 * 24 + nt * 8 + gr) * HBF_STRIDE + ks * 16 + 2 * gc;
                unsigned b0 = *reinterpret_cast<const unsigned*>(bh);
                unsigned b1 = *reinterpret_cast<const unsigned*>(bh + 8);
                mma16816(Cpe[nt], Ah, b0, b1);
                mma16816(Cpe[nt], Al, b0, b1);
            }
        }
#pragma unroll
        for (int nt = 0; nt < 3; nt++) {
#pragma unroll
            for (int i = 0; i < 2; i++) {
#pragma unroll
                for (int j = 0; j < 2; j++) {
                    int row = mt * 16 + gr + i * 8;
                    int nb = nt * 8 + 2 * gc + j;
                    if (nb < KNNC) {
                        float val = Cpe[nt][i * 2 + j] + pb2[row];
                        int off = p1 * DIMC * KNNC + row * KNNC + nb;
                        float hv = s_h[off] + val;
                        s_vg[off] += val;
                        s_hbf[(p1 * 24 + nb) * HBF_STRIDE + row] = __float2bfloat16_rn(hv);
                    }
                }
            }
        }
    }
    __syncthreads();

    // ---- Phase 2: GEMM1 (2-term mma) both points -> s_abf ----
    const uint4* W1 = reinterpret_cast<const uint4*>(g_w1frag);
    const uint4* Ahi_p = reinterpret_cast<const uint4*>(g_w2frag) + ((0 * 8 + w) * 16) * 32;
    const uint4* Alo_p = reinterpret_cast<const uint4*>(g_w2frag) + ((1 * 8 + w) * 16) * 32;

#pragma unroll
    for (int p = 0; p < PPB; p++) {
        float C2[2][3][4];
#pragma unroll
        for (int mi = 0; mi < 2; mi++)
#pragma unroll
            for (int nt = 0; nt < 3; nt++)
#pragma unroll
                for (int r = 0; r < 4; r++) C2[mi][nt][r] = 0.f;

#pragma unroll
        for (int ks = 0; ks < 4; ks++) {
            unsigned bh0[3], bh1[3];
#pragma unroll
            for (int nt = 0; nt < 3; nt++) {
                const __nv_bfloat16* bh =
                    s_hbf + (p * 24 + nt * 8 + gr) * HBF_STRIDE + ks * 16 + 2 * gc;
                bh0[nt] = *reinterpret_cast<const unsigned*>(bh);
                bh1[nt] = *reinterpret_cast<const unsigned*>(bh + 8);
            }
#pragma unroll
            for (int mi = 0; mi < 2; mi++) {
                int mt = w * 2 + mi;
                uint4 Ah = W1[((0 * 16 + mt) * 4 + ks) * 32 + lane];
                uint4 Al = W1[((1 * 16 + mt) * 4 + ks) * 32 + lane];
#pragma unroll
                for (int nt = 0; nt < 3; nt++) {
                    mma16816(C2[mi][nt], Ah, bh0[nt], bh1[nt]);
                    mma16816(C2[mi][nt], Al, bh0[nt], bh1[nt]);
                }
            }
        }
        if (p == 0) __syncthreads();   // pe1bf reads done before s_abf overwrite
#pragma unroll
        for (int mi = 0; mi < 2; mi++) {
#pragma unroll
            for (int i = 0; i < 2; i++) {
                int row = (w * 2 + mi) * 16 + gr + i * 8;
                float inv = g_c1inv[row], bias = g_c1bias[row];
#pragma unroll
                for (int nt = 0; nt < 3; nt++) {
#pragma unroll
                    for (int j = 0; j < 2; j++) {
                        float x = fmaxf(fmaf(C2[mi][nt][i * 2 + j], inv, bias), 0.f);
                        int nn = nt * 8 + 2 * gc + j;
                        s_abf[(p * 24 + nn) * ABF_STRIDE + row] = __float2bfloat16_rn(x);
                    }
                }
            }
        }
    }
    __syncthreads();

    // ---- Phase 3: GEMM2 (2-term), ks-outer ----
    float C3[PPB][3][4];
#pragma unroll
    for (int p = 0; p < PPB; p++)
#pragma unroll
        for (int nt = 0; nt < 3; nt++)
#pragma unroll
            for (int r = 0; r < 4; r++) C3[p][nt][r] = 0.f;

#pragma unroll 4
    for (int ks = 0; ks < 16; ks++) {
        uint4 Ah = Ahi_p[ks * 32 + lane];
        uint4 Al = Alo_p[ks * 32 + lane];
#pragma unroll
        for (int p = 0; p < PPB; p++) {
#pragma unroll
            for (int nt = 0; nt < 3; nt++) {
                const __nv_bfloat16* bp =
                    s_abf + (p * 24 + nt * 8 + gr) * ABF_STRIDE + ks * 16 + 2 * gc;
                unsigned b0 = *reinterpret_cast<const unsigned*>(bp);
                unsigned b1 = *reinterpret_cast<const unsigned*>(bp + 8);
                mma16816(C3[p][nt], Ah, b0, b1);
                mma16816(C3[p][nt], Al, b0, b1);
            }
        }
    }

    // ---- epilogue: softmax + aggregate ----
    {
#pragma unroll
        for (int p = 0; p < PPB; p++) {
#pragma unroll
            for (int half = 0; half < 2; half++) {
                int r = w * 16 + gr + half * 8;
                int o = r >> 1;
                float ab = abt[o];
                float vals[6];
                int nvalid = (gc < 2) ? 6 : 4;
#pragma unroll
                for (int nt = 0; nt < 3; nt++)
#pragma unroll
                    for (int j = 0; j < 2; j++)
                        vals[nt * 2 + j] = C3[p][nt][half * 2 + j] + ab;
                float mx = -3.4e38f;
                for (int i = 0; i < nvalid; i++) mx = fmaxf(mx, vals[i]);
                mx = fmaxf(mx, __shfl_xor_sync(0xffffffffu, mx, 1));
                mx = fmaxf(mx, __shfl_xor_sync(0xffffffffu, mx, 2));
                const float* vgr = s_vg + p * DIMC * KNNC + o * KNNC;
                float s = 0.f, ws = 0.f;
                for (int i = 0; i < nvalid; i++) {
                    int nt = i >> 1, j = i & 1;
                    int nb = nt * 8 + 2 * gc + j;
                    float e = __expf(vals[i] - mx);
                    s += e;
                    ws = fmaf(e, vgr[nb], ws);
                }
                s += __shfl_xor_sync(0xffffffffu, s, 1);
                s += __shfl_xor_sync(0xffffffffu, s, 2);
                ws += __shfl_xor_sync(0xffffffffu, ws, 1);
                ws += __shfl_xor_sync(0xffffffffu, ws, 2);
                if (gc == 0) s_agg[p * 128 + (r & 1) * 64 + (r >> 1)] = ws / s;
            }
        }
    }
    __syncthreads();

    // ---- Phase 5: y = we @ agg + be + residual (float4 LDS on s_agg) ----
    {
        int c2 = tid >> 1, rr = tid & 1;
        float accp[PPB];
#pragma unroll
        for (int pp = 0; pp < PPB; pp++) accp[pp] = 0.f;
        const float4* w4 = reinterpret_cast<const float4*>(we + c2 * DIMC);
#pragma unroll 4
        for (int o4 = 0; o4 < DIMC / 4; o4++) {
            float4 ww = w4[o4];
#pragma unroll
            for (int pp = 0; pp < PPB; pp++) {
                const float4 av = *reinterpret_cast<const float4*>(
                    s_agg + pp * 128 + rr * 64 + o4 * 4);
                accp[pp] = fmaf(ww.x, av.x,
                           fmaf(ww.y, av.y,
                           fmaf(ww.z, av.z,
                           fmaf(ww.w, av.w, accp[pp]))));
            }
        }
        float bb = be[c2];
#pragma unroll
        for (int pp = 0; pp < PPB; pp++) {
            out[((size_t)(b * CINC + c2)) * (NPTS * UPF) + 2 * (size_t)(n0 + pp) + rr] =
                accp[pp] + bb + query[(b * CINC + c2) * NPTS + n0 + pp];
        }
    }
}

// ================= launch =================
extern "C" void kernel_launch(void* const* d_in, const int* in_sizes, int n_in,
                              void* d_out, int out_size)
{
    const float* pos1     = (const float*)d_in[0];
    const float* query    = (const float*)d_in[1];
    const float* pos2     = (const float*)d_in[2];
    const float* key_feat = (const float*)d_in[3];
    const float* wq  = (const float*)d_in[4];
    const float* bq  = (const float*)d_in[5];
    const float* wk  = (const float*)d_in[6];
    const float* bk  = (const float*)d_in[7];
    const float* wv  = (const float*)d_in[8];
    const float* bv  = (const float*)d_in[9];
    const float* pw1 = (const float*)d_in[10];
    const float* pb1 = (const float*)d_in[11];
    const float* pg  = (const float*)d_in[12];
    const float* pbt = (const float*)d_in[13];
    const float* pm  = (const float*)d_in[14];
    const float* pv  = (const float*)d_in[15];
    const float* pw2 = (const float*)d_in[16];
    const float* pb2 = (const float*)d_in[17];
    const float* aw1 = (const float*)d_in[18];
    const float* ab1 = (const float*)d_in[19];
    const float* ag  = (const float*)d_in[20];
    const float* abt2= (const float*)d_in[21];
    const float* am  = (const float*)d_in[22];
    const float* av  = (const float*)d_in[23];
    const float* awt = (const float*)d_in[24];
    const float* abt = (const float*)d_in[25];
    const float* we  = (const float*)d_in[26];
    const float* be  = (const float*)d_in[27];
    float* out = (float*)d_out;

    prep_kernel<<<128, 256>>>(aw1, pw2, wq, wk, wv, awt, ab1, ag, abt2, am, av,
                              pw1, pb1, pg, pbt, pm, pv);
    qkv_kernel<<<dim3(NPTS / 128, BATCH), 256>>>(query, key_feat, bq, bk, bv);
    knn_kernel<<<dim3(NPTS / 128, BATCH), 512>>>(pos1, pos2);
    attn_kernel<<<dim3(NPTS / PPB, BATCH), 256>>>(
        pos1, pos2, query, pb2, abt, we, be, out);
}